// round 3
// baseline (speedup 1.0000x reference)
#include <cuda_runtime.h>
#include <cstdint>
#include <math.h>

#define D_MODEL 1024
#define SEQ     2048
#define BATCH   4
#define ROWS    (BATCH*SEQ)   // 8192
#define DS      16
#define DFF     4096
#define NHEADS  8
#define HDIM    128

// ---------------- scratch ----------------
__device__ float g_xn  [ROWS*D_MODEL];
__device__ float g_xn1 [ROWS*D_MODEL];
__device__ float g_gate[ROWS*D_MODEL];
__device__ float g_q   [ROWS*D_MODEL];
__device__ float g_k   [ROWS*D_MODEL];
__device__ float g_v   [ROWS*D_MODEL];
__device__ float g_ctx [ROWS*D_MODEL];
__device__ float g_x2  [ROWS*D_MODEL];
__device__ float g_xn2 [ROWS*D_MODEL];
__device__ float g_y   [ROWS*D_MODEL];
__device__ float g_ffn1[ROWS*DFF];
__device__ float g_cat [ROWS*2*D_MODEL];   // [mamba | tout], pitch 2048
__device__ float g_delta[ROWS*DS];
__device__ float g_bt  [ROWS*DS];
__device__ float g_h   [ROWS*DS];

__device__ __forceinline__ float tanh_fast(float x){
    float y; asm("tanh.approx.f32 %0, %1;" : "=f"(y) : "f"(x)); return y;
}
__device__ __forceinline__ uint32_t smem_to_u32(const void* p){
    uint32_t a;
    asm("{ .reg .u64 t; cvta.to.shared.u64 t, %1; cvt.u32.u64 %0, t; }" : "=r"(a) : "l"(p));
    return a;
}
__device__ __forceinline__ uint32_t f2tf32(float x){
    uint32_t r; asm("cvt.rna.tf32.f32 %0, %1;" : "=r"(r) : "f"(x)); return r;
}
#define SWZ(o) ((o) ^ (((o) >> 3) & 0x70))

__device__ __forceinline__ void ldm_x4(uint32_t* r, uint32_t addr){
    asm volatile("ldmatrix.sync.aligned.m8n8.x4.shared.b16 {%0,%1,%2,%3}, [%4];"
        : "=r"(r[0]), "=r"(r[1]), "=r"(r[2]), "=r"(r[3]) : "r"(addr));
}
__device__ __forceinline__ void mma_tf32(float* d, const uint32_t* a, uint32_t b0, uint32_t b1){
    asm volatile("mma.sync.aligned.m16n8k8.row.col.f32.tf32.tf32.f32 "
        "{%0,%1,%2,%3}, {%4,%5,%6,%7}, {%8,%9}, {%0,%1,%2,%3};"
        : "+f"(d[0]), "+f"(d[1]), "+f"(d[2]), "+f"(d[3])
        : "r"(a[0]), "r"(a[1]), "r"(a[2]), "r"(a[3]), "r"(b0), "r"(b1));
}

// ---------------- tf32 tensor-core GEMM: C = act(A@B + bias) (+res) ----------------
// A: MxK (lda), B: KxN row-major, C pitch ldc, res pitch ldr. Tile 128x128xk32.
#define GEMM_SMEM 65536
template<int ACT>
__global__ void __launch_bounds__(256) gemm_mma(
    const float* __restrict__ A, const float* __restrict__ B,
    const float* __restrict__ bias, const float* __restrict__ res,
    float* __restrict__ C, int M, int N, int K, int lda, int ldc, int ldr)
{
    extern __shared__ char smem[];
    const uint32_t sbase = smem_to_u32(smem);
    const int tid = threadIdx.x;
    const int lane = tid & 31, wid = tid >> 5;
    const int warp_m = wid >> 2, warp_n = wid & 3;
    const int row0 = blockIdx.y*128, col0 = blockIdx.x*128;

    float acc[4][4][4];
    #pragma unroll
    for (int i=0;i<4;i++)
        #pragma unroll
        for (int j=0;j<4;j++)
            #pragma unroll
            for (int c=0;c<4;c++) acc[i][j][c]=0.f;

    // per-thread gmem tile coords
    const int ar = tid>>3, ac4 = (tid&7)<<2;     // A: 128 rows handled as tid+i*256 below
    const int bk = tid>>5, bn4 = (tid&31)<<2;    // B: likewise

    float4 pa[4], pb[4];
    const float* Ag0 = A + (size_t)row0*lda;
    const float* Bg0 = B + col0;

    // prefetch chunk 0
    #pragma unroll
    for (int i=0;i<4;i++){
        const int f=tid+i*256, r=f>>3, c4=(f&7)<<2;
        pa[i] = *(const float4*)(Ag0 + (size_t)r*lda + c4);
        const int kk=f>>5, n4=(f&31)<<2;
        pb[i] = *(const float4*)(Bg0 + (size_t)kk*N + n4);
    }

    const int nk = K>>5;
    const int sub = lane>>3, rr = lane&7;
    for (int kt=0; kt<nk; ++kt){
        const int cur = kt&1;
        char* sA = smem + cur*16384;
        char* sB = smem + 32768 + cur*16384;
        #pragma unroll
        for (int i=0;i<4;i++){
            const int f=tid+i*256, r=f>>3, c4=(f&7)<<2;
            uint32_t* p = (uint32_t*)(sA + SWZ((uint32_t)(r*128 + c4*4)));
            p[0]=f2tf32(pa[i].x); p[1]=f2tf32(pa[i].y); p[2]=f2tf32(pa[i].z); p[3]=f2tf32(pa[i].w);
            const int kk=f>>5, n4=(f&31)<<2;
            *(uint32_t*)(sB + SWZ((uint32_t)((n4+0)*128 + kk*4))) = f2tf32(pb[i].x);
            *(uint32_t*)(sB + SWZ((uint32_t)((n4+1)*128 + kk*4))) = f2tf32(pb[i].y);
            *(uint32_t*)(sB + SWZ((uint32_t)((n4+2)*128 + kk*4))) = f2tf32(pb[i].z);
            *(uint32_t*)(sB + SWZ((uint32_t)((n4+3)*128 + kk*4))) = f2tf32(pb[i].w);
        }
        __syncthreads();
        if (kt+1 < nk){
            const float* Ag = Ag0 + (size_t)(kt+1)*32;
            const float* Bg = Bg0 + (size_t)(kt+1)*32*N;
            #pragma unroll
            for (int i=0;i<4;i++){
                const int f=tid+i*256, r=f>>3, c4=(f&7)<<2;
                pa[i] = *(const float4*)(Ag + (size_t)r*lda + c4);
                const int kk=f>>5, n4=(f&31)<<2;
                pb[i] = *(const float4*)(Bg + (size_t)kk*N + n4);
            }
        }
        const uint32_t aB = sbase + cur*16384;
        const uint32_t bB = sbase + 32768 + cur*16384;
        #pragma unroll
        for (int s=0;s<4;s++){
            uint32_t af[4][4], bf[2][4];
            #pragma unroll
            for (int mt=0;mt<4;mt++){
                const int m  = warp_m*64 + mt*16 + (sub&1)*8 + rr;
                const int ku = s*2 + (sub>>1);
                ldm_x4(af[mt], aB + SWZ((uint32_t)(m*128 + ku*16)));
            }
            #pragma unroll
            for (int p=0;p<2;p++){
                const int n  = warp_n*32 + p*16 + (sub>>1)*8 + rr;
                const int ku = s*2 + (sub&1);
                ldm_x4(bf[p], bB + SWZ((uint32_t)(n*128 + ku*16)));
            }
            #pragma unroll
            for (int mt=0;mt<4;mt++){
                #pragma unroll
                for (int nt=0;nt<4;nt++)
                    mma_tf32(acc[mt][nt], af[mt], bf[nt>>1][(nt&1)*2], bf[nt>>1][(nt&1)*2+1]);
            }
        }
        __syncthreads();
    }

    // epilogue: regs -> gmem (float2 per fragment row)
    const int qrow = lane>>2, qcol = (lane&3)*2;
    #pragma unroll
    for (int mt=0;mt<4;mt++){
        #pragma unroll
        for (int nt=0;nt<4;nt++){
            const int col = col0 + warp_n*32 + nt*8 + qcol;
            float2 bb = make_float2(0.f,0.f);
            if (bias) bb = *(const float2*)(bias + col);
            #pragma unroll
            for (int half=0; half<2; half++){
                const int row = row0 + warp_m*64 + mt*16 + qrow + half*8;
                float vx = acc[mt][nt][half*2+0] + bb.x;
                float vy = acc[mt][nt][half*2+1] + bb.y;
                if (ACT==1){ vx = 1.f/(1.f+__expf(-vx)); vy = 1.f/(1.f+__expf(-vy)); }
                else if (ACT==2){ vx = fmaxf(vx,0.f); vy = fmaxf(vy,0.f); }
                if (res){
                    const float2 rv = *(const float2*)(res + (size_t)row*ldr + col);
                    vx += rv.x; vy += rv.y;
                }
                *(float2*)(C + (size_t)row*ldc + col) = make_float2(vx,vy);
            }
        }
    }
}

// ---------------- LayerNorm (optionally dual-output) ----------------
__global__ void __launch_bounds__(256) ln_kernel(
    const float* __restrict__ x,
    const float* __restrict__ g0, const float* __restrict__ b0, float* __restrict__ out0,
    const float* __restrict__ g1, const float* __restrict__ b1, float* __restrict__ out1)
{
    __shared__ float red[64];
    const int row = blockIdx.x;
    const int tid = threadIdx.x;
    const float4 v = ((const float4*)(x + (size_t)row*D_MODEL))[tid];
    float s  = v.x+v.y+v.z+v.w;
    float sq = v.x*v.x+v.y*v.y+v.z*v.z+v.w*v.w;
    #pragma unroll
    for (int o=16;o;o>>=1){ s += __shfl_xor_sync(0xffffffffu,s,o); sq += __shfl_xor_sync(0xffffffffu,sq,o); }
    if ((tid&31)==0){ red[tid>>5]=s; red[(tid>>5)+8]=sq; }
    __syncthreads();
    if (tid<32){
        float ss=(tid<8)?red[tid]:0.f, qq=(tid<8)?red[tid+8]:0.f;
        #pragma unroll
        for (int o=4;o;o>>=1){ ss += __shfl_xor_sync(0xffffffffu,ss,o); qq += __shfl_xor_sync(0xffffffffu,qq,o); }
        if (tid==0){ red[32]=ss; red[33]=qq; }
    }
    __syncthreads();
    const float mean = red[32]*(1.f/D_MODEL);
    const float var  = red[33]*(1.f/D_MODEL) - mean*mean;
    const float inv  = rsqrtf(var + 1e-5f);
    {
        const float4 g = ((const float4*)g0)[tid];
        const float4 b = ((const float4*)b0)[tid];
        float4 o0;
        o0.x = (v.x-mean)*inv*g.x + b.x;
        o0.y = (v.y-mean)*inv*g.y + b.y;
        o0.z = (v.z-mean)*inv*g.z + b.z;
        o0.w = (v.w-mean)*inv*g.w + b.w;
        ((float4*)(out0 + (size_t)row*D_MODEL))[tid] = o0;
    }
    if (out1){
        const float4 g = ((const float4*)g1)[tid];
        const float4 b = ((const float4*)b1)[tid];
        float4 o1;
        o1.x = (v.x-mean)*inv*g.x + b.x;
        o1.y = (v.y-mean)*inv*g.y + b.y;
        o1.z = (v.z-mean)*inv*g.z + b.z;
        o1.w = (v.w-mean)*inv*g.w + b.w;
        ((float4*)(out1 + (size_t)row*D_MODEL))[tid] = o1;
    }
}

// ---------------- delta / Bt ----------------
__global__ void __launch_bounds__(256) delta_bt_kernel(
    const float* __restrict__ xn,
    const float* __restrict__ Wd, const float* __restrict__ bd,
    const float* __restrict__ Wi, const float* __restrict__ bi,
    float* __restrict__ delta, float* __restrict__ bt)
{
    __shared__ float xs[D_MODEL];
    __shared__ float red[256];
    const int row = blockIdx.x, tid = threadIdx.x;
    ((float4*)xs)[tid] = ((const float4*)(xn + (size_t)row*D_MODEL))[tid];
    __syncthreads();
    const int c = tid & 15;
    const int which = (tid>>4)&1;
    const int grp = tid>>5;
    const float* W = which ? Wi : Wd;
    float acc = 0.f;
    const int k0 = grp*128;
    #pragma unroll 8
    for (int k=0;k<128;k++) acc += xs[k0+k]*W[(size_t)(k0+k)*16 + c];
    red[tid]=acc; __syncthreads();
    if (tid<32){
        float sacc=0.f;
        #pragma unroll
        for (int g=0;g<8;g++) sacc += red[g*32+tid];
        if (tid<16) delta[(size_t)row*16+tid] = 1.f/(1.f+__expf(-(sacc+bd[tid])));
        else        bt   [(size_t)row*16+tid-16] = sacc + bi[tid-16];
    }
}

// ---------------- sequential mamba scan ----------------
__global__ void __launch_bounds__(32) scan_kernel(
    const float* __restrict__ delta, const float* __restrict__ bt,
    const float* __restrict__ A, float* __restrict__ h_all)
{
    __shared__ float ds[128*16], bs[128*16];
    const int b = blockIdx.x, lane = threadIdx.x;
    const int j = lane & 15;
    float Acol[16];
    #pragma unroll
    for (int i=0;i<16;i++) Acol[i] = A[i*16 + j];
    float h = 0.f;
    const float* dp = delta + (size_t)b*SEQ*16;
    const float* bp = bt    + (size_t)b*SEQ*16;
    float* hp = h_all + (size_t)b*SEQ*16;
    for (int chunk=0; chunk<SEQ; chunk+=128){
        const float4* s0 = (const float4*)(dp + (size_t)chunk*16);
        const float4* s1 = (const float4*)(bp + (size_t)chunk*16);
        for (int i=lane;i<512;i+=32){ ((float4*)ds)[i]=s0[i]; ((float4*)bs)[i]=s1[i]; }
        __syncwarp();
        #pragma unroll 4
        for (int t=0;t<128;t++){
            const float d = ds[t*16+j];
            const float bv = bs[t*16+j];
            const float v = h*d;
            float a0 = bv, a1 = 0.f;
            #pragma unroll
            for (int i=0;i<16;i+=2){
                a0 += __shfl_sync(0xffffffffu, v, i,   16)*Acol[i];
                a1 += __shfl_sync(0xffffffffu, v, i+1, 16)*Acol[i+1];
            }
            h = tanh_fast(a0+a1);
            if (lane<16) hp[(size_t)(chunk+t)*16 + j] = h;
        }
        __syncwarp();
    }
}

// ---------------- mamba_out = (h @ C) * gate + x -> cat[:,0:1024] ----------------
__global__ void __launch_bounds__(256) mamba_out_kernel(
    const float* __restrict__ h_all, const float* __restrict__ Cm,
    const float* __restrict__ gate, const float* __restrict__ x,
    float* __restrict__ out)  // pitch 2048
{
    __shared__ float hs[16];
    const int row = blockIdx.x, tid = threadIdx.x;
    if (tid<16) hs[tid] = h_all[(size_t)row*16+tid];
    __syncthreads();
    const size_t base = (size_t)row*D_MODEL;
    const size_t obase = (size_t)row*2048;
    #pragma unroll
    for (int kk=0; kk<4; kk++){
        const int c = tid + kk*256;
        float acc = 0.f;
        #pragma unroll
        for (int i=0;i<16;i++) acc += hs[i]*Cm[(size_t)i*D_MODEL + c];
        out[obase+c] = acc*gate[base+c] + x[base+c];
    }
}

// ---------------- fp32 flash attention ----------------
__global__ void __launch_bounds__(256) attn_kernel(
    const float* __restrict__ Q, const float* __restrict__ K,
    const float* __restrict__ V, float* __restrict__ O)
{
    extern __shared__ float sm[];
    float* Qs   = sm;
    float* KVs  = sm + 64*128;
    float* Ss   = sm + 2*64*128;
    float* mrow = Ss + 64*64;
    float* lrow = mrow + 64;
    float* arow = lrow + 64;

    const int tid = threadIdx.x;
    const int q0  = blockIdx.x*64;
    const int b   = blockIdx.y>>3;
    const int h   = blockIdx.y&7;
    const float* Qb = Q + ((size_t)b*SEQ + q0)*D_MODEL + h*HDIM;
    const float* Kb = K + (size_t)b*SEQ*D_MODEL + h*HDIM;
    const float* Vb = V + (size_t)b*SEQ*D_MODEL + h*HDIM;
    const float scale = 0.08838834764831845f;

    for (int i=tid;i<64*32;i+=256){
        const int r=i>>5, c=(i&31)<<2;
        float4 t = *(const float4*)(Qb + (size_t)r*D_MODEL + c);
        t.x*=scale; t.y*=scale; t.z*=scale; t.w*=scale;
        *(float4*)&Qs[r*128+c] = t;
    }
    if (tid<64){ mrow[tid]=-1e30f; lrow[tid]=0.f; }

    const int str = tid>>4, stc = tid&15;
    float o[4][8];
    #pragma unroll
    for (int i=0;i<4;i++){
        #pragma unroll
        for (int j=0;j<8;j++) o[i][j]=0.f;
    }
    __syncthreads();

    for (int kt=0; kt<SEQ; kt+=64){
        for (int i=tid;i<64*32;i+=256){
            const int r=i>>5, c=(i&31)<<2;
            *(float4*)&KVs[r*128+c] = *(const float4*)(Kb + (size_t)(kt+r)*D_MODEL + c);
        }
        __syncthreads();

        float s[4][4];
        #pragma unroll
        for (int i=0;i<4;i++){
            #pragma unroll
            for (int j=0;j<4;j++) s[i][j]=0.f;
        }
        for (int d0=0; d0<128; d0+=4){
            float4 qv[4], kv[4];
            #pragma unroll
            for (int i=0;i<4;i++) qv[i] = *(const float4*)&Qs[(str*4+i)*128 + d0];
            #pragma unroll
            for (int j=0;j<4;j++) kv[j] = *(const float4*)&KVs[(stc*4+j)*128 + d0];
            #pragma unroll
            for (int i=0;i<4;i++){
                #pragma unroll
                for (int j=0;j<4;j++)
                    s[i][j] += qv[i].x*kv[j].x + qv[i].y*kv[j].y + qv[i].z*kv[j].z + qv[i].w*kv[j].w;
            }
        }

        #pragma unroll
        for (int i=0;i<4;i++){
            const int r = str*4+i;
            float mx = fmaxf(fmaxf(s[i][0],s[i][1]), fmaxf(s[i][2],s[i][3]));
            #pragma unroll
            for (int off=8; off; off>>=1) mx = fmaxf(mx, __shfl_xor_sync(0xffffffffu,mx,off));
            const float mold = mrow[r];
            const float mnew = fmaxf(mold, mx);
            const float p0=__expf(s[i][0]-mnew), p1=__expf(s[i][1]-mnew);
            const float p2=__expf(s[i][2]-mnew), p3=__expf(s[i][3]-mnew);
            float sum = p0+p1+p2+p3;
            #pragma unroll
            for (int off=8; off; off>>=1) sum += __shfl_xor_sync(0xffffffffu,sum,off);
            if (stc==0){
                const float al = __expf(mold-mnew);
                mrow[r]=mnew; lrow[r]=lrow[r]*al+sum; arow[r]=al;
            }
            *(float4*)&Ss[r*64 + stc*4] = make_float4(p0,p1,p2,p3);
        }
        __syncthreads();

        for (int i=tid;i<64*32;i+=256){
            const int r=i>>5, c=(i&31)<<2;
            *(float4*)&KVs[r*128+c] = *(const float4*)(Vb + (size_t)(kt+r)*D_MODEL + c);
        }
        __syncthreads();

        #pragma unroll
        for (int i=0;i<4;i++){
            const float al = arow[str*4+i];
            #pragma unroll
            for (int j=0;j<8;j++) o[i][j] *= al;
        }
        for (int kk=0; kk<64; kk+=4){
            float pr[4][4];
            #pragma unroll
            for (int i=0;i<4;i++){
                const float4 p = *(const float4*)&Ss[(str*4+i)*64 + kk];
                pr[i][0]=p.x; pr[i][1]=p.y; pr[i][2]=p.z; pr[i][3]=p.w;
            }
            #pragma unroll
            for (int dd=0; dd<4; dd++){
                float vv[8];
                *(float4*)&vv[0] = *(const float4*)&KVs[(kk+dd)*128 + stc*8];
                *(float4*)&vv[4] = *(const float4*)&KVs[(kk+dd)*128 + stc*8 + 4];
                #pragma unroll
                for (int i=0;i<4;i++){
                    #pragma unroll
                    for (int j=0;j<8;j++) o[i][j] += pr[i][dd]*vv[j];
                }
            }
        }
        __syncthreads();
    }

    float* Ob = O + ((size_t)b*SEQ + q0)*D_MODEL + h*HDIM;
    #pragma unroll
    for (int i=0;i<4;i++){
        const int r = str*4+i;
        const float inv = 1.f/lrow[r];
        *(float4*)(Ob + (size_t)r*D_MODEL + stc*8)     = make_float4(o[i][0]*inv,o[i][1]*inv,o[i][2]*inv,o[i][3]*inv);
        *(float4*)(Ob + (size_t)r*D_MODEL + stc*8 + 4) = make_float4(o[i][4]*inv,o[i][5]*inv,o[i][6]*inv,o[i][7]*inv);
    }
}

// ---------------- launch ----------------
extern "C" void kernel_launch(void* const* d_in, const int* in_sizes, int n_in,
                              void* d_out, int out_size)
{
    const float* x      = (const float*)d_in[0];
    const float* ln_g   = (const float*)d_in[1];
    const float* ln_b   = (const float*)d_in[2];
    const float* Wdelta = (const float*)d_in[3];
    const float* bdelta = (const float*)d_in[4];
    const float* Win    = (const float*)d_in[5];
    const float* b_in   = (const float*)d_in[6];
    const float* Wgate  = (const float*)d_in[7];
    const float* bgate  = (const float*)d_in[8];
    const float* Amat   = (const float*)d_in[9];
    const float* Cmat   = (const float*)d_in[10];
    const float* ln1_g  = (const float*)d_in[11];
    const float* ln1_b  = (const float*)d_in[12];
    const float* Wq     = (const float*)d_in[13];
    const float* bq     = (const float*)d_in[14];
    const float* Wk     = (const float*)d_in[15];
    const float* bk     = (const float*)d_in[16];
    const float* Wv     = (const float*)d_in[17];
    const float* bv     = (const float*)d_in[18];
    const float* Wo     = (const float*)d_in[19];
    const float* bo     = (const float*)d_in[20];
    const float* ln2_g  = (const float*)d_in[21];
    const float* ln2_b  = (const float*)d_in[22];
    const float* W1     = (const float*)d_in[23];
    const float* b1     = (const float*)d_in[24];
    const float* W2     = (const float*)d_in[25];
    const float* b2     = (const float*)d_in[26];
    const float* Wf     = (const float*)d_in[27];
    const float* bf     = (const float*)d_in[28];
    const float* lnf_g  = (const float*)d_in[29];
    const float* lnf_b  = (const float*)d_in[30];

    float *xn,*xn1,*gate,*q,*k,*v,*ctx,*x2,*xn2,*y,*ffn1,*cat,*delta,*bt,*h;
    cudaGetSymbolAddress((void**)&xn,   g_xn);
    cudaGetSymbolAddress((void**)&xn1,  g_xn1);
    cudaGetSymbolAddress((void**)&gate, g_gate);
    cudaGetSymbolAddress((void**)&q,    g_q);
    cudaGetSymbolAddress((void**)&k,    g_k);
    cudaGetSymbolAddress((void**)&v,    g_v);
    cudaGetSymbolAddress((void**)&ctx,  g_ctx);
    cudaGetSymbolAddress((void**)&x2,   g_x2);
    cudaGetSymbolAddress((void**)&xn2,  g_xn2);
    cudaGetSymbolAddress((void**)&y,    g_y);
    cudaGetSymbolAddress((void**)&ffn1, g_ffn1);
    cudaGetSymbolAddress((void**)&cat,  g_cat);
    cudaGetSymbolAddress((void**)&delta,g_delta);
    cudaGetSymbolAddress((void**)&bt,   g_bt);
    cudaGetSymbolAddress((void**)&h,    g_h);

    cudaFuncSetAttribute(gemm_mma<0>, cudaFuncAttributeMaxDynamicSharedMemorySize, GEMM_SMEM);
    cudaFuncSetAttribute(gemm_mma<1>, cudaFuncAttributeMaxDynamicSharedMemorySize, GEMM_SMEM);
    cudaFuncSetAttribute(gemm_mma<2>, cudaFuncAttributeMaxDynamicSharedMemorySize, GEMM_SMEM);

    const dim3 gD(D_MODEL/128, ROWS/128);   // (8, 64)
    const dim3 gF(DFF/128,     ROWS/128);   // (32, 64)

    // Mamba branch prep
    ln_kernel<<<ROWS,256>>>(x, ln_g, ln_b, xn, ln1_g, ln1_b, xn1);
    delta_bt_kernel<<<ROWS,256>>>(xn, Wdelta, bdelta, Win, b_in, delta, bt);
    scan_kernel<<<BATCH,32>>>(delta, bt, Amat, h);
    gemm_mma<1><<<gD,256,GEMM_SMEM>>>(xn, Wgate, bgate, nullptr, gate, ROWS, D_MODEL, D_MODEL, D_MODEL, D_MODEL, 0);
    mamba_out_kernel<<<ROWS,256>>>(h, Cmat, gate, x, cat);     // cat[:,0:1024]

    // Transformer branch
    gemm_mma<0><<<gD,256,GEMM_SMEM>>>(xn1, Wq, bq, nullptr, q, ROWS, D_MODEL, D_MODEL, D_MODEL, D_MODEL, 0);
    gemm_mma<0><<<gD,256,GEMM_SMEM>>>(xn1, Wk, bk, nullptr, k, ROWS, D_MODEL, D_MODEL, D_MODEL, D_MODEL, 0);
    gemm_mma<0><<<gD,256,GEMM_SMEM>>>(xn1, Wv, bv, nullptr, v, ROWS, D_MODEL, D_MODEL, D_MODEL, D_MODEL, 0);

    const size_t attn_smem = (size_t)(2*64*128 + 64*64 + 3*64)*sizeof(float);
    cudaFuncSetAttribute(attn_kernel, cudaFuncAttributeMaxDynamicSharedMemorySize, (int)attn_smem);
    attn_kernel<<<dim3(SEQ/64, BATCH*NHEADS), 256, attn_smem>>>(q, k, v, ctx);

    gemm_mma<0><<<gD,256,GEMM_SMEM>>>(ctx, Wo, bo, x, x2, ROWS, D_MODEL, D_MODEL, D_MODEL, D_MODEL, D_MODEL);
    ln_kernel<<<ROWS,256>>>(x2, ln2_g, ln2_b, xn2, nullptr, nullptr, nullptr);
    gemm_mma<2><<<gF,256,GEMM_SMEM>>>(xn2, W1, b1, nullptr, ffn1, ROWS, DFF, D_MODEL, D_MODEL, DFF, 0);
    // tout = x2 + ffn1@W2 + b2  -> cat[:,1024:2048]
    gemm_mma<0><<<gD,256,GEMM_SMEM>>>(ffn1, W2, b2, x2, cat + D_MODEL, ROWS, D_MODEL, DFF, DFF, 2*D_MODEL, D_MODEL);

    // Fusion: y = cat @ Wf + bf  (K = 2048)
    gemm_mma<0><<<gD,256,GEMM_SMEM>>>(cat, Wf, bf, nullptr, y, ROWS, D_MODEL, 2*D_MODEL, 2*D_MODEL, D_MODEL, 0);

    // Final LN -> output
    ln_kernel<<<ROWS,256>>>(y, lnf_g, lnf_b, (float*)d_out, nullptr, nullptr, nullptr);
}

// round 4
// speedup vs baseline: 6.4120x; 6.4120x over previous
#include <cuda_runtime.h>
#include <cstdint>
#include <math.h>

#define D_MODEL 1024
#define SEQ     2048
#define BATCH   4
#define ROWS    (BATCH*SEQ)   // 8192
#define DS      16
#define DFF     4096
#define NHEADS  8
#define HDIM    128

// ---------------- scratch ----------------
__device__ float g_xn  [ROWS*D_MODEL];
__device__ float g_xn1 [ROWS*D_MODEL];
__device__ float g_gate[ROWS*D_MODEL];
__device__ float g_q   [ROWS*D_MODEL];
__device__ float g_k   [ROWS*D_MODEL];
__device__ float g_v   [ROWS*D_MODEL];
__device__ float g_ctx [ROWS*D_MODEL];
__device__ float g_x2  [ROWS*D_MODEL];
__device__ float g_xn2 [ROWS*D_MODEL];
__device__ float g_y   [ROWS*D_MODEL];
__device__ float g_ffn1[ROWS*DFF];
__device__ float g_cat [ROWS*2*D_MODEL];   // [mamba | tout], pitch 2048
__device__ float g_delta[ROWS*DS];
__device__ float g_bt  [ROWS*DS];
__device__ float g_h   [ROWS*DS];
// transposed + tf32-rounded weights [N][K]
__device__ float g_WgT[D_MODEL*D_MODEL];
__device__ float g_WqT[D_MODEL*D_MODEL];
__device__ float g_WkT[D_MODEL*D_MODEL];
__device__ float g_WvT[D_MODEL*D_MODEL];
__device__ float g_WoT[D_MODEL*D_MODEL];
__device__ float g_W1T[DFF*D_MODEL];
__device__ float g_W2T[D_MODEL*DFF];
__device__ float g_WfT[D_MODEL*2*D_MODEL];

__device__ __forceinline__ float tanh_fast(float x){
    float y; asm("tanh.approx.f32 %0, %1;" : "=f"(y) : "f"(x)); return y;
}
__device__ __forceinline__ uint32_t smem_to_u32(const void* p){
    uint32_t a;
    asm("{ .reg .u64 t; cvta.to.shared.u64 t, %1; cvt.u32.u64 %0, t; }" : "=r"(a) : "l"(p));
    return a;
}
__device__ __forceinline__ uint32_t f2tf32(float x){
    uint32_t r; asm("cvt.rna.tf32.f32 %0, %1;" : "=r"(r) : "f"(x)); return r;
}
__device__ __forceinline__ float rnd_tf32(float x){ return __uint_as_float(f2tf32(x)); }
#define SWZ(o) ((o) ^ (((o) >> 3) & 0x70))

__device__ __forceinline__ void ldm_x4(uint32_t* r, uint32_t addr){
    asm volatile("ldmatrix.sync.aligned.m8n8.x4.shared.b16 {%0,%1,%2,%3}, [%4];"
        : "=r"(r[0]), "=r"(r[1]), "=r"(r[2]), "=r"(r[3]) : "r"(addr));
}
__device__ __forceinline__ void mma_tf32(float* d, const uint32_t* a, uint32_t b0, uint32_t b1){
    asm volatile("mma.sync.aligned.m16n8k8.row.col.f32.tf32.tf32.f32 "
        "{%0,%1,%2,%3}, {%4,%5,%6,%7}, {%8,%9}, {%0,%1,%2,%3};"
        : "+f"(d[0]), "+f"(d[1]), "+f"(d[2]), "+f"(d[3])
        : "r"(a[0]), "r"(a[1]), "r"(a[2]), "r"(a[3]), "r"(b0), "r"(b1));
}
__device__ __forceinline__ void cp16(uint32_t dst, const void* src){
    asm volatile("cp.async.cg.shared.global [%0], [%1], 16;" :: "r"(dst), "l"(src));
}
#define CP_COMMIT() asm volatile("cp.async.commit_group;" ::: "memory")
#define CP_WAIT1()  asm volatile("cp.async.wait_group 1;" ::: "memory")

// ---------------- weight prep: transpose + tf32 round  src[K][N] -> dst[N][K] ----------------
__global__ void __launch_bounds__(256) wprep(const float* __restrict__ src, float* __restrict__ dst,
                                             int K, int N){
    __shared__ float t[32][33];
    const int n0 = blockIdx.x*32, k0 = blockIdx.y*32;
    const int x = threadIdx.x & 31, y = threadIdx.x >> 5;   // y: 0..7
    #pragma unroll
    for (int j=0;j<4;j++) t[y*4+j][x] = src[(size_t)(k0+y*4+j)*N + n0 + x];
    __syncthreads();
    #pragma unroll
    for (int j=0;j<4;j++)
        dst[(size_t)(n0+y*4+j)*K + k0 + x] = rnd_tf32(t[x][y*4+j]);
}

// ---------------- tf32 mma GEMM with cp.async 3-stage pipeline ----------------
// A: MxK row-major (lda), already tf32-representable. Bt: NxK K-major (pitch K).
// C pitch ldc, res pitch ldr. Tile 128x128, K-chunk 32.
#define GEMM_SMEM (3*32768)
template<int ACT, int RND>
__global__ void __launch_bounds__(256,2) gemm_mma(
    const float* __restrict__ A, const float* __restrict__ Bt,
    const float* __restrict__ bias, const float* __restrict__ res,
    float* __restrict__ C, int N, int K, int lda, int ldc, int ldr)
{
    extern __shared__ char smem[];
    const uint32_t sbase = smem_to_u32(smem);
    const int tid = threadIdx.x;
    const int lane = tid & 31, wid = tid >> 5;
    const int warp_m = wid >> 2, warp_n = wid & 3;
    const int row0 = blockIdx.y*128, col0 = blockIdx.x*128;
    const int sub = lane>>3, rr = lane&7;

    const float* Ag = A  + (size_t)row0*lda;
    const float* Bg = Bt + (size_t)col0*K;

    float acc[4][4][4];
    #pragma unroll
    for (int i=0;i<4;i++)
        #pragma unroll
        for (int j=0;j<4;j++){ acc[i][j][0]=0.f; acc[i][j][1]=0.f; acc[i][j][2]=0.f; acc[i][j][3]=0.f; }

    const int nk = K>>5;
    // issue stage kt into buffer kt%3
    auto issue = [&](int kt){
        const uint32_t sA = sbase + (kt%3)*32768;
        const uint32_t sB = sA + 16384;
        const int koff = kt*32;
        #pragma unroll
        for (int i=0;i<4;i++){
            const int f = tid + i*256, r = f>>3, seg = f&7;
            cp16(sA + SWZ((uint32_t)(r*128 + seg*16)), Ag + (size_t)r*lda + koff + seg*4);
            cp16(sB + SWZ((uint32_t)(r*128 + seg*16)), Bg + (size_t)r*K   + koff + seg*4);
        }
    };
    issue(0); CP_COMMIT();
    if (nk>1) issue(1); CP_COMMIT();

    for (int kt=0; kt<nk; ++kt){
        CP_WAIT1();
        __syncthreads();
        if (kt+2 < nk) issue(kt+2);
        CP_COMMIT();
        const uint32_t aB = sbase + (kt%3)*32768;
        const uint32_t bB = aB + 16384;
        #pragma unroll
        for (int s=0;s<4;s++){
            uint32_t af[4][4], bf[2][4];
            #pragma unroll
            for (int mt=0;mt<4;mt++){
                const int m  = warp_m*64 + mt*16 + (sub&1)*8 + rr;
                const int ku = s*2 + (sub>>1);
                ldm_x4(af[mt], aB + SWZ((uint32_t)(m*128 + ku*16)));
            }
            #pragma unroll
            for (int p=0;p<2;p++){
                const int n  = warp_n*32 + p*16 + (sub>>1)*8 + rr;
                const int ku = s*2 + (sub&1);
                ldm_x4(bf[p], bB + SWZ((uint32_t)(n*128 + ku*16)));
            }
            #pragma unroll
            for (int mt=0;mt<4;mt++)
                #pragma unroll
                for (int nt=0;nt<4;nt++)
                    mma_tf32(acc[mt][nt], af[mt], bf[nt>>1][(nt&1)*2], bf[nt>>1][(nt&1)*2+1]);
        }
        __syncthreads();
    }

    // epilogue via smem staging (pitch 132) -> coalesced float4 stores
    float* Es = (float*)smem;
    const int qrow = lane>>2, qcol = (lane&3)*2;
    #pragma unroll
    for (int mt=0;mt<4;mt++)
        #pragma unroll
        for (int nt=0;nt<4;nt++)
            #pragma unroll
            for (int half=0; half<2; half++){
                const int r = warp_m*64 + mt*16 + qrow + half*8;
                const int c = warp_n*32 + nt*8 + qcol;
                *(float2*)&Es[r*132 + c] = make_float2(acc[mt][nt][half*2], acc[mt][nt][half*2+1]);
            }
    __syncthreads();
    #pragma unroll
    for (int i=0;i<16;i++){
        const int f = tid + i*256, r = f>>5, c4 = (f&31)<<2;
        float4 v = *(float4*)&Es[r*132 + c4];
        const int col = col0 + c4;
        if (bias){
            const float4 bb = *(const float4*)(bias + col);
            v.x+=bb.x; v.y+=bb.y; v.z+=bb.z; v.w+=bb.w;
        }
        if (ACT==1){
            v.x=1.f/(1.f+__expf(-v.x)); v.y=1.f/(1.f+__expf(-v.y));
            v.z=1.f/(1.f+__expf(-v.z)); v.w=1.f/(1.f+__expf(-v.w));
        } else if (ACT==2){
            v.x=fmaxf(v.x,0.f); v.y=fmaxf(v.y,0.f); v.z=fmaxf(v.z,0.f); v.w=fmaxf(v.w,0.f);
        }
        if (res){
            const float4 rv = *(const float4*)(res + (size_t)(row0+r)*ldr + col);
            v.x+=rv.x; v.y+=rv.y; v.z+=rv.z; v.w+=rv.w;
        }
        if (RND){ v.x=rnd_tf32(v.x); v.y=rnd_tf32(v.y); v.z=rnd_tf32(v.z); v.w=rnd_tf32(v.w); }
        *(float4*)(C + (size_t)(row0+r)*ldc + col) = v;
    }
}

// ---------------- tf32 mma flash attention ----------------
// grid (SEQ/128, BATCH*NHEADS), 256 threads (8 warps x 16 q-rows)
// smem: Qs 4 panels [128][32] (64KB) | Ks 4 panels [64][32] (32KB)
//       | Vts 2 panels [128][32] (32KB) | Ps 2 panels [128][32] (32KB)
#define ATT_SMEM (64*1024 + 32*1024 + 32*1024 + 32*1024)
__global__ void __launch_bounds__(256,1) attn_mma(
    const float* __restrict__ Q, const float* __restrict__ K,
    const float* __restrict__ V, float* __restrict__ O)
{
    extern __shared__ char smem[];
    const uint32_t sQ  = smem_to_u32(smem);
    const uint32_t sK  = sQ + 65536;
    const uint32_t sVt = sK + 32768;
    const uint32_t sP  = sVt + 32768;
    float* fsm = (float*)smem;

    const int tid = threadIdx.x, lane = tid&31, wid = tid>>5;
    const int sub = lane>>3, rr = lane&7;
    const int qt = blockIdx.x;
    const int b  = blockIdx.y>>3, h = blockIdx.y&7;
    const int m0 = wid*16;
    const float scale = 0.08838834764831845f;  // 1/sqrt(128)

    const float* Qb = Q + ((size_t)(b*SEQ + qt*128))*D_MODEL + h*HDIM;
    const float* Kb = K + (size_t)b*SEQ*D_MODEL + h*HDIM;
    const float* Vb = V + (size_t)b*SEQ*D_MODEL + h*HDIM;

    // load Q tile [128][128] into 4 swizzled panels
    #pragma unroll
    for (int i=0;i<16;i++){
        const int f = tid + i*256, r = f>>5, c4 = (f&31)<<2;
        const float4 v = *(const float4*)(Qb + (size_t)r*D_MODEL + c4);
        *(float4*)(smem + (c4>>5)*16384 + SWZ((uint32_t)(r*128 + (c4&31)*4))) = v;
    }

    float oacc[16][4];
    #pragma unroll
    for (int i=0;i<16;i++){ oacc[i][0]=0.f; oacc[i][1]=0.f; oacc[i][2]=0.f; oacc[i][3]=0.f; }
    float m_run[2] = {-1e30f,-1e30f}, l_run[2] = {0.f,0.f};

    for (int kv=0; kv<SEQ/64; ++kv){
        __syncthreads();   // protect Ks/Vts/Ps vs previous iteration's reads
        // K tile [64][128] -> 4 panels [64][32]
        #pragma unroll
        for (int i=0;i<8;i++){
            const int f = tid + i*256, r = f>>5, c4 = (f&31)<<2;
            const float4 v = *(const float4*)(Kb + (size_t)(kv*64+r)*D_MODEL + c4);
            *(float4*)(smem + 65536 + (c4>>5)*8192 + SWZ((uint32_t)(r*128 + (c4&31)*4))) = v;
        }
        // V tile [64][128] -> transposed Vts [128 d][64 seqk] (2 panels [128][32])
        #pragma unroll
        for (int i=0;i<8;i++){
            const int f = tid + i*256;
            const int r = f&63, dblk = f>>6;        // dblk 0..31
            const int d4 = dblk*4;
            const float4 v = *(const float4*)(Vb + (size_t)(kv*64+r)*D_MODEL + d4);
            char* pan = smem + 98304 + (r>>5)*16384;
            const int col = (r&31)*4;
            *(float*)(pan + SWZ((uint32_t)((d4+0)*128 + col))) = v.x;
            *(float*)(pan + SWZ((uint32_t)((d4+1)*128 + col))) = v.y;
            *(float*)(pan + SWZ((uint32_t)((d4+2)*128 + col))) = v.z;
            *(float*)(pan + SWZ((uint32_t)((d4+3)*128 + col))) = v.w;
        }
        __syncthreads();

        // ---- S = Q @ K^T (per warp: rows m0..m0+15, cols 0..63) ----
        float sacc[8][4];
        #pragma unroll
        for (int i=0;i<8;i++){ sacc[i][0]=0.f; sacc[i][1]=0.f; sacc[i][2]=0.f; sacc[i][3]=0.f; }
        #pragma unroll
        for (int p=0;p<4;p++){
            #pragma unroll
            for (int s=0;s<4;s++){
                uint32_t af[4], bf[4][4];
                {
                    const int m  = m0 + (sub&1)*8 + rr;
                    const int ku = s*2 + (sub>>1);
                    ldm_x4(af, sQ + p*16384 + SWZ((uint32_t)(m*128 + ku*16)));
                }
                #pragma unroll
                for (int g=0;g<4;g++){
                    const int n  = g*16 + (sub>>1)*8 + rr;
                    const int ku = s*2 + (sub&1);
                    ldm_x4(bf[g], sK + p*8192 + SWZ((uint32_t)(n*128 + ku*16)));
                }
                #pragma unroll
                for (int nt=0;nt<8;nt++)
                    mma_tf32(sacc[nt], af, bf[nt>>1][(nt&1)*2], bf[nt>>1][(nt&1)*2+1]);
            }
        }

        // ---- FA2 softmax (rows warp-local; quad reduce over lane%4) ----
        #pragma unroll
        for (int hh=0; hh<2; ++hh){
            float mx = -1e30f;
            #pragma unroll
            for (int nt=0;nt<8;nt++)
                mx = fmaxf(mx, fmaxf(sacc[nt][hh*2], sacc[nt][hh*2+1]));
            mx *= scale;
            mx = fmaxf(mx, __shfl_xor_sync(0xffffffffu, mx, 1));
            mx = fmaxf(mx, __shfl_xor_sync(0xffffffffu, mx, 2));
            const float mnew = fmaxf(m_run[hh], mx);
            const float alpha = __expf(m_run[hh] - mnew);
            float lsum = 0.f;
            const int prow = m0 + (lane>>2) + hh*8;
            #pragma unroll
            for (int nt=0;nt<8;nt++){
                const float p0 = __expf(scale*sacc[nt][hh*2+0] - mnew);
                const float p1 = __expf(scale*sacc[nt][hh*2+1] - mnew);
                lsum += p0 + p1;
                const int c = nt*8 + (lane&3)*2;
                *(float2*)(smem + 131072 + (c>>5)*16384 + SWZ((uint32_t)(prow*128 + (c&31)*4)))
                    = make_float2(p0, p1);
            }
            lsum += __shfl_xor_sync(0xffffffffu, lsum, 1);
            lsum += __shfl_xor_sync(0xffffffffu, lsum, 2);
            #pragma unroll
            for (int nt=0;nt<16;nt++){ oacc[nt][hh*2] *= alpha; oacc[nt][hh*2+1] *= alpha; }
            l_run[hh] = l_run[hh]*alpha + lsum;
            m_run[hh] = mnew;
        }
        __syncwarp();

        // ---- O += P @ V (per warp: rows m0..m0+15, d 0..127) ----
        #pragma unroll
        for (int p=0;p<2;p++){
            #pragma unroll
            for (int s=0;s<4;s++){
                uint32_t af[4], bf[8][4];
                {
                    const int m  = m0 + (sub&1)*8 + rr;
                    const int ku = s*2 + (sub>>1);
                    ldm_x4(af, sP + p*16384 + SWZ((uint32_t)(m*128 + ku*16)));
                }
                #pragma unroll
                for (int g=0;g<8;g++){
                    const int n  = g*16 + (sub>>1)*8 + rr;
                    const int ku = s*2 + (sub&1);
                    ldm_x4(bf[g], sVt + p*16384 + SWZ((uint32_t)(n*128 + ku*16)));
                }
                #pragma unroll
                for (int nt=0;nt<16;nt++)
                    mma_tf32(oacc[nt], af, bf[nt>>1][(nt&1)*2], bf[nt>>1][(nt&1)*2+1]);
            }
        }
    }

    // epilogue: normalize + round, write ctx
    float* Ob = O + ((size_t)(b*SEQ + qt*128))*D_MODEL + h*HDIM;
    #pragma unroll
    for (int hh=0; hh<2; ++hh){
        const float inv = 1.f/l_run[hh];
        const int row = m0 + (lane>>2) + hh*8;
        #pragma unroll
        for (int nt=0;nt<16;nt++){
            const int col = nt*8 + (lane&3)*2;
            *(float2*)(Ob + (size_t)row*D_MODEL + col) =
                make_float2(rnd_tf32(oacc[nt][hh*2]*inv), rnd_tf32(oacc[nt][hh*2+1]*inv));
        }
    }
}

// ---------------- LayerNorm (optionally dual-output, optional tf32 rounding) ----------------
__global__ void __launch_bounds__(256) ln_kernel(
    const float* __restrict__ x,
    const float* __restrict__ g0, const float* __restrict__ b0, float* __restrict__ out0,
    const float* __restrict__ g1, const float* __restrict__ b1, float* __restrict__ out1,
    int rnd)
{
    __shared__ float red[64];
    const int row = blockIdx.x;
    const int tid = threadIdx.x;
    const float4 v = ((const float4*)(x + (size_t)row*D_MODEL))[tid];
    float s  = v.x+v.y+v.z+v.w;
    float sq = v.x*v.x+v.y*v.y+v.z*v.z+v.w*v.w;
    #pragma unroll
    for (int o=16;o;o>>=1){ s += __shfl_xor_sync(0xffffffffu,s,o); sq += __shfl_xor_sync(0xffffffffu,sq,o); }
    if ((tid&31)==0){ red[tid>>5]=s; red[(tid>>5)+8]=sq; }
    __syncthreads();
    if (tid<32){
        float ss=(tid<8)?red[tid]:0.f, qq=(tid<8)?red[tid+8]:0.f;
        #pragma unroll
        for (int o=4;o;o>>=1){ ss += __shfl_xor_sync(0xffffffffu,ss,o); qq += __shfl_xor_sync(0xffffffffu,qq,o); }
        if (tid==0){ red[32]=ss; red[33]=qq; }
    }
    __syncthreads();
    const float mean = red[32]*(1.f/D_MODEL);
    const float var  = red[33]*(1.f/D_MODEL) - mean*mean;
    const float inv  = rsqrtf(var + 1e-5f);
    {
        const float4 g = ((const float4*)g0)[tid];
        const float4 b = ((const float4*)b0)[tid];
        float4 o0;
        o0.x = (v.x-mean)*inv*g.x + b.x;
        o0.y = (v.y-mean)*inv*g.y + b.y;
        o0.z = (v.z-mean)*inv*g.z + b.z;
        o0.w = (v.w-mean)*inv*g.w + b.w;
        if (rnd){ o0.x=rnd_tf32(o0.x); o0.y=rnd_tf32(o0.y); o0.z=rnd_tf32(o0.z); o0.w=rnd_tf32(o0.w); }
        ((float4*)(out0 + (size_t)row*D_MODEL))[tid] = o0;
    }
    if (out1){
        const float4 g = ((const float4*)g1)[tid];
        const float4 b = ((const float4*)b1)[tid];
        float4 o1;
        o1.x = (v.x-mean)*inv*g.x + b.x;
        o1.y = (v.y-mean)*inv*g.y + b.y;
        o1.z = (v.z-mean)*inv*g.z + b.z;
        o1.w = (v.w-mean)*inv*g.w + b.w;
        if (rnd){ o1.x=rnd_tf32(o1.x); o1.y=rnd_tf32(o1.y); o1.z=rnd_tf32(o1.z); o1.w=rnd_tf32(o1.w); }
        ((float4*)(out1 + (size_t)row*D_MODEL))[tid] = o1;
    }
}

// ---------------- delta / Bt ----------------
__global__ void __launch_bounds__(256) delta_bt_kernel(
    const float* __restrict__ xn,
    const float* __restrict__ Wd, const float* __restrict__ bd,
    const float* __restrict__ Wi, const float* __restrict__ bi,
    float* __restrict__ delta, float* __restrict__ bt)
{
    __shared__ float xs[D_MODEL];
    __shared__ float red[256];
    const int row = blockIdx.x, tid = threadIdx.x;
    ((float4*)xs)[tid] = ((const float4*)(xn + (size_t)row*D_MODEL))[tid];
    __syncthreads();
    const int c = tid & 15;
    const int which = (tid>>4)&1;
    const int grp = tid>>5;
    const float* W = which ? Wi : Wd;
    float acc = 0.f;
    const int k0 = grp*128;
    #pragma unroll 8
    for (int k=0;k<128;k++) acc += xs[k0+k]*W[(size_t)(k0+k)*16 + c];
    red[tid]=acc; __syncthreads();
    if (tid<32){
        float sacc=0.f;
        #pragma unroll
        for (int g=0;g<8;g++) sacc += red[g*32+tid];
        if (tid<16) delta[(size_t)row*16+tid] = 1.f/(1.f+__expf(-(sacc+bd[tid])));
        else        bt   [(size_t)row*16+tid-16] = sacc + bi[tid-16];
    }
}

// ---------------- sequential mamba scan ----------------
__global__ void __launch_bounds__(32) scan_kernel(
    const float* __restrict__ delta, const float* __restrict__ bt,
    const float* __restrict__ A, float* __restrict__ h_all)
{
    __shared__ float ds[128*16], bs[128*16];
    const int b = blockIdx.x, lane = threadIdx.x;
    const int j = lane & 15;
    float Acol[16];
    #pragma unroll
    for (int i=0;i<16;i++) Acol[i] = A[i*16 + j];
    float h = 0.f;
    const float* dp = delta + (size_t)b*SEQ*16;
    const float* bp = bt    + (size_t)b*SEQ*16;
    float* hp = h_all + (size_t)b*SEQ*16;
    for (int chunk=0; chunk<SEQ; chunk+=128){
        const float4* s0 = (const float4*)(dp + (size_t)chunk*16);
        const float4* s1 = (const float4*)(bp + (size_t)chunk*16);
        for (int i=lane;i<512;i+=32){ ((float4*)ds)[i]=s0[i]; ((float4*)bs)[i]=s1[i]; }
        __syncwarp();
        #pragma unroll 4
        for (int t=0;t<128;t++){
            const float d = ds[t*16+j];
            const float bv = bs[t*16+j];
            const float v = h*d;
            float a0 = bv, a1 = 0.f;
            #pragma unroll
            for (int i=0;i<16;i+=2){
                a0 += __shfl_sync(0xffffffffu, v, i,   16)*Acol[i];
                a1 += __shfl_sync(0xffffffffu, v, i+1, 16)*Acol[i+1];
            }
            h = tanh_fast(a0+a1);
            if (lane<16) hp[(size_t)(chunk+t)*16 + j] = h;
        }
        __syncwarp();
    }
}

// ---------------- mamba_out = (h @ C) * gate + x -> cat[:,0:1024] (tf32-rounded) ----------------
__global__ void __launch_bounds__(256) mamba_out_kernel(
    const float* __restrict__ h_all, const float* __restrict__ Cm,
    const float* __restrict__ gate, const float* __restrict__ x,
    float* __restrict__ out)  // pitch 2048
{
    __shared__ float hs[16];
    const int row = blockIdx.x, tid = threadIdx.x;
    if (tid<16) hs[tid] = h_all[(size_t)row*16+tid];
    __syncthreads();
    const size_t base = (size_t)row*D_MODEL;
    const size_t obase = (size_t)row*2048;
    #pragma unroll
    for (int kk=0; kk<4; kk++){
        const int c = tid + kk*256;
        float acc = 0.f;
        #pragma unroll
        for (int i=0;i<16;i++) acc += hs[i]*Cm[(size_t)i*D_MODEL + c];
        out[obase+c] = rnd_tf32(acc*gate[base+c] + x[base+c]);
    }
}

// ---------------- launch ----------------
extern "C" void kernel_launch(void* const* d_in, const int* in_sizes, int n_in,
                              void* d_out, int out_size)
{
    const float* x      = (const float*)d_in[0];
    const float* ln_g   = (const float*)d_in[1];
    const float* ln_b   = (const float*)d_in[2];
    const float* Wdelta = (const float*)d_in[3];
    const float* bdelta = (const float*)d_in[4];
    const float* Win    = (const float*)d_in[5];
    const float* b_in   = (const float*)d_in[6];
    const float* Wgate  = (const float*)d_in[7];
    const float* bgate  = (const float*)d_in[8];
    const float* Amat   = (const float*)d_in[9];
    const float* Cmat   = (const float*)d_in[10];
    const float* ln1_g  = (const float*)d_in[11];
    const float* ln1_b  = (const float*)d_in[12];
    const float* Wq     = (const float*)d_in[13];
    const float* bq     = (const float*)d_in[14];
    const float* Wk     = (const float*)d_in[15];
    const float* bk     = (const float*)d_in[16];
    const float* Wv     = (const float*)d_in[17];
    const float* bv     = (const float*)d_in[18];
    const float* Wo     = (const float*)d_in[19];
    const float* bo     = (const float*)d_in[20];
    const float* ln2_g  = (const float*)d_in[21];
    const float* ln2_b  = (const float*)d_in[22];
    const float* W1     = (const float*)d_in[23];
    const float* b1     = (const float*)d_in[24];
    const float* W2     = (const float*)d_in[25];
    const float* b2     = (const float*)d_in[26];
    const float* Wf     = (const float*)d_in[27];
    const float* bf     = (const float*)d_in[28];
    const float* lnf_g  = (const float*)d_in[29];
    const float* lnf_b  = (const float*)d_in[30];

    float *xn,*xn1,*gate,*q,*k,*v,*ctx,*x2,*xn2,*y,*ffn1,*cat,*delta,*bt,*h;
    float *WgT,*WqT,*WkT,*WvT,*WoT,*W1T,*W2T,*WfT;
    cudaGetSymbolAddress((void**)&xn,   g_xn);
    cudaGetSymbolAddress((void**)&xn1,  g_xn1);
    cudaGetSymbolAddress((void**)&gate, g_gate);
    cudaGetSymbolAddress((void**)&q,    g_q);
    cudaGetSymbolAddress((void**)&k,    g_k);
    cudaGetSymbolAddress((void**)&v,    g_v);
    cudaGetSymbolAddress((void**)&ctx,  g_ctx);
    cudaGetSymbolAddress((void**)&x2,   g_x2);
    cudaGetSymbolAddress((void**)&xn2,  g_xn2);
    cudaGetSymbolAddress((void**)&y,    g_y);
    cudaGetSymbolAddress((void**)&ffn1, g_ffn1);
    cudaGetSymbolAddress((void**)&cat,  g_cat);
    cudaGetSymbolAddress((void**)&delta,g_delta);
    cudaGetSymbolAddress((void**)&bt,   g_bt);
    cudaGetSymbolAddress((void**)&h,    g_h);
    cudaGetSymbolAddress((void**)&WgT,  g_WgT);
    cudaGetSymbolAddress((void**)&WqT,  g_WqT);
    cudaGetSymbolAddress((void**)&WkT,  g_WkT);
    cudaGetSymbolAddress((void**)&WvT,  g_WvT);
    cudaGetSymbolAddress((void**)&WoT,  g_WoT);
    cudaGetSymbolAddress((void**)&W1T,  g_W1T);
    cudaGetSymbolAddress((void**)&W2T,  g_W2T);
    cudaGetSymbolAddress((void**)&WfT,  g_WfT);

    cudaFuncSetAttribute(gemm_mma<0,0>, cudaFuncAttributeMaxDynamicSharedMemorySize, GEMM_SMEM);
    cudaFuncSetAttribute(gemm_mma<0,1>, cudaFuncAttributeMaxDynamicSharedMemorySize, GEMM_SMEM);
    cudaFuncSetAttribute(gemm_mma<1,0>, cudaFuncAttributeMaxDynamicSharedMemorySize, GEMM_SMEM);
    cudaFuncSetAttribute(gemm_mma<2,1>, cudaFuncAttributeMaxDynamicSharedMemorySize, GEMM_SMEM);
    cudaFuncSetAttribute(attn_mma, cudaFuncAttributeMaxDynamicSharedMemorySize, ATT_SMEM);

    // ---- weight prep (transpose + tf32 round) ----
    wprep<<<dim3(D_MODEL/32, D_MODEL/32),256>>>(Wgate, WgT, D_MODEL, D_MODEL);
    wprep<<<dim3(D_MODEL/32, D_MODEL/32),256>>>(Wq,    WqT, D_MODEL, D_MODEL);
    wprep<<<dim3(D_MODEL/32, D_MODEL/32),256>>>(Wk,    WkT, D_MODEL, D_MODEL);
    wprep<<<dim3(D_MODEL/32, D_MODEL/32),256>>>(Wv,    WvT, D_MODEL, D_MODEL);
    wprep<<<dim3(D_MODEL/32, D_MODEL/32),256>>>(Wo,    WoT, D_MODEL, D_MODEL);
    wprep<<<dim3(DFF/32,     D_MODEL/32),256>>>(W1,    W1T, D_MODEL, DFF);
    wprep<<<dim3(D_MODEL/32, DFF/32),    256>>>(W2,    W2T, DFF,     D_MODEL);
    wprep<<<dim3(D_MODEL/32, 2*D_MODEL/32),256>>>(Wf,  WfT, 2*D_MODEL, D_MODEL);

    const dim3 gD(D_MODEL/128, ROWS/128);   // (8, 64)
    const dim3 gF(DFF/128,     ROWS/128);   // (32, 64)

    // Mamba branch prep
    ln_kernel<<<ROWS,256>>>(x, ln_g, ln_b, xn, ln1_g, ln1_b, xn1, 1);
    delta_bt_kernel<<<ROWS,256>>>(xn, Wdelta, bdelta, Win, b_in, delta, bt);
    scan_kernel<<<BATCH,32>>>(delta, bt, Amat, h);
    gemm_mma<1,0><<<gD,256,GEMM_SMEM>>>(xn, WgT, bgate, nullptr, gate, D_MODEL, D_MODEL, D_MODEL, D_MODEL, 0);
    mamba_out_kernel<<<ROWS,256>>>(h, Cmat, gate, x, cat);     // cat[:,0:1024]

    // Transformer branch: q/k/v (rounded for attention mma)
    gemm_mma<0,1><<<gD,256,GEMM_SMEM>>>(xn1, WqT, bq, nullptr, q, D_MODEL, D_MODEL, D_MODEL, D_MODEL, 0);
    gemm_mma<0,1><<<gD,256,GEMM_SMEM>>>(xn1, WkT, bk, nullptr, k, D_MODEL, D_MODEL, D_MODEL, D_MODEL, 0);
    gemm_mma<0,1><<<gD,256,GEMM_SMEM>>>(xn1, WvT, bv, nullptr, v, D_MODEL, D_MODEL, D_MODEL, D_MODEL, 0);

    attn_mma<<<dim3(SEQ/128, BATCH*NHEADS), 256, ATT_SMEM>>>(q, k, v, ctx);

    gemm_mma<0,0><<<gD,256,GEMM_SMEM>>>(ctx, WoT, bo, x, x2, D_MODEL, D_MODEL, D_MODEL, D_MODEL, D_MODEL);
    ln_kernel<<<ROWS,256>>>(x2, ln2_g, ln2_b, xn2, nullptr, nullptr, nullptr, 1);
    gemm_mma<2,1><<<gF,256,GEMM_SMEM>>>(xn2, W1T, b1, nullptr, ffn1, DFF, D_MODEL, D_MODEL, DFF, 0);
    // tout = x2 + ffn1@W2 + b2  -> cat[:,1024:2048] (rounded)
    gemm_mma<0,1><<<gD,256,GEMM_SMEM>>>(ffn1, W2T, b2, x2, cat + D_MODEL, D_MODEL, DFF, DFF, 2*D_MODEL, D_MODEL);

    // Fusion: y = cat @ Wf + bf  (K = 2048)
    gemm_mma<0,0><<<gD,256,GEMM_SMEM>>>(cat, WfT, bf, nullptr, y, D_MODEL, 2*D_MODEL, 2*D_MODEL, D_MODEL, 0);

    // Final LN -> output
    ln_kernel<<<ROWS,256>>>(y, lnf_g, lnf_b, (float*)d_out, nullptr, nullptr, nullptr, 0);
}

// round 6
// speedup vs baseline: 10.6050x; 1.6539x over previous
#include <cuda_runtime.h>
#include <cuda_fp16.h>
#include <cstdint>
#include <math.h>

#define D_MODEL 1024
#define SEQ     2048
#define BATCH   4
#define ROWS    (BATCH*SEQ)   // 8192
#define DS      16
#define DFF     4096
#define NHEADS  8
#define HDIM    128

// ---------------- scratch ----------------
__device__ __half g_xnh  [ROWS*D_MODEL];
__device__ __half g_xn1h [ROWS*D_MODEL];
__device__ __half g_qkvh [ROWS*3*D_MODEL];     // q|k|v packed, pitch 3072
__device__ __half g_ctxh [ROWS*D_MODEL];
__device__ __half g_xn2h [ROWS*D_MODEL];
__device__ __half g_ffn1h[ROWS*DFF];
__device__ __half g_cath [ROWS*2*D_MODEL];     // [mamba | tout], pitch 2048
__device__ float  g_gate [ROWS*D_MODEL];
__device__ float  g_x2   [ROWS*D_MODEL];
__device__ float  g_y    [ROWS*D_MODEL];
__device__ float  g_delta[ROWS*DS];
__device__ float  g_bt   [ROWS*DS];
__device__ float  g_h    [ROWS*DS];
__device__ float  g_bqkv [3*D_MODEL];
// transposed fp16 weights [N][K]
__device__ __half g_WgT [D_MODEL*D_MODEL];
__device__ __half g_WqkvT[3*D_MODEL*D_MODEL];
__device__ __half g_WoT [D_MODEL*D_MODEL];
__device__ __half g_W1T [DFF*D_MODEL];
__device__ __half g_W2T [D_MODEL*DFF];
__device__ __half g_WfT [D_MODEL*2*D_MODEL];

__device__ __forceinline__ float tanh_fast(float x){
    float y; asm("tanh.approx.f32 %0, %1;" : "=f"(y) : "f"(x)); return y;
}
__device__ __forceinline__ uint32_t smem_to_u32(const void* p){
    uint32_t a;
    asm("{ .reg .u64 t; cvta.to.shared.u64 t, %1; cvt.u32.u64 %0, t; }" : "=r"(a) : "l"(p));
    return a;
}
#define SWZ(o) ((o) ^ (((o) >> 3) & 0x70))

__device__ __forceinline__ void ldm_x4(uint32_t* r, uint32_t addr){
    asm volatile("ldmatrix.sync.aligned.m8n8.x4.shared.b16 {%0,%1,%2,%3}, [%4];"
        : "=r"(r[0]), "=r"(r[1]), "=r"(r[2]), "=r"(r[3]) : "r"(addr));
}
__device__ __forceinline__ void ldm_x4t(uint32_t* r, uint32_t addr){
    asm volatile("ldmatrix.sync.aligned.m8n8.x4.trans.shared.b16 {%0,%1,%2,%3}, [%4];"
        : "=r"(r[0]), "=r"(r[1]), "=r"(r[2]), "=r"(r[3]) : "r"(addr));
}
__device__ __forceinline__ void mma_fp16(float* d, const uint32_t* a, uint32_t b0, uint32_t b1){
    asm volatile("mma.sync.aligned.m16n8k16.row.col.f32.f16.f16.f32 "
        "{%0,%1,%2,%3}, {%4,%5,%6,%7}, {%8,%9}, {%0,%1,%2,%3};"
        : "+f"(d[0]), "+f"(d[1]), "+f"(d[2]), "+f"(d[3])
        : "r"(a[0]), "r"(a[1]), "r"(a[2]), "r"(a[3]), "r"(b0), "r"(b1));
}
__device__ __forceinline__ void cp16(uint32_t dst, const void* src){
    asm volatile("cp.async.cg.shared.global [%0], [%1], 16;" :: "r"(dst), "l"(src));
}
#define CP_COMMIT() asm volatile("cp.async.commit_group;" ::: "memory")
#define CP_WAIT1()  asm volatile("cp.async.wait_group 1;" ::: "memory")

// ---------------- weight prep: transpose + fp16  src[K][N] -> dst[N][K] ----------------
__global__ void __launch_bounds__(256) wprep(const float* __restrict__ src, __half* __restrict__ dst,
                                             int K, int N){
    __shared__ float t[32][33];
    const int n0 = blockIdx.x*32, k0 = blockIdx.y*32;
    const int x = threadIdx.x & 31, y = threadIdx.x >> 5;
    #pragma unroll
    for (int j=0;j<4;j++) t[y*4+j][x] = src[(size_t)(k0+y*4+j)*N + n0 + x];
    __syncthreads();
    #pragma unroll
    for (int j=0;j<4;j++)
        dst[(size_t)(n0+y*4+j)*K + k0 + x] = __float2half_rn(t[x][y*4+j]);
}

__global__ void __launch_bounds__(256) biaspack(const float* bq, const float* bk, const float* bv,
                                                float* out){
    const int i = blockIdx.x*256 + threadIdx.x;
    if (i < D_MODEL){ out[i]=bq[i]; out[i+D_MODEL]=bk[i]; out[i+2*D_MODEL]=bv[i]; }
}

// ---------------- fp16 mma GEMM, cp.async 3-stage, tile 128x128 x k64 ----------------
// A: MxK fp16 (lda halves). Bt: NxK fp16 (pitch K). bias/res fp32. Out: fp32 Cf or fp16 Ch.
#define GEMM_SMEM (3*32768)
template<int ACT, int OUTH>
__global__ void __launch_bounds__(256,2) gemm_mma(
    const __half* __restrict__ A, const __half* __restrict__ Bt,
    const float* __restrict__ bias, const float* __restrict__ res,
    float* __restrict__ Cf, __half* __restrict__ Ch,
    int K, int lda, int ldc, int ldr)
{
    extern __shared__ char smem[];
    const uint32_t sbase = smem_to_u32(smem);
    const int tid = threadIdx.x;
    const int lane = tid & 31, wid = tid >> 5;
    const int warp_m = wid >> 2, warp_n = wid & 3;
    const int row0 = blockIdx.y*128, col0 = blockIdx.x*128;
    const int sub = lane>>3, rr = lane&7;

    const __half* Ag = A  + (size_t)row0*lda;
    const __half* Bg = Bt + (size_t)col0*K;

    float acc[4][4][4];
    #pragma unroll
    for (int i=0;i<4;i++)
        #pragma unroll
        for (int j=0;j<4;j++){ acc[i][j][0]=0.f; acc[i][j][1]=0.f; acc[i][j][2]=0.f; acc[i][j][3]=0.f; }

    const int nk = K>>6;
    auto issue = [&](int kt){
        const uint32_t sA = sbase + (kt%3)*32768;
        const uint32_t sB = sA + 16384;
        const int koff = kt*64;
        #pragma unroll
        for (int i=0;i<4;i++){
            const int f = tid + i*256, r = f>>3, seg = f&7;
            cp16(sA + SWZ((uint32_t)(r*128 + seg*16)), Ag + (size_t)r*lda + koff + seg*8);
            cp16(sB + SWZ((uint32_t)(r*128 + seg*16)), Bg + (size_t)r*K   + koff + seg*8);
        }
    };
    issue(0); CP_COMMIT();
    if (nk>1) issue(1); CP_COMMIT();

    for (int kt=0; kt<nk; ++kt){
        CP_WAIT1();
        __syncthreads();
        if (kt+2 < nk) issue(kt+2);
        CP_COMMIT();
        const uint32_t aB = sbase + (kt%3)*32768;
        const uint32_t bB = aB + 16384;
        #pragma unroll
        for (int s=0;s<4;s++){
            uint32_t af[4][4], bf[2][4];
            #pragma unroll
            for (int mt=0;mt<4;mt++){
                const int m = warp_m*64 + mt*16 + (sub&1)*8 + rr;
                ldm_x4(af[mt], aB + SWZ((uint32_t)(m*128 + s*32 + (sub>>1)*16)));
            }
            #pragma unroll
            for (int p=0;p<2;p++){
                const int n = warp_n*32 + p*16 + (sub&1)*8 + rr;
                ldm_x4(bf[p], bB + SWZ((uint32_t)(n*128 + s*32 + (sub>>1)*16)));
            }
            #pragma unroll
            for (int mt=0;mt<4;mt++)
                #pragma unroll
                for (int p=0;p<2;p++){
                    mma_fp16(acc[mt][p*2+0], af[mt], bf[p][0], bf[p][2]);
                    mma_fp16(acc[mt][p*2+1], af[mt], bf[p][1], bf[p][3]);
                }
        }
        __syncthreads();
    }

    // epilogue via smem staging (pitch 132 floats)
    float* Es = (float*)smem;
    const int qrow = lane>>2, qcol = (lane&3)*2;
    #pragma unroll
    for (int mt=0;mt<4;mt++)
        #pragma unroll
        for (int nt=0;nt<4;nt++)
            #pragma unroll
            for (int half=0; half<2; half++){
                const int r = warp_m*64 + mt*16 + qrow + half*8;
                const int c = warp_n*32 + nt*8 + qcol;
                *(float2*)&Es[r*132 + c] = make_float2(acc[mt][nt][half*2], acc[mt][nt][half*2+1]);
            }
    __syncthreads();
    #pragma unroll
    for (int i=0;i<16;i++){
        const int f = tid + i*256, r = f>>5, c4 = (f&31)<<2;
        float4 v = *(float4*)&Es[r*132 + c4];
        const int col = col0 + c4;
        if (bias){
            const float4 bb = *(const float4*)(bias + col);
            v.x+=bb.x; v.y+=bb.y; v.z+=bb.z; v.w+=bb.w;
        }
        if (ACT==1){
            v.x=1.f/(1.f+__expf(-v.x)); v.y=1.f/(1.f+__expf(-v.y));
            v.z=1.f/(1.f+__expf(-v.z)); v.w=1.f/(1.f+__expf(-v.w));
        } else if (ACT==2){
            v.x=fmaxf(v.x,0.f); v.y=fmaxf(v.y,0.f); v.z=fmaxf(v.z,0.f); v.w=fmaxf(v.w,0.f);
        }
        if (res){
            const float4 rv = *(const float4*)(res + (size_t)(row0+r)*ldr + col);
            v.x+=rv.x; v.y+=rv.y; v.z+=rv.z; v.w+=rv.w;
        }
        if (OUTH){
            __half* p = Ch + (size_t)(row0+r)*ldc + col;
            *(__half2*)(p)   = __floats2half2_rn(v.x, v.y);
            *(__half2*)(p+2) = __floats2half2_rn(v.z, v.w);
        } else {
            *(float4*)(Cf + (size_t)(row0+r)*ldc + col) = v;
        }
    }
}

// ---------------- fp16 mma flash attention ----------------
// grid (SEQ/128, BATCH*NHEADS), 256 thr (8 warps x 16 q-rows), QKV pitch 3072 halves.
// smem: Q 2 panels [128][128B] 32KB | K 2 panels [64][128B] 16KB | V 2 panels [64][128B] 16KB
//       | P 1 panel [128][128B] 16KB  = 80KB
#define ATT_SMEM (32768 + 16384 + 16384 + 16384)
__global__ void __launch_bounds__(256,2) attn_mma(
    const __half* __restrict__ QKV, __half* __restrict__ O)
{
    extern __shared__ char smem[];
    const uint32_t sQ = smem_to_u32(smem);
    const uint32_t sK = sQ + 32768;
    const uint32_t sV = sK + 16384;
    const uint32_t sP = sV + 16384;

    const int tid = threadIdx.x, lane = tid&31, wid = tid>>5;
    const int sub = lane>>3, rr = lane&7;
    const int qt = blockIdx.x;
    const int b  = blockIdx.y>>3, h = blockIdx.y&7;
    const int m0 = wid*16;
    const float scale = 0.08838834764831845f;

    const __half* Qb = QKV + ((size_t)(b*SEQ + qt*128))*3072 + h*HDIM;
    const __half* Kb = QKV + (size_t)b*SEQ*3072 + D_MODEL   + h*HDIM;
    const __half* Vb = QKV + (size_t)b*SEQ*3072 + 2*D_MODEL + h*HDIM;

    // Q tile [128 rows][128 halves] -> 2 panels
    #pragma unroll
    for (int i=0;i<8;i++){
        const int f = tid + i*256, r = f>>4, cs = f&15;
        const uint4 v = *(const uint4*)(Qb + (size_t)r*3072 + cs*8);
        *(uint4*)(smem + (cs>>3)*16384 + SWZ((uint32_t)(r*128 + (cs&7)*16))) = v;
    }

    float oacc[16][4];
    #pragma unroll
    for (int i=0;i<16;i++){ oacc[i][0]=0.f; oacc[i][1]=0.f; oacc[i][2]=0.f; oacc[i][3]=0.f; }
    float m_run[2] = {-1e30f,-1e30f}, l_run[2] = {0.f,0.f};

    for (int kv=0; kv<SEQ/64; ++kv){
        __syncthreads();
        // K,V tiles [64][128 halves] -> 2 panels each
        #pragma unroll
        for (int i=0;i<4;i++){
            const int f = tid + i*256, r = f>>4, cs = f&15;
            const uint4 kvv = *(const uint4*)(Kb + (size_t)(kv*64+r)*3072 + cs*8);
            *(uint4*)(smem + 32768 + (cs>>3)*8192 + SWZ((uint32_t)(r*128 + (cs&7)*16))) = kvv;
            const uint4 vvv = *(const uint4*)(Vb + (size_t)(kv*64+r)*3072 + cs*8);
            *(uint4*)(smem + 49152 + (cs>>3)*8192 + SWZ((uint32_t)(r*128 + (cs&7)*16))) = vvv;
        }
        __syncthreads();

        // ---- S = Q @ K^T : per warp rows m0..m0+15, cols 0..63 ----
        float sacc[8][4];
        #pragma unroll
        for (int i=0;i<8;i++){ sacc[i][0]=0.f; sacc[i][1]=0.f; sacc[i][2]=0.f; sacc[i][3]=0.f; }
        #pragma unroll
        for (int s=0;s<8;s++){
            const int p = s>>2, sk = s&3;
            uint32_t af[4], bf[4][4];
            {
                const int m = m0 + (sub&1)*8 + rr;
                ldm_x4(af, sQ + p*16384 + SWZ((uint32_t)(m*128 + sk*32 + (sub>>1)*16)));
            }
            #pragma unroll
            for (int g=0;g<4;g++){
                const int n = g*16 + (sub&1)*8 + rr;
                ldm_x4(bf[g], sK + p*8192 + SWZ((uint32_t)(n*128 + sk*32 + (sub>>1)*16)));
            }
            #pragma unroll
            for (int g=0;g<4;g++){
                mma_fp16(sacc[g*2+0], af, bf[g][0], bf[g][2]);
                mma_fp16(sacc[g*2+1], af, bf[g][1], bf[g][3]);
            }
        }

        // ---- FA2 softmax (rows warp-local; quad reduce) ----
        #pragma unroll
        for (int hh=0; hh<2; ++hh){
            float mx = -1e30f;
            #pragma unroll
            for (int nt=0;nt<8;nt++)
                mx = fmaxf(mx, fmaxf(sacc[nt][hh*2], sacc[nt][hh*2+1]));
            mx *= scale;
            mx = fmaxf(mx, __shfl_xor_sync(0xffffffffu, mx, 1));
            mx = fmaxf(mx, __shfl_xor_sync(0xffffffffu, mx, 2));
            const float mnew = fmaxf(m_run[hh], mx);
            const float alpha = __expf(m_run[hh] - mnew);
            float lsum = 0.f;
            const int prow = m0 + (lane>>2) + hh*8;
            #pragma unroll
            for (int nt=0;nt<8;nt++){
                const float p0 = __expf(scale*sacc[nt][hh*2+0] - mnew);
                const float p1 = __expf(scale*sacc[nt][hh*2+1] - mnew);
                lsum += p0 + p1;
                *(__half2*)(smem + 65536 + SWZ((uint32_t)(prow*128 + nt*16 + (lane&3)*4)))
                    = __floats2half2_rn(p0, p1);
            }
            lsum += __shfl_xor_sync(0xffffffffu, lsum, 1);
            lsum += __shfl_xor_sync(0xffffffffu, lsum, 2);
            #pragma unroll
            for (int nt=0;nt<16;nt++){ oacc[nt][hh*2] *= alpha; oacc[nt][hh*2+1] *= alpha; }
            l_run[hh] = l_run[hh]*alpha + lsum;
            m_run[hh] = mnew;
        }
        __syncwarp();

        // ---- O += P @ V : B frags via ldmatrix.trans on V[kv][d] ----
        #pragma unroll
        for (int s=0;s<4;s++){
            uint32_t af[4];
            {
                const int m = m0 + (sub&1)*8 + rr;
                ldm_x4(af, sP + SWZ((uint32_t)(m*128 + s*32 + (sub>>1)*16)));
            }
            #pragma unroll
            for (int g=0;g<8;g++){
                uint32_t vf[4];
                const int dbase = g*16;
                const int kvrow = s*16 + (sub&1)*8 + rr;
                const int dloc  = (dbase + (sub>>1)*8) & 63;
                ldm_x4t(vf, sV + (dbase>>6)*8192 + SWZ((uint32_t)(kvrow*128 + dloc*2)));
                mma_fp16(oacc[g*2+0], af, vf[0], vf[1]);
                mma_fp16(oacc[g*2+1], af, vf[2], vf[3]);
            }
        }
    }

    // epilogue: normalize, write ctx fp16 (pitch 1024)
    __half* Ob = O + ((size_t)(b*SEQ + qt*128))*D_MODEL + h*HDIM;
    #pragma unroll
    for (int hh=0; hh<2; ++hh){
        const float inv = 1.f/l_run[hh];
        const int row = m0 + (lane>>2) + hh*8;
        #pragma unroll
        for (int nt=0;nt<16;nt++){
            const int col = nt*8 + (lane&3)*2;
            *(__half2*)(Ob + (size_t)row*D_MODEL + col) =
                __floats2half2_rn(oacc[nt][hh*2]*inv, oacc[nt][hh*2+1]*inv);
        }
    }
}

// ---------------- LayerNorm -> fp16 (dual) ----------------
__global__ void __launch_bounds__(256) ln_h(
    const float* __restrict__ x,
    const float* __restrict__ g0, const float* __restrict__ b0, __half* __restrict__ out0,
    const float* __restrict__ g1, const float* __restrict__ b1, __half* __restrict__ out1)
{
    __shared__ float red[64];
    const int row = blockIdx.x;
    const int tid = threadIdx.x;
    const float4 v = ((const float4*)(x + (size_t)row*D_MODEL))[tid];
    float s  = v.x+v.y+v.z+v.w;
    float sq = v.x*v.x+v.y*v.y+v.z*v.z+v.w*v.w;
    #pragma unroll
    for (int o=16;o;o>>=1){ s += __shfl_xor_sync(0xffffffffu,s,o); sq += __shfl_xor_sync(0xffffffffu,sq,o); }
    if ((tid&31)==0){ red[tid>>5]=s; red[(tid>>5)+8]=sq; }
    __syncthreads();
    if (tid<32){
        float ss=(tid<8)?red[tid]:0.f, qq=(tid<8)?red[tid+8]:0.f;
        #pragma unroll
        for (int o=4;o;o>>=1){ ss += __shfl_xor_sync(0xffffffffu,ss,o); qq += __shfl_xor_sync(0xffffffffu,qq,o); }
        if (tid==0){ red[32]=ss; red[33]=qq; }
    }
    __syncthreads();
    const float mean = red[32]*(1.f/D_MODEL);
    const float var  = red[33]*(1.f/D_MODEL) - mean*mean;
    const float inv  = rsqrtf(var + 1e-5f);
    {
        const float4 g = ((const float4*)g0)[tid];
        const float4 b = ((const float4*)b0)[tid];
        __half2 h0 = __floats2half2_rn((v.x-mean)*inv*g.x + b.x, (v.y-mean)*inv*g.y + b.y);
        __half2 h1 = __floats2half2_rn((v.z-mean)*inv*g.z + b.z, (v.w-mean)*inv*g.w + b.w);
        __half* p = out0 + (size_t)row*D_MODEL + tid*4;
        *(__half2*)p = h0; *(__half2*)(p+2) = h1;
    }
    if (out1){
        const float4 g = ((const float4*)g1)[tid];
        const float4 b = ((const float4*)b1)[tid];
        __half2 h0 = __floats2half2_rn((v.x-mean)*inv*g.x + b.x, (v.y-mean)*inv*g.y + b.y);
        __half2 h1 = __floats2half2_rn((v.z-mean)*inv*g.z + b.z, (v.w-mean)*inv*g.w + b.w);
        __half* p = out1 + (size_t)row*D_MODEL + tid*4;
        *(__half2*)p = h0; *(__half2*)(p+2) = h1;
    }
}

// ---------------- final LayerNorm -> fp32 ----------------
__global__ void __launch_bounds__(256) ln_f(
    const float* __restrict__ x,
    const float* __restrict__ g0, const float* __restrict__ b0, float* __restrict__ out0)
{
    __shared__ float red[64];
    const int row = blockIdx.x;
    const int tid = threadIdx.x;
    const float4 v = ((const float4*)(x + (size_t)row*D_MODEL))[tid];
    float s  = v.x+v.y+v.z+v.w;
    float sq = v.x*v.x+v.y*v.y+v.z*v.z+v.w*v.w;
    #pragma unroll
    for (int o=16;o;o>>=1){ s += __shfl_xor_sync(0xffffffffu,s,o); sq += __shfl_xor_sync(0xffffffffu,sq,o); }
    if ((tid&31)==0){ red[tid>>5]=s; red[(tid>>5)+8]=sq; }
    __syncthreads();
    if (tid<32){
        float ss=(tid<8)?red[tid]:0.f, qq=(tid<8)?red[tid+8]:0.f;
        #pragma unroll
        for (int o=4;o;o>>=1){ ss += __shfl_xor_sync(0xffffffffu,ss,o); qq += __shfl_xor_sync(0xffffffffu,qq,o); }
        if (tid==0){ red[32]=ss; red[33]=qq; }
    }
    __syncthreads();
    const float mean = red[32]*(1.f/D_MODEL);
    const float var  = red[33]*(1.f/D_MODEL) - mean*mean;
    const float inv  = rsqrtf(var + 1e-5f);
    const float4 g = ((const float4*)g0)[tid];
    const float4 b = ((const float4*)b0)[tid];
    float4 o0;
    o0.x = (v.x-mean)*inv*g.x + b.x;
    o0.y = (v.y-mean)*inv*g.y + b.y;
    o0.z = (v.z-mean)*inv*g.z + b.z;
    o0.w = (v.w-mean)*inv*g.w + b.w;
    ((float4*)(out0 + (size_t)row*D_MODEL))[tid] = o0;
}

// ---------------- delta / Bt (xn fp16 in) ----------------
__global__ void __launch_bounds__(256) delta_bt_kernel(
    const __half* __restrict__ xn,
    const float* __restrict__ Wd, const float* __restrict__ bd,
    const float* __restrict__ Wi, const float* __restrict__ bi,
    float* __restrict__ delta, float* __restrict__ bt)
{
    __shared__ float xs[D_MODEL];
    __shared__ float red[256];
    const int row = blockIdx.x, tid = threadIdx.x;
    #pragma unroll
    for (int i=0;i<4;i++) xs[tid + i*256] = __half2float(xn[(size_t)row*D_MODEL + tid + i*256]);
    __syncthreads();
    const int c = tid & 15;
    const int which = (tid>>4)&1;
    const int grp = tid>>5;
    const float* W = which ? Wi : Wd;
    float acc = 0.f;
    const int k0 = grp*128;
    #pragma unroll 8
    for (int k=0;k<128;k++) acc += xs[k0+k]*W[(size_t)(k0+k)*16 + c];
    red[tid]=acc; __syncthreads();
    if (tid<32){
        float sacc=0.f;
        #pragma unroll
        for (int g=0;g<8;g++) sacc += red[g*32+tid];
        if (tid<16) delta[(size_t)row*16+tid] = 1.f/(1.f+__expf(-(sacc+bd[tid])));
        else        bt   [(size_t)row*16+tid-16] = sacc + bi[tid-16];
    }
}

// ---------------- sequential mamba scan ----------------
__global__ void __launch_bounds__(32) scan_kernel(
    const float* __restrict__ delta, const float* __restrict__ bt,
    const float* __restrict__ A, float* __restrict__ h_all)
{
    __shared__ float ds[128*16], bs[128*16];
    const int b = blockIdx.x, lane = threadIdx.x;
    const int j = lane & 15;
    float Acol[16];
    #pragma unroll
    for (int i=0;i<16;i++) Acol[i] = A[i*16 + j];
    float h = 0.f;
    const float* dp = delta + (size_t)b*SEQ*16;
    const float* bp = bt    + (size_t)b*SEQ*16;
    float* hp = h_all + (size_t)b*SEQ*16;
    for (int chunk=0; chunk<SEQ; chunk+=128){
        const float4* s0 = (const float4*)(dp + (size_t)chunk*16);
        const float4* s1 = (const float4*)(bp + (size_t)chunk*16);
        for (int i=lane;i<512;i+=32){ ((float4*)ds)[i]=s0[i]; ((float4*)bs)[i]=s1[i]; }
        __syncwarp();
        #pragma unroll 4
        for (int t=0;t<128;t++){
            const float d = ds[t*16+j];
            const float bv = bs[t*16+j];
            const float v = h*d;
            float a0 = bv, a1 = 0.f;
            #pragma unroll
            for (int i=0;i<16;i+=2){
                a0 += __shfl_sync(0xffffffffu, v, i,   16)*Acol[i];
                a1 += __shfl_sync(0xffffffffu, v, i+1, 16)*Acol[i+1];
            }
            h = tanh_fast(a0+a1);
            if (lane<16) hp[(size_t)(chunk+t)*16 + j] = h;
        }
        __syncwarp();
    }
}

// ---------------- mamba_out -> cat[:,0:1024] fp16 ----------------
__global__ void __launch_bounds__(256) mamba_out_kernel(
    const float* __restrict__ h_all, const float* __restrict__ Cm,
    const float* __restrict__ gate, const float* __restrict__ x,
    __half* __restrict__ out)  // pitch 2048
{
    __shared__ float hs[16];
    const int row = blockIdx.x, tid = threadIdx.x;
    if (tid<16) hs[tid] = h_all[(size_t)row*16+tid];
    __syncthreads();
    const size_t base = (size_t)row*D_MODEL;
    const size_t obase = (size_t)row*2048;
    #pragma unroll
    for (int kk=0; kk<4; kk++){
        const int c = tid + kk*256;
        float acc = 0.f;
        #pragma unroll
        for (int i=0;i<16;i++) acc += hs[i]*Cm[(size_t)i*D_MODEL + c];
        out[obase+c] = __float2half_rn(acc*gate[base+c] + x[base+c]);
    }
}

// ---------------- launch ----------------
extern "C" void kernel_launch(void* const* d_in, const int* in_sizes, int n_in,
                              void* d_out, int out_size)
{
    const float* x      = (const float*)d_in[0];
    const float* ln_g   = (const float*)d_in[1];
    const float* ln_b   = (const float*)d_in[2];
    const float* Wdelta = (const float*)d_in[3];
    const float* bdelta = (const float*)d_in[4];
    const float* Win    = (const float*)d_in[5];
    const float* b_in   = (const float*)d_in[6];
    const float* Wgate  = (const float*)d_in[7];
    const float* bgate  = (const float*)d_in[8];
    const float* Amat   = (const float*)d_in[9];
    const float* Cmat   = (const float*)d_in[10];
    const float* ln1_g  = (const float*)d_in[11];
    const float* ln1_b  = (const float*)d_in[12];
    const float* Wq     = (const float*)d_in[13];
    const float* bq     = (const float*)d_in[14];
    const float* Wk     = (const float*)d_in[15];
    const float* bk     = (const float*)d_in[16];
    const float* Wv     = (const float*)d_in[17];
    const float* bv     = (const float*)d_in[18];
    const float* Wo     = (const float*)d_in[19];
    const float* bo     = (const float*)d_in[20];
    const float* ln2_g  = (const float*)d_in[21];
    const float* ln2_b  = (const float*)d_in[22];
    const float* W1     = (const float*)d_in[23];
    const float* b1     = (const float*)d_in[24];
    const float* W2     = (const float*)d_in[25];
    const float* b2     = (const float*)d_in[26];
    const float* Wf     = (const float*)d_in[27];
    const float* bf     = (const float*)d_in[28];
    const float* lnf_g  = (const float*)d_in[29];
    const float* lnf_b  = (const float*)d_in[30];

    __half *xnh,*xn1h,*qkvh,*ctxh,*xn2h,*ffn1h,*cath;
    __half *WgT,*WqkvT,*WoT,*W1T,*W2T,*WfT;
    float *gate,*x2,*y,*delta,*bt,*h,*bqkv;
    cudaGetSymbolAddress((void**)&xnh,  g_xnh);
    cudaGetSymbolAddress((void**)&xn1h, g_xn1h);
    cudaGetSymbolAddress((void**)&qkvh, g_qkvh);
    cudaGetSymbolAddress((void**)&ctxh, g_ctxh);
    cudaGetSymbolAddress((void**)&xn2h, g_xn2h);
    cudaGetSymbolAddress((void**)&ffn1h,g_ffn1h);
    cudaGetSymbolAddress((void**)&cath, g_cath);
    cudaGetSymbolAddress((void**)&gate, g_gate);
    cudaGetSymbolAddress((void**)&x2,   g_x2);
    cudaGetSymbolAddress((void**)&y,    g_y);
    cudaGetSymbolAddress((void**)&delta,g_delta);
    cudaGetSymbolAddress((void**)&bt,   g_bt);
    cudaGetSymbolAddress((void**)&h,    g_h);
    cudaGetSymbolAddress((void**)&bqkv, g_bqkv);
    cudaGetSymbolAddress((void**)&WgT,  g_WgT);
    cudaGetSymbolAddress((void**)&WqkvT,g_WqkvT);
    cudaGetSymbolAddress((void**)&WoT,  g_WoT);
    cudaGetSymbolAddress((void**)&W1T,  g_W1T);
    cudaGetSymbolAddress((void**)&W2T,  g_W2T);
    cudaGetSymbolAddress((void**)&WfT,  g_WfT);

    cudaFuncSetAttribute(gemm_mma<0,0>, cudaFuncAttributeMaxDynamicSharedMemorySize, GEMM_SMEM);
    cudaFuncSetAttribute(gemm_mma<0,1>, cudaFuncAttributeMaxDynamicSharedMemorySize, GEMM_SMEM);
    cudaFuncSetAttribute(gemm_mma<1,0>, cudaFuncAttributeMaxDynamicSharedMemorySize, GEMM_SMEM);
    cudaFuncSetAttribute(gemm_mma<2,1>, cudaFuncAttributeMaxDynamicSharedMemorySize, GEMM_SMEM);
    cudaFuncSetAttribute(attn_mma, cudaFuncAttributeMaxDynamicSharedMemorySize, ATT_SMEM);

    const dim3 gD(D_MODEL/128, ROWS/128);   // (8, 64)
    const dim3 gQKV(3*D_MODEL/128, ROWS/128);
    const dim3 gF(DFF/128,     ROWS/128);

    // 1-3: qkv weight prep (packed)
    wprep<<<dim3(D_MODEL/32, D_MODEL/32),256>>>(Wq, WqkvT,                    D_MODEL, D_MODEL);
    wprep<<<dim3(D_MODEL/32, D_MODEL/32),256>>>(Wk, WqkvT + D_MODEL*D_MODEL,  D_MODEL, D_MODEL);
    wprep<<<dim3(D_MODEL/32, D_MODEL/32),256>>>(Wv, WqkvT + 2*D_MODEL*D_MODEL,D_MODEL, D_MODEL);
    // 4: dual LN
    ln_h<<<ROWS,256>>>(x, ln_g, ln_b, xnh, ln1_g, ln1_b, xn1h);
    // 5: bias pack
    biaspack<<<4,256>>>(bq, bk, bv, bqkv);
    // 6: fused qkv GEMM (profiled by ncu -s 5 -c 1)
    gemm_mma<0,1><<<gQKV,256,GEMM_SMEM>>>(xn1h, WqkvT, bqkv, nullptr, nullptr, qkvh, D_MODEL, D_MODEL, 3*D_MODEL, 0);
    // 7-8: gate
    wprep<<<dim3(D_MODEL/32, D_MODEL/32),256>>>(Wgate, WgT, D_MODEL, D_MODEL);
    gemm_mma<1,0><<<gD,256,GEMM_SMEM>>>(xnh, WgT, bgate, nullptr, gate, nullptr, D_MODEL, D_MODEL, D_MODEL, 0);
    // 9-11: mamba
    delta_bt_kernel<<<ROWS,256>>>(xnh, Wdelta, bdelta, Win, b_in, delta, bt);
    scan_kernel<<<BATCH,32>>>(delta, bt, Amat, h);
    mamba_out_kernel<<<ROWS,256>>>(h, Cmat, gate, x, cath);
    // 12: attention
    attn_mma<<<dim3(SEQ/128, BATCH*NHEADS), 256, ATT_SMEM>>>(qkvh, ctxh);
    // 13-14: Wo + residual
    wprep<<<dim3(D_MODEL/32, D_MODEL/32),256>>>(Wo, WoT, D_MODEL, D_MODEL);
    gemm_mma<0,0><<<gD,256,GEMM_SMEM>>>(ctxh, WoT, bo, x, x2, nullptr, D_MODEL, D_MODEL, D_MODEL, D_MODEL);
    // 15: ln2
    ln_h<<<ROWS,256>>>(x2, ln2_g, ln2_b, xn2h, nullptr, nullptr, nullptr);
    // 16-17: W1 (relu)
    wprep<<<dim3(DFF/32, D_MODEL/32),256>>>(W1, W1T, D_MODEL, DFF);
    gemm_mma<2,1><<<gF,256,GEMM_SMEM>>>(xn2h, W1T, b1, nullptr, nullptr, ffn1h, D_MODEL, D_MODEL, DFF, 0);
    // 18-19: W2 + residual -> cat[:,1024:]
    wprep<<<dim3(D_MODEL/32, DFF/32),256>>>(W2, W2T, DFF, D_MODEL);
    gemm_mma<0,1><<<gD,256,GEMM_SMEM>>>(ffn1h, W2T, b2, x2, nullptr, cath + D_MODEL, DFF, DFF, 2*D_MODEL, D_MODEL);
    // 20-21: fusion (K=2048)
    wprep<<<dim3(D_MODEL/32, 2*D_MODEL/32),256>>>(Wf, WfT, 2*D_MODEL, D_MODEL);
    gemm_mma<0,0><<<gD,256,GEMM_SMEM>>>(cath, WfT, bf, nullptr, y, nullptr, 2*D_MODEL, 2*D_MODEL, D_MODEL, 0);
    // 22: final LN -> out
    ln_f<<<ROWS,256>>>(y, lnf_g, lnf_b, (float*)d_out);
}

// round 7
// speedup vs baseline: 11.4115x; 1.0760x over previous
#include <cuda_runtime.h>
#include <cuda_fp16.h>
#include <cstdint>
#include <math.h>

#define D_MODEL 1024
#define SEQ     2048
#define BATCH   4
#define ROWS    (BATCH*SEQ)   // 8192
#define DS      16
#define DFF     4096
#define NHEADS  8
#define HDIM    128

// ---------------- scratch ----------------
__device__ __half g_xnh  [ROWS*D_MODEL];
__device__ __half g_xn1h [ROWS*D_MODEL];
__device__ __half g_qkvh [ROWS*3*D_MODEL];     // q|k|v packed, pitch 3072
__device__ __half g_ctxh [ROWS*D_MODEL];
__device__ __half g_xn2h [ROWS*D_MODEL];
__device__ __half g_ffn1h[ROWS*DFF];
__device__ __half g_cath [ROWS*2*D_MODEL];     // [mamba | tout], pitch 2048
__device__ __half g_gateh[ROWS*D_MODEL];
__device__ float  g_x2   [ROWS*D_MODEL];
__device__ float  g_y    [ROWS*D_MODEL];
__device__ float  g_delta[ROWS*DS];
__device__ float  g_bt   [ROWS*DS];
__device__ float  g_h    [ROWS*DS];
__device__ float  g_bqkv [3*D_MODEL];
// fp16 weights, ORIGINAL [K][N] row-major orientation
__device__ __half g_Wgh  [D_MODEL*D_MODEL];
__device__ __half g_Wqkvh[D_MODEL*3*D_MODEL];  // pitch 3072
__device__ __half g_Woh  [D_MODEL*D_MODEL];
__device__ __half g_W1h  [D_MODEL*DFF];
__device__ __half g_W2h  [DFF*D_MODEL];
__device__ __half g_Wfh  [2*D_MODEL*D_MODEL];

__device__ __forceinline__ float tanh_fast(float x){
    float y; asm("tanh.approx.f32 %0, %1;" : "=f"(y) : "f"(x)); return y;
}
__device__ __forceinline__ uint32_t smem_to_u32(const void* p){
    uint32_t a;
    asm("{ .reg .u64 t; cvta.to.shared.u64 t, %1; cvt.u32.u64 %0, t; }" : "=r"(a) : "l"(p));
    return a;
}
#define SWZ(o) ((o) ^ (((o) >> 3) & 0x70))

__device__ __forceinline__ void ldm_x4(uint32_t* r, uint32_t addr){
    asm volatile("ldmatrix.sync.aligned.m8n8.x4.shared.b16 {%0,%1,%2,%3}, [%4];"
        : "=r"(r[0]), "=r"(r[1]), "=r"(r[2]), "=r"(r[3]) : "r"(addr));
}
__device__ __forceinline__ void ldm_x4t(uint32_t* r, uint32_t addr){
    asm volatile("ldmatrix.sync.aligned.m8n8.x4.trans.shared.b16 {%0,%1,%2,%3}, [%4];"
        : "=r"(r[0]), "=r"(r[1]), "=r"(r[2]), "=r"(r[3]) : "r"(addr));
}
__device__ __forceinline__ void mma_fp16(float* d, const uint32_t* a, uint32_t b0, uint32_t b1){
    asm volatile("mma.sync.aligned.m16n8k16.row.col.f32.f16.f16.f32 "
        "{%0,%1,%2,%3}, {%4,%5,%6,%7}, {%8,%9}, {%0,%1,%2,%3};"
        : "+f"(d[0]), "+f"(d[1]), "+f"(d[2]), "+f"(d[3])
        : "r"(a[0]), "r"(a[1]), "r"(a[2]), "r"(a[3]), "r"(b0), "r"(b1));
}
__device__ __forceinline__ void cp16(uint32_t dst, const void* src){
    asm volatile("cp.async.cg.shared.global [%0], [%1], 16;" :: "r"(dst), "l"(src));
}
#define CP_COMMIT() asm volatile("cp.async.commit_group;" ::: "memory")
#define CP_WAIT1()  asm volatile("cp.async.wait_group 1;" ::: "memory")

// ---------------- weight convert: fp32 [K][N] -> fp16 same layout, dst pitch ldn, col offset ----------------
__global__ void __launch_bounds__(256) wcvt(const float* __restrict__ src, __half* __restrict__ dst,
                                            int N, int ldn, int coff, int total4){
    const int i = blockIdx.x*256 + threadIdx.x;
    if (i >= total4) return;
    const int e = i*4;
    const int row = e / N, col = e % N;
    const float4 v = *(const float4*)(src + e);
    __half* p = dst + (size_t)row*ldn + coff + col;
    *(__half2*)(p)   = __floats2half2_rn(v.x, v.y);
    *(__half2*)(p+2) = __floats2half2_rn(v.z, v.w);
}

__global__ void __launch_bounds__(256) biaspack(const float* bq, const float* bk, const float* bv,
                                                float* out){
    const int i = blockIdx.x*256 + threadIdx.x;
    if (i < D_MODEL){ out[i]=bq[i]; out[i+D_MODEL]=bk[i]; out[i+2*D_MODEL]=bv[i]; }
}

// ---------------- fp16 mma GEMM, cp.async 3-stage, tile 128x128 x k64, B row-major [K][N] ----------------
#define GEMM_SMEM (3*32768)
template<int ACT, int OUTH>
__global__ void __launch_bounds__(256,2) gemm_mma(
    const __half* __restrict__ A, const __half* __restrict__ B,
    const float* __restrict__ bias, const float* __restrict__ res,
    float* __restrict__ Cf, __half* __restrict__ Ch,
    int K, int lda, int ldb, int ldc, int ldr)
{
    extern __shared__ char smem[];
    const uint32_t sbase = smem_to_u32(smem);
    const int tid = threadIdx.x;
    const int lane = tid & 31, wid = tid >> 5;
    const int warp_m = wid >> 2, warp_n = wid & 3;
    const int row0 = blockIdx.y*128, col0 = blockIdx.x*128;
    const int sub = lane>>3, rr = lane&7;

    const __half* Ag = A + (size_t)row0*lda;
    const __half* Bg = B + col0;

    float acc[4][4][4];
    #pragma unroll
    for (int i=0;i<4;i++)
        #pragma unroll
        for (int j=0;j<4;j++){ acc[i][j][0]=0.f; acc[i][j][1]=0.f; acc[i][j][2]=0.f; acc[i][j][3]=0.f; }

    const int nk = K>>6;
    auto issue = [&](int kt){
        const uint32_t sA = sbase + (kt%3)*32768;
        const uint32_t sB = sA + 16384;
        const int koff = kt*64;
        #pragma unroll
        for (int i=0;i<4;i++){
            const int f = tid + i*256;
            // A: [128 rows][64 halves] (128B swizzled rows)
            const int ar = f>>3, aseg = f&7;
            cp16(sA + SWZ((uint32_t)(ar*128 + aseg*16)), Ag + (size_t)ar*lda + koff + aseg*8);
            // B: [64 k-rows][128 n-halves] -> 2 panels [64][64]
            const int br = f>>4, cs = f&15;
            cp16(sB + (cs>>3)*8192 + SWZ((uint32_t)(br*128 + (cs&7)*16)),
                 Bg + (size_t)(koff+br)*ldb + cs*8);
        }
    };
    issue(0); CP_COMMIT();
    if (nk>1) issue(1); CP_COMMIT();

    for (int kt=0; kt<nk; ++kt){
        CP_WAIT1();
        __syncthreads();
        if (kt+2 < nk) issue(kt+2);
        CP_COMMIT();
        const uint32_t aB = sbase + (kt%3)*32768;
        const uint32_t bB = aB + 16384;
        #pragma unroll
        for (int s=0;s<4;s++){
            uint32_t af[4][4], bf[2][4];
            #pragma unroll
            for (int mt=0;mt<4;mt++){
                const int m = warp_m*64 + mt*16 + (sub&1)*8 + rr;
                ldm_x4(af[mt], aB + SWZ((uint32_t)(m*128 + s*32 + (sub>>1)*16)));
            }
            #pragma unroll
            for (int p=0;p<2;p++){
                const int kr = s*16 + (sub&1)*8 + rr;
                const int nbase = warp_n*32 + p*16;
                const int dloc = (nbase&63) + (sub>>1)*8;
                ldm_x4t(bf[p], bB + (nbase>>6)*8192 + SWZ((uint32_t)(kr*128 + dloc*2)));
            }
            #pragma unroll
            for (int mt=0;mt<4;mt++)
                #pragma unroll
                for (int p=0;p<2;p++){
                    mma_fp16(acc[mt][p*2+0], af[mt], bf[p][0], bf[p][1]);
                    mma_fp16(acc[mt][p*2+1], af[mt], bf[p][2], bf[p][3]);
                }
        }
    }
    __syncthreads();

    // epilogue via smem staging (pitch 132 floats)
    float* Es = (float*)smem;
    const int qrow = lane>>2, qcol = (lane&3)*2;
    #pragma unroll
    for (int mt=0;mt<4;mt++)
        #pragma unroll
        for (int nt=0;nt<4;nt++)
            #pragma unroll
            for (int half=0; half<2; half++){
                const int r = warp_m*64 + mt*16 + qrow + half*8;
                const int c = warp_n*32 + nt*8 + qcol;
                *(float2*)&Es[r*132 + c] = make_float2(acc[mt][nt][half*2], acc[mt][nt][half*2+1]);
            }
    __syncthreads();
    #pragma unroll
    for (int i=0;i<16;i++){
        const int f = tid + i*256, r = f>>5, c4 = (f&31)<<2;
        float4 v = *(float4*)&Es[r*132 + c4];
        const int col = col0 + c4;
        if (bias){
            const float4 bb = *(const float4*)(bias + col);
            v.x+=bb.x; v.y+=bb.y; v.z+=bb.z; v.w+=bb.w;
        }
        if (ACT==1){
            v.x=1.f/(1.f+__expf(-v.x)); v.y=1.f/(1.f+__expf(-v.y));
            v.z=1.f/(1.f+__expf(-v.z)); v.w=1.f/(1.f+__expf(-v.w));
        } else if (ACT==2){
            v.x=fmaxf(v.x,0.f); v.y=fmaxf(v.y,0.f); v.z=fmaxf(v.z,0.f); v.w=fmaxf(v.w,0.f);
        }
        if (res){
            const float4 rv = *(const float4*)(res + (size_t)(row0+r)*ldr + col);
            v.x+=rv.x; v.y+=rv.y; v.z+=rv.z; v.w+=rv.w;
        }
        if (OUTH){
            __half* p = Ch + (size_t)(row0+r)*ldc + col;
            *(__half2*)(p)   = __floats2half2_rn(v.x, v.y);
            *(__half2*)(p+2) = __floats2half2_rn(v.z, v.w);
        } else {
            *(float4*)(Cf + (size_t)(row0+r)*ldc + col) = v;
        }
    }
}

// ---------------- fp16 mma flash attention, double-buffered KV via cp.async ----------------
// grid (SEQ/128, BATCH*NHEADS), 256 thr (8 warps x 16 q-rows), QKV pitch 3072 halves.
// smem: Q 32KB | K 2 bufs x 16KB | V 2 bufs x 16KB | P 16KB = 112KB
#define ATT_SMEM (32768 + 32768 + 32768 + 16384)
__global__ void __launch_bounds__(256,2) attn_mma(
    const __half* __restrict__ QKV, __half* __restrict__ O)
{
    extern __shared__ char smem[];
    const uint32_t sQ = smem_to_u32(smem);
    const uint32_t sK = sQ + 32768;
    const uint32_t sV = sK + 32768;
    const uint32_t sP = sV + 32768;

    const int tid = threadIdx.x, lane = tid&31, wid = tid>>5;
    const int sub = lane>>3, rr = lane&7;
    const int qt = blockIdx.x;
    const int b  = blockIdx.y>>3, h = blockIdx.y&7;
    const int m0 = wid*16;
    const float scale = 0.08838834764831845f;

    const __half* Qb = QKV + ((size_t)(b*SEQ + qt*128))*3072 + h*HDIM;
    const __half* Kb = QKV + (size_t)b*SEQ*3072 + D_MODEL   + h*HDIM;
    const __half* Vb = QKV + (size_t)b*SEQ*3072 + 2*D_MODEL + h*HDIM;

    auto issueKV = [&](int kv){
        const uint32_t kbuf = sK + (kv&1)*16384;
        const uint32_t vbuf = sV + (kv&1)*16384;
        #pragma unroll
        for (int i=0;i<4;i++){
            const int f = tid + i*256, r = f>>4, cs = f&15;
            const uint32_t off = (uint32_t)((cs>>3)*8192 + SWZ((uint32_t)(r*128 + (cs&7)*16)));
            cp16(kbuf + off, Kb + (size_t)(kv*64+r)*3072 + cs*8);
            cp16(vbuf + off, Vb + (size_t)(kv*64+r)*3072 + cs*8);
        }
    };

    // Q tile [128 rows][128 halves] -> 2 panels (plain loads, once)
    #pragma unroll
    for (int i=0;i<8;i++){
        const int f = tid + i*256, r = f>>4, cs = f&15;
        const uint4 v = *(const uint4*)(Qb + (size_t)r*3072 + cs*8);
        *(uint4*)(smem + (cs>>3)*16384 + SWZ((uint32_t)(r*128 + (cs&7)*16))) = v;
    }
    issueKV(0); CP_COMMIT();
    issueKV(1); CP_COMMIT();

    float oacc[16][4];
    #pragma unroll
    for (int i=0;i<16;i++){ oacc[i][0]=0.f; oacc[i][1]=0.f; oacc[i][2]=0.f; oacc[i][3]=0.f; }
    float m_run[2] = {-1e30f,-1e30f}, l_run[2] = {0.f,0.f};

    for (int kv=0; kv<SEQ/64; ++kv){
        CP_WAIT1();
        __syncthreads();
        const uint32_t kB = sK + (kv&1)*16384;
        const uint32_t vB = sV + (kv&1)*16384;

        // ---- S = Q @ K^T ----
        float sacc[8][4];
        #pragma unroll
        for (int i=0;i<8;i++){ sacc[i][0]=0.f; sacc[i][1]=0.f; sacc[i][2]=0.f; sacc[i][3]=0.f; }
        #pragma unroll
        for (int s=0;s<8;s++){
            const int p = s>>2, sk = s&3;
            uint32_t af[4], bf[4][4];
            {
                const int m = m0 + (sub&1)*8 + rr;
                ldm_x4(af, sQ + p*16384 + SWZ((uint32_t)(m*128 + sk*32 + (sub>>1)*16)));
            }
            #pragma unroll
            for (int g=0;g<4;g++){
                const int n = g*16 + (sub&1)*8 + rr;
                ldm_x4(bf[g], kB + p*8192 + SWZ((uint32_t)(n*128 + sk*32 + (sub>>1)*16)));
            }
            #pragma unroll
            for (int g=0;g<4;g++){
                mma_fp16(sacc[g*2+0], af, bf[g][0], bf[g][2]);
                mma_fp16(sacc[g*2+1], af, bf[g][1], bf[g][3]);
            }
        }

        // ---- FA2 softmax (rows warp-local; quad reduce) ----
        #pragma unroll
        for (int hh=0; hh<2; ++hh){
            float mx = -1e30f;
            #pragma unroll
            for (int nt=0;nt<8;nt++)
                mx = fmaxf(mx, fmaxf(sacc[nt][hh*2], sacc[nt][hh*2+1]));
            mx *= scale;
            mx = fmaxf(mx, __shfl_xor_sync(0xffffffffu, mx, 1));
            mx = fmaxf(mx, __shfl_xor_sync(0xffffffffu, mx, 2));
            const float mnew = fmaxf(m_run[hh], mx);
            const float alpha = __expf(m_run[hh] - mnew);
            float lsum = 0.f;
            const int prow = m0 + (lane>>2) + hh*8;
            #pragma unroll
            for (int nt=0;nt<8;nt++){
                const float p0 = __expf(scale*sacc[nt][hh*2+0] - mnew);
                const float p1 = __expf(scale*sacc[nt][hh*2+1] - mnew);
                lsum += p0 + p1;
                *(__half2*)(smem + 98304 + SWZ((uint32_t)(prow*128 + nt*16 + (lane&3)*4)))
                    = __floats2half2_rn(p0, p1);
            }
            lsum += __shfl_xor_sync(0xffffffffu, lsum, 1);
            lsum += __shfl_xor_sync(0xffffffffu, lsum, 2);
            #pragma unroll
            for (int nt=0;nt<16;nt++){ oacc[nt][hh*2] *= alpha; oacc[nt][hh*2+1] *= alpha; }
            l_run[hh] = l_run[hh]*alpha + lsum;
            m_run[hh] = mnew;
        }
        __syncwarp();

        // ---- O += P @ V ----
        #pragma unroll
        for (int s=0;s<4;s++){
            uint32_t af[4];
            {
                const int m = m0 + (sub&1)*8 + rr;
                ldm_x4(af, sP + SWZ((uint32_t)(m*128 + s*32 + (sub>>1)*16)));
            }
            #pragma unroll
            for (int g=0;g<8;g++){
                uint32_t vf[4];
                const int dbase = g*16;
                const int kvrow = s*16 + (sub&1)*8 + rr;
                const int dloc  = (dbase + (sub>>1)*8) & 63;
                ldm_x4t(vf, vB + (dbase>>6)*8192 + SWZ((uint32_t)(kvrow*128 + dloc*2)));
                mma_fp16(oacc[g*2+0], af, vf[0], vf[1]);
                mma_fp16(oacc[g*2+1], af, vf[2], vf[3]);
            }
        }
        __syncthreads();                      // all warps done with buf kv&1
        if (kv+2 < SEQ/64) issueKV(kv+2);
        CP_COMMIT();
    }

    // epilogue: normalize, write ctx fp16 (pitch 1024)
    __half* Ob = O + ((size_t)(b*SEQ + qt*128))*D_MODEL + h*HDIM;
    #pragma unroll
    for (int hh=0; hh<2; ++hh){
        const float inv = 1.f/l_run[hh];
        const int row = m0 + (lane>>2) + hh*8;
        #pragma unroll
        for (int nt=0;nt<16;nt++){
            const int col = nt*8 + (lane&3)*2;
            *(__half2*)(Ob + (size_t)row*D_MODEL + col) =
                __floats2half2_rn(oacc[nt][hh*2]*inv, oacc[nt][hh*2+1]*inv);
        }
    }
}

// ---------------- LayerNorm -> fp16 (dual) ----------------
__global__ void __launch_bounds__(256) ln_h(
    const float* __restrict__ x,
    const float* __restrict__ g0, const float* __restrict__ b0, __half* __restrict__ out0,
    const float* __restrict__ g1, const float* __restrict__ b1, __half* __restrict__ out1)
{
    __shared__ float red[64];
    const int row = blockIdx.x;
    const int tid = threadIdx.x;
    const float4 v = ((const float4*)(x + (size_t)row*D_MODEL))[tid];
    float s  = v.x+v.y+v.z+v.w;
    float sq = v.x*v.x+v.y*v.y+v.z*v.z+v.w*v.w;
    #pragma unroll
    for (int o=16;o;o>>=1){ s += __shfl_xor_sync(0xffffffffu,s,o); sq += __shfl_xor_sync(0xffffffffu,sq,o); }
    if ((tid&31)==0){ red[tid>>5]=s; red[(tid>>5)+8]=sq; }
    __syncthreads();
    if (tid<32){
        float ss=(tid<8)?red[tid]:0.f, qq=(tid<8)?red[tid+8]:0.f;
        #pragma unroll
        for (int o=4;o;o>>=1){ ss += __shfl_xor_sync(0xffffffffu,ss,o); qq += __shfl_xor_sync(0xffffffffu,qq,o); }
        if (tid==0){ red[32]=ss; red[33]=qq; }
    }
    __syncthreads();
    const float mean = red[32]*(1.f/D_MODEL);
    const float var  = red[33]*(1.f/D_MODEL) - mean*mean;
    const float inv  = rsqrtf(var + 1e-5f);
    {
        const float4 g = ((const float4*)g0)[tid];
        const float4 b = ((const float4*)b0)[tid];
        __half2 h0 = __floats2half2_rn((v.x-mean)*inv*g.x + b.x, (v.y-mean)*inv*g.y + b.y);
        __half2 h1 = __floats2half2_rn((v.z-mean)*inv*g.z + b.z, (v.w-mean)*inv*g.w + b.w);
        __half* p = out0 + (size_t)row*D_MODEL + tid*4;
        *(__half2*)p = h0; *(__half2*)(p+2) = h1;
    }
    if (out1){
        const float4 g = ((const float4*)g1)[tid];
        const float4 b = ((const float4*)b1)[tid];
        __half2 h0 = __floats2half2_rn((v.x-mean)*inv*g.x + b.x, (v.y-mean)*inv*g.y + b.y);
        __half2 h1 = __floats2half2_rn((v.z-mean)*inv*g.z + b.z, (v.w-mean)*inv*g.w + b.w);
        __half* p = out1 + (size_t)row*D_MODEL + tid*4;
        *(__half2*)p = h0; *(__half2*)(p+2) = h1;
    }
}

// ---------------- final LayerNorm -> fp32 ----------------
__global__ void __launch_bounds__(256) ln_f(
    const float* __restrict__ x,
    const float* __restrict__ g0, const float* __restrict__ b0, float* __restrict__ out0)
{
    __shared__ float red[64];
    const int row = blockIdx.x;
    const int tid = threadIdx.x;
    const float4 v = ((const float4*)(x + (size_t)row*D_MODEL))[tid];
    float s  = v.x+v.y+v.z+v.w;
    float sq = v.x*v.x+v.y*v.y+v.z*v.z+v.w*v.w;
    #pragma unroll
    for (int o=16;o;o>>=1){ s += __shfl_xor_sync(0xffffffffu,s,o); sq += __shfl_xor_sync(0xffffffffu,sq,o); }
    if ((tid&31)==0){ red[tid>>5]=s; red[(tid>>5)+8]=sq; }
    __syncthreads();
    if (tid<32){
        float ss=(tid<8)?red[tid]:0.f, qq=(tid<8)?red[tid+8]:0.f;
        #pragma unroll
        for (int o=4;o;o>>=1){ ss += __shfl_xor_sync(0xffffffffu,ss,o); qq += __shfl_xor_sync(0xffffffffu,qq,o); }
        if (tid==0){ red[32]=ss; red[33]=qq; }
    }
    __syncthreads();
    const float mean = red[32]*(1.f/D_MODEL);
    const float var  = red[33]*(1.f/D_MODEL) - mean*mean;
    const float inv  = rsqrtf(var + 1e-5f);
    const float4 g = ((const float4*)g0)[tid];
    const float4 b = ((const float4*)b0)[tid];
    float4 o0;
    o0.x = (v.x-mean)*inv*g.x + b.x;
    o0.y = (v.y-mean)*inv*g.y + b.y;
    o0.z = (v.z-mean)*inv*g.z + b.z;
    o0.w = (v.w-mean)*inv*g.w + b.w;
    ((float4*)(out0 + (size_t)row*D_MODEL))[tid] = o0;
}

// ---------------- delta / Bt (xn fp16 in) ----------------
__global__ void __launch_bounds__(256) delta_bt_kernel(
    const __half* __restrict__ xn,
    const float* __restrict__ Wd, const float* __restrict__ bd,
    const float* __restrict__ Wi, const float* __restrict__ bi,
    float* __restrict__ delta, float* __restrict__ bt)
{
    __shared__ float xs[D_MODEL];
    __shared__ float red[256];
    const int row = blockIdx.x, tid = threadIdx.x;
    #pragma unroll
    for (int i=0;i<4;i++) xs[tid + i*256] = __half2float(xn[(size_t)row*D_MODEL + tid + i*256]);
    __syncthreads();
    const int c = tid & 15;
    const int which = (tid>>4)&1;
    const int grp = tid>>5;
    const float* W = which ? Wi : Wd;
    float acc = 0.f;
    const int k0 = grp*128;
    #pragma unroll 8
    for (int k=0;k<128;k++) acc += xs[k0+k]*W[(size_t)(k0+k)*16 + c];
    red[tid]=acc; __syncthreads();
    if (tid<32){
        float sacc=0.f;
        #pragma unroll
        for (int g=0;g<8;g++) sacc += red[g*32+tid];
        if (tid<16) delta[(size_t)row*16+tid] = 1.f/(1.f+__expf(-(sacc+bd[tid])));
        else        bt   [(size_t)row*16+tid-16] = sacc + bi[tid-16];
    }
}

// ---------------- sequential mamba scan ----------------
__global__ void __launch_bounds__(32) scan_kernel(
    const float* __restrict__ delta, const float* __restrict__ bt,
    const float* __restrict__ A, float* __restrict__ h_all)
{
    __shared__ float ds[128*16], bs[128*16];
    const int b = blockIdx.x, lane = threadIdx.x;
    const int j = lane & 15;
    float Acol[16];
    #pragma unroll
    for (int i=0;i<16;i++) Acol[i] = A[i*16 + j];
    float h = 0.f;
    const float* dp = delta + (size_t)b*SEQ*16;
    const float* bp = bt    + (size_t)b*SEQ*16;
    float* hp = h_all + (size_t)b*SEQ*16;
    for (int chunk=0; chunk<SEQ; chunk+=128){
        const float4* s0 = (const float4*)(dp + (size_t)chunk*16);
        const float4* s1 = (const float4*)(bp + (size_t)chunk*16);
        for (int i=lane;i<512;i+=32){ ((float4*)ds)[i]=s0[i]; ((float4*)bs)[i]=s1[i]; }
        __syncwarp();
        #pragma unroll 4
        for (int t=0;t<128;t++){
            const float d = ds[t*16+j];
            const float bv = bs[t*16+j];
            const float v = h*d;
            float a0 = bv, a1 = 0.f;
            #pragma unroll
            for (int i=0;i<16;i+=2){
                a0 += __shfl_sync(0xffffffffu, v, i,   16)*Acol[i];
                a1 += __shfl_sync(0xffffffffu, v, i+1, 16)*Acol[i+1];
            }
            h = tanh_fast(a0+a1);
            if (lane<16) hp[(size_t)(chunk+t)*16 + j] = h;
        }
        __syncwarp();
    }
}

// ---------------- mamba_out -> cat[:,0:1024] fp16 (gate fp16 in) ----------------
__global__ void __launch_bounds__(256) mamba_out_kernel(
    const float* __restrict__ h_all, const float* __restrict__ Cm,
    const __half* __restrict__ gate, const float* __restrict__ x,
    __half* __restrict__ out)  // pitch 2048
{
    __shared__ float hs[16];
    const int row = blockIdx.x, tid = threadIdx.x;
    if (tid<16) hs[tid] = h_all[(size_t)row*16+tid];
    __syncthreads();
    const size_t base = (size_t)row*D_MODEL;
    const size_t obase = (size_t)row*2048;
    #pragma unroll
    for (int kk=0; kk<4; kk++){
        const int c = tid + kk*256;
        float acc = 0.f;
        #pragma unroll
        for (int i=0;i<16;i++) acc += hs[i]*Cm[(size_t)i*D_MODEL + c];
        out[obase+c] = __float2half_rn(acc*__half2float(gate[base+c]) + x[base+c]);
    }
}

// ---------------- launch ----------------
extern "C" void kernel_launch(void* const* d_in, const int* in_sizes, int n_in,
                              void* d_out, int out_size)
{
    const float* x      = (const float*)d_in[0];
    const float* ln_g   = (const float*)d_in[1];
    const float* ln_b   = (const float*)d_in[2];
    const float* Wdelta = (const float*)d_in[3];
    const float* bdelta = (const float*)d_in[4];
    const float* Win    = (const float*)d_in[5];
    const float* b_in   = (const float*)d_in[6];
    const float* Wgate  = (const float*)d_in[7];
    const float* bgate  = (const float*)d_in[8];
    const float* Amat   = (const float*)d_in[9];
    const float* Cmat   = (const float*)d_in[10];
    const float* ln1_g  = (const float*)d_in[11];
    const float* ln1_b  = (const float*)d_in[12];
    const float* Wq     = (const float*)d_in[13];
    const float* bq     = (const float*)d_in[14];
    const float* Wk     = (const float*)d_in[15];
    const float* bk     = (const float*)d_in[16];
    const float* Wv     = (const float*)d_in[17];
    const float* bv     = (const float*)d_in[18];
    const float* Wo     = (const float*)d_in[19];
    const float* bo     = (const float*)d_in[20];
    const float* ln2_g  = (const float*)d_in[21];
    const float* ln2_b  = (const float*)d_in[22];
    const float* W1     = (const float*)d_in[23];
    const float* b1     = (const float*)d_in[24];
    const float* W2     = (const float*)d_in[25];
    const float* b2     = (const float*)d_in[26];
    const float* Wf     = (const float*)d_in[27];
    const float* bf     = (const float*)d_in[28];
    const float* lnf_g  = (const float*)d_in[29];
    const float* lnf_b  = (const float*)d_in[30];

    __half *xnh,*xn1h,*qkvh,*ctxh,*xn2h,*ffn1h,*cath,*gateh;
    __half *Wgh,*Wqkvh,*Woh,*W1h,*W2h,*Wfh;
    float *x2,*y,*delta,*bt,*h,*bqkv;
    cudaGetSymbolAddress((void**)&xnh,  g_xnh);
    cudaGetSymbolAddress((void**)&xn1h, g_xn1h);
    cudaGetSymbolAddress((void**)&qkvh, g_qkvh);
    cudaGetSymbolAddress((void**)&ctxh, g_ctxh);
    cudaGetSymbolAddress((void**)&xn2h, g_xn2h);
    cudaGetSymbolAddress((void**)&ffn1h,g_ffn1h);
    cudaGetSymbolAddress((void**)&cath, g_cath);
    cudaGetSymbolAddress((void**)&gateh,g_gateh);
    cudaGetSymbolAddress((void**)&x2,   g_x2);
    cudaGetSymbolAddress((void**)&y,    g_y);
    cudaGetSymbolAddress((void**)&delta,g_delta);
    cudaGetSymbolAddress((void**)&bt,   g_bt);
    cudaGetSymbolAddress((void**)&h,    g_h);
    cudaGetSymbolAddress((void**)&bqkv, g_bqkv);
    cudaGetSymbolAddress((void**)&Wgh,  g_Wgh);
    cudaGetSymbolAddress((void**)&Wqkvh,g_Wqkvh);
    cudaGetSymbolAddress((void**)&Woh,  g_Woh);
    cudaGetSymbolAddress((void**)&W1h,  g_W1h);
    cudaGetSymbolAddress((void**)&W2h,  g_W2h);
    cudaGetSymbolAddress((void**)&Wfh,  g_Wfh);

    cudaFuncSetAttribute(gemm_mma<0,0>, cudaFuncAttributeMaxDynamicSharedMemorySize, GEMM_SMEM);
    cudaFuncSetAttribute(gemm_mma<0,1>, cudaFuncAttributeMaxDynamicSharedMemorySize, GEMM_SMEM);
    cudaFuncSetAttribute(gemm_mma<1,1>, cudaFuncAttributeMaxDynamicSharedMemorySize, GEMM_SMEM);
    cudaFuncSetAttribute(gemm_mma<2,1>, cudaFuncAttributeMaxDynamicSharedMemorySize, GEMM_SMEM);
    cudaFuncSetAttribute(attn_mma, cudaFuncAttributeMaxDynamicSharedMemorySize, ATT_SMEM);

    const dim3 gD(D_MODEL/128, ROWS/128);   // (8, 64)
    const dim3 gQKV(3*D_MODEL/128, ROWS/128);
    const dim3 gF(DFF/128,     ROWS/128);

    const int M4 = D_MODEL*D_MODEL/4;       // 256K float4 per 1024x1024
    // 1-3: qkv weight convert (packed into pitch 3072)
    wcvt<<<M4/256,256>>>(Wq, Wqkvh, D_MODEL, 3*D_MODEL, 0,         M4);
    wcvt<<<M4/256,256>>>(Wk, Wqkvh, D_MODEL, 3*D_MODEL, D_MODEL,   M4);
    wcvt<<<M4/256,256>>>(Wv, Wqkvh, D_MODEL, 3*D_MODEL, 2*D_MODEL, M4);
    // 4: dual LN
    ln_h<<<ROWS,256>>>(x, ln_g, ln_b, xnh, ln1_g, ln1_b, xn1h);
    // 5: bias pack
    biaspack<<<4,256>>>(bq, bk, bv, bqkv);
    // 6: fused qkv GEMM
    gemm_mma<0,1><<<gQKV,256,GEMM_SMEM>>>(xn1h, Wqkvh, bqkv, nullptr, nullptr, qkvh,
                                          D_MODEL, D_MODEL, 3*D_MODEL, 3*D_MODEL, 0);
    // 7-8: gate (fp16 out)
    wcvt<<<M4/256,256>>>(Wgate, Wgh, D_MODEL, D_MODEL, 0, M4);
    gemm_mma<1,1><<<gD,256,GEMM_SMEM>>>(xnh, Wgh, bgate, nullptr, nullptr, gateh,
                                        D_MODEL, D_MODEL, D_MODEL, D_MODEL, 0);
    // 9-11: mamba
    delta_bt_kernel<<<ROWS,256>>>(xnh, Wdelta, bdelta, Win, b_in, delta, bt);
    scan_kernel<<<BATCH,32>>>(delta, bt, Amat, h);
    mamba_out_kernel<<<ROWS,256>>>(h, Cmat, gateh, x, cath);
    // 12: attention
    attn_mma<<<dim3(SEQ/128, BATCH*NHEADS), 256, ATT_SMEM>>>(qkvh, ctxh);
    // 13-14: Wo + residual
    wcvt<<<M4/256,256>>>(Wo, Woh, D_MODEL, D_MODEL, 0, M4);
    gemm_mma<0,0><<<gD,256,GEMM_SMEM>>>(ctxh, Woh, bo, x, x2, nullptr,
                                        D_MODEL, D_MODEL, D_MODEL, D_MODEL, D_MODEL);
    // 15: ln2
    ln_h<<<ROWS,256>>>(x2, ln2_g, ln2_b, xn2h, nullptr, nullptr, nullptr);
    // 16-17: W1 (relu)
    wcvt<<<4*M4/256,256>>>(W1, W1h, DFF, DFF, 0, 4*M4);
    gemm_mma<2,1><<<gF,256,GEMM_SMEM>>>(xn2h, W1h, b1, nullptr, nullptr, ffn1h,
                                        D_MODEL, D_MODEL, DFF, DFF, 0);
    // 18-19: W2 + residual -> cat[:,1024:]
    wcvt<<<4*M4/256,256>>>(W2, W2h, D_MODEL, D_MODEL, 0, 4*M4);
    gemm_mma<0,1><<<gD,256,GEMM_SMEM>>>(ffn1h, W2h, b2, x2, nullptr, cath + D_MODEL,
                                        DFF, DFF, D_MODEL, 2*D_MODEL, D_MODEL);
    // 20-21: fusion (K=2048)
    wcvt<<<2*M4/256,256>>>(Wf, Wfh, D_MODEL, D_MODEL, 0, 2*M4);
    gemm_mma<0,0><<<gD,256,GEMM_SMEM>>>(cath, Wfh, bf, nullptr, y, nullptr,
                                        2*D_MODEL, 2*D_MODEL, D_MODEL, D_MODEL, 0);
    // 22: final LN -> out
    ln_f<<<ROWS,256>>>(y, lnf_g, lnf_b, (float*)d_out);
}

// round 11
// speedup vs baseline: 13.7696x; 1.2066x over previous
#include <cuda_runtime.h>
#include <cuda_fp16.h>
#include <cstdint>
#include <math.h>

#define D_MODEL 1024
#define SEQ     2048
#define BATCH   4
#define ROWS    (BATCH*SEQ)   // 8192
#define DS      16
#define DFF     4096
#define NHEADS  8
#define HDIM    128

// ---------------- scratch ----------------
__device__ __half g_xnh  [ROWS*D_MODEL];
__device__ __half g_xn1h [ROWS*D_MODEL];
__device__ __half g_qkvh [ROWS*3*D_MODEL];     // q|k|v packed, pitch 3072
__device__ __half g_ctxh [ROWS*D_MODEL];
__device__ __half g_xn2h [ROWS*D_MODEL];
__device__ __half g_ffn1h[ROWS*DFF];
__device__ __half g_cath [ROWS*2*D_MODEL];     // [mamba | tout], pitch 2048
__device__ __half g_gateh[ROWS*D_MODEL];
__device__ float  g_x2   [ROWS*D_MODEL];
__device__ float  g_y    [ROWS*D_MODEL];
__device__ float  g_delta[ROWS*DS];
__device__ float  g_bt   [ROWS*DS];
__device__ float  g_h    [ROWS*DS];
__device__ float  g_bqkv [3*D_MODEL];
// fp16 weights, ORIGINAL [K][N] row-major orientation
__device__ __half g_Wgh  [D_MODEL*D_MODEL];
__device__ __half g_Wqkvh[D_MODEL*3*D_MODEL];  // pitch 3072
__device__ __half g_Woh  [D_MODEL*D_MODEL];
__device__ __half g_W1h  [D_MODEL*DFF];
__device__ __half g_W2h  [DFF*D_MODEL];
__device__ __half g_Wfh  [2*D_MODEL*D_MODEL];

__device__ __forceinline__ float tanh_fast(float x){
    float y; asm("tanh.approx.f32 %0, %1;" : "=f"(y) : "f"(x)); return y;
}
__device__ __forceinline__ uint32_t smem_to_u32(const void* p){
    uint32_t a;
    asm("{ .reg .u64 t; cvta.to.shared.u64 t, %1; cvt.u32.u64 %0, t; }" : "=r"(a) : "l"(p));
    return a;
}
#define SWZ(o) ((o) ^ (((o) >> 3) & 0x70))

__device__ __forceinline__ void ldm_x4(uint32_t* r, uint32_t addr){
    asm volatile("ldmatrix.sync.aligned.m8n8.x4.shared.b16 {%0,%1,%2,%3}, [%4];"
        : "=r"(r[0]), "=r"(r[1]), "=r"(r[2]), "=r"(r[3]) : "r"(addr));
}
__device__ __forceinline__ void ldm_x4t(uint32_t* r, uint32_t addr){
    asm volatile("ldmatrix.sync.aligned.m8n8.x4.trans.shared.b16 {%0,%1,%2,%3}, [%4];"
        : "=r"(r[0]), "=r"(r[1]), "=r"(r[2]), "=r"(r[3]) : "r"(addr));
}
__device__ __forceinline__ void mma_fp16(float* d, const uint32_t* a, uint32_t b0, uint32_t b1){
    asm volatile("mma.sync.aligned.m16n8k16.row.col.f32.f16.f16.f32 "
        "{%0,%1,%2,%3}, {%4,%5,%6,%7}, {%8,%9}, {%0,%1,%2,%3};"
        : "+f"(d[0]), "+f"(d[1]), "+f"(d[2]), "+f"(d[3])
        : "r"(a[0]), "r"(a[1]), "r"(a[2]), "r"(a[3]), "r"(b0), "r"(b1));
}
__device__ __forceinline__ void cp16(uint32_t dst, const void* src){
    asm volatile("cp.async.cg.shared.global [%0], [%1], 16;" :: "r"(dst), "l"(src));
}
#define CP_COMMIT() asm volatile("cp.async.commit_group;" ::: "memory")
#define CP_WAIT1()  asm volatile("cp.async.wait_group 1;" ::: "memory")

// ---------------- weight convert: fp32 [K][N] -> fp16 same layout, dst pitch ldn, col offset ----------------
__global__ void __launch_bounds__(256) wcvt(const float* __restrict__ src, __half* __restrict__ dst,
                                            int N, int ldn, int coff, int total4){
    const int i = blockIdx.x*256 + threadIdx.x;
    if (i >= total4) return;
    const int e = i*4;
    const int row = e / N, col = e % N;
    const float4 v = *(const float4*)(src + e);
    __half* p = dst + (size_t)row*ldn + coff + col;
    *(__half2*)(p)   = __floats2half2_rn(v.x, v.y);
    *(__half2*)(p+2) = __floats2half2_rn(v.z, v.w);
}

__global__ void __launch_bounds__(256) biaspack(const float* bq, const float* bk, const float* bv,
                                                float* out){
    const int i = blockIdx.x*256 + threadIdx.x;
    if (i < D_MODEL){ out[i]=bq[i]; out[i+D_MODEL]=bk[i]; out[i+2*D_MODEL]=bv[i]; }
}

// ---------------- fp16 mma GEMM, cp.async 3-stage, tile 128x128 x k64, B row-major [K][N] ----------------
#define GEMM_SMEM (3*32768)
template<int ACT, int OUTH>
__global__ void __launch_bounds__(256,2) gemm_mma(
    const __half* __restrict__ A, const __half* __restrict__ B,
    const float* __restrict__ bias, const float* __restrict__ res,
    float* __restrict__ Cf, __half* __restrict__ Ch,
    int K, int lda, int ldb, int ldc, int ldr)
{
    extern __shared__ char smem[];
    const uint32_t sbase = smem_to_u32(smem);
    const int tid = threadIdx.x;
    const int lane = tid & 31, wid = tid >> 5;
    const int warp_m = wid >> 2, warp_n = wid & 3;
    const int row0 = blockIdx.y*128, col0 = blockIdx.x*128;
    const int sub = lane>>3, rr = lane&7;

    const __half* Ag = A + (size_t)row0*lda;
    const __half* Bg = B + col0;

    float acc[4][4][4];
    #pragma unroll
    for (int i=0;i<4;i++)
        #pragma unroll
        for (int j=0;j<4;j++){ acc[i][j][0]=0.f; acc[i][j][1]=0.f; acc[i][j][2]=0.f; acc[i][j][3]=0.f; }

    const int nk = K>>6;
    auto issue = [&](int kt){
        const uint32_t sA = sbase + (kt%3)*32768;
        const uint32_t sB = sA + 16384;
        const int koff = kt*64;
        #pragma unroll
        for (int i=0;i<4;i++){
            const int f = tid + i*256;
            const int ar = f>>3, aseg = f&7;
            cp16(sA + SWZ((uint32_t)(ar*128 + aseg*16)), Ag + (size_t)ar*lda + koff + aseg*8);
            const int br = f>>4, cs = f&15;
            cp16(sB + (cs>>3)*8192 + SWZ((uint32_t)(br*128 + (cs&7)*16)),
                 Bg + (size_t)(koff+br)*ldb + cs*8);
        }
    };
    issue(0); CP_COMMIT();
    if (nk>1) issue(1); CP_COMMIT();

    for (int kt=0; kt<nk; ++kt){
        CP_WAIT1();
        __syncthreads();
        if (kt+2 < nk) issue(kt+2);
        CP_COMMIT();
        const uint32_t aB = sbase + (kt%3)*32768;
        const uint32_t bB = aB + 16384;
        #pragma unroll
        for (int s=0;s<4;s++){
            uint32_t af[4][4], bf[2][4];
            #pragma unroll
            for (int mt=0;mt<4;mt++){
                const int m = warp_m*64 + mt*16 + (sub&1)*8 + rr;
                ldm_x4(af[mt], aB + SWZ((uint32_t)(m*128 + s*32 + (sub>>1)*16)));
            }
            #pragma unroll
            for (int p=0;p<2;p++){
                const int kr = s*16 + (sub&1)*8 + rr;
                const int nbase = warp_n*32 + p*16;
                const int dloc = (nbase&63) + (sub>>1)*8;
                ldm_x4t(bf[p], bB + (nbase>>6)*8192 + SWZ((uint32_t)(kr*128 + dloc*2)));
            }
            #pragma unroll
            for (int mt=0;mt<4;mt++)
                #pragma unroll
                for (int p=0;p<2;p++){
                    mma_fp16(acc[mt][p*2+0], af[mt], bf[p][0], bf[p][1]);
                    mma_fp16(acc[mt][p*2+1], af[mt], bf[p][2], bf[p][3]);
                }
        }
    }
    __syncthreads();

    // epilogue via smem staging (pitch 132 floats)
    float* Es = (float*)smem;
    const int qrow = lane>>2, qcol = (lane&3)*2;
    #pragma unroll
    for (int mt=0;mt<4;mt++)
        #pragma unroll
        for (int nt=0;nt<4;nt++)
            #pragma unroll
            for (int half=0; half<2; half++){
                const int r = warp_m*64 + mt*16 + qrow + half*8;
                const int c = warp_n*32 + nt*8 + qcol;
                *(float2*)&Es[r*132 + c] = make_float2(acc[mt][nt][half*2], acc[mt][nt][half*2+1]);
            }
    __syncthreads();
    #pragma unroll
    for (int i=0;i<16;i++){
        const int f = tid + i*256, r = f>>5, c4 = (f&31)<<2;
        float4 v = *(float4*)&Es[r*132 + c4];
        const int col = col0 + c4;
        if (bias){
            const float4 bb = *(const float4*)(bias + col);
            v.x+=bb.x; v.y+=bb.y; v.z+=bb.z; v.w+=bb.w;
        }
        if (ACT==1){
            v.x=1.f/(1.f+__expf(-v.x)); v.y=1.f/(1.f+__expf(-v.y));
            v.z=1.f/(1.f+__expf(-v.z)); v.w=1.f/(1.f+__expf(-v.w));
        } else if (ACT==2){
            v.x=fmaxf(v.x,0.f); v.y=fmaxf(v.y,0.f); v.z=fmaxf(v.z,0.f); v.w=fmaxf(v.w,0.f);
        }
        if (res){
            const float4 rv = *(const float4*)(res + (size_t)(row0+r)*ldr + col);
            v.x+=rv.x; v.y+=rv.y; v.z+=rv.z; v.w+=rv.w;
        }
        if (OUTH){
            __half* p = Ch + (size_t)(row0+r)*ldc + col;
            *(__half2*)(p)   = __floats2half2_rn(v.x, v.y);
            *(__half2*)(p+2) = __floats2half2_rn(v.z, v.w);
        } else {
            *(float4*)(Cf + (size_t)(row0+r)*ldc + col) = v;
        }
    }
}

// ---------------- fp16 mma flash attention, double-buffered KV via cp.async ----------------
#define ATT_SMEM (32768 + 32768 + 32768 + 16384)
__global__ void __launch_bounds__(256,2) attn_mma(
    const __half* __restrict__ QKV, __half* __restrict__ O)
{
    extern __shared__ char smem[];
    const uint32_t sQ = smem_to_u32(smem);
    const uint32_t sK = sQ + 32768;
    const uint32_t sV = sK + 32768;
    const uint32_t sP = sV + 32768;

    const int tid = threadIdx.x, lane = tid&31, wid = tid>>5;
    const int sub = lane>>3, rr = lane&7;
    const int qt = blockIdx.x;
    const int b  = blockIdx.y>>3, h = blockIdx.y&7;
    const int m0 = wid*16;
    const float scale = 0.08838834764831845f;

    const __half* Qb = QKV + ((size_t)(b*SEQ + qt*128))*3072 + h*HDIM;
    const __half* Kb = QKV + (size_t)b*SEQ*3072 + D_MODEL   + h*HDIM;
    const __half* Vb = QKV + (size_t)b*SEQ*3072 + 2*D_MODEL + h*HDIM;

    auto issueKV = [&](int kv){
        const uint32_t kbuf = sK + (kv&1)*16384;
        const uint32_t vbuf = sV + (kv&1)*16384;
        #pragma unroll
        for (int i=0;i<4;i++){
            const int f = tid + i*256, r = f>>4, cs = f&15;
            const uint32_t off = (uint32_t)((cs>>3)*8192 + SWZ((uint32_t)(r*128 + (cs&7)*16)));
            cp16(kbuf + off, Kb + (size_t)(kv*64+r)*3072 + cs*8);
            cp16(vbuf + off, Vb + (size_t)(kv*64+r)*3072 + cs*8);
        }
    };

    #pragma unroll
    for (int i=0;i<8;i++){
        const int f = tid + i*256, r = f>>4, cs = f&15;
        const uint4 v = *(const uint4*)(Qb + (size_t)r*3072 + cs*8);
        *(uint4*)(smem + (cs>>3)*16384 + SWZ((uint32_t)(r*128 + (cs&7)*16))) = v;
    }
    issueKV(0); CP_COMMIT();
    issueKV(1); CP_COMMIT();

    float oacc[16][4];
    #pragma unroll
    for (int i=0;i<16;i++){ oacc[i][0]=0.f; oacc[i][1]=0.f; oacc[i][2]=0.f; oacc[i][3]=0.f; }
    float m_run[2] = {-1e30f,-1e30f}, l_run[2] = {0.f,0.f};

    for (int kv=0; kv<SEQ/64; ++kv){
        CP_WAIT1();
        __syncthreads();
        const uint32_t kB = sK + (kv&1)*16384;
        const uint32_t vB = sV + (kv&1)*16384;

        float sacc[8][4];
        #pragma unroll
        for (int i=0;i<8;i++){ sacc[i][0]=0.f; sacc[i][1]=0.f; sacc[i][2]=0.f; sacc[i][3]=0.f; }
        #pragma unroll
        for (int s=0;s<8;s++){
            const int p = s>>2, sk = s&3;
            uint32_t af[4], bf[4][4];
            {
                const int m = m0 + (sub&1)*8 + rr;
                ldm_x4(af, sQ + p*16384 + SWZ((uint32_t)(m*128 + sk*32 + (sub>>1)*16)));
            }
            #pragma unroll
            for (int g=0;g<4;g++){
                const int n = g*16 + (sub&1)*8 + rr;
                ldm_x4(bf[g], kB + p*8192 + SWZ((uint32_t)(n*128 + sk*32 + (sub>>1)*16)));
            }
            #pragma unroll
            for (int g=0;g<4;g++){
                mma_fp16(sacc[g*2+0], af, bf[g][0], bf[g][2]);
                mma_fp16(sacc[g*2+1], af, bf[g][1], bf[g][3]);
            }
        }

        #pragma unroll
        for (int hh=0; hh<2; ++hh){
            float mx = -1e30f;
            #pragma unroll
            for (int nt=0;nt<8;nt++)
                mx = fmaxf(mx, fmaxf(sacc[nt][hh*2], sacc[nt][hh*2+1]));
            mx *= scale;
            mx = fmaxf(mx, __shfl_xor_sync(0xffffffffu, mx, 1));
            mx = fmaxf(mx, __shfl_xor_sync(0xffffffffu, mx, 2));
            const float mnew = fmaxf(m_run[hh], mx);
            const float alpha = __expf(m_run[hh] - mnew);
            float lsum = 0.f;
            const int prow = m0 + (lane>>2) + hh*8;
            #pragma unroll
            for (int nt=0;nt<8;nt++){
                const float p0 = __expf(scale*sacc[nt][hh*2+0] - mnew);
                const float p1 = __expf(scale*sacc[nt][hh*2+1] - mnew);
                lsum += p0 + p1;
                *(__half2*)(smem + 98304 + SWZ((uint32_t)(prow*128 + nt*16 + (lane&3)*4)))
                    = __floats2half2_rn(p0, p1);
            }
            lsum += __shfl_xor_sync(0xffffffffu, lsum, 1);
            lsum += __shfl_xor_sync(0xffffffffu, lsum, 2);
            #pragma unroll
            for (int nt=0;nt<16;nt++){ oacc[nt][hh*2] *= alpha; oacc[nt][hh*2+1] *= alpha; }
            l_run[hh] = l_run[hh]*alpha + lsum;
            m_run[hh] = mnew;
        }
        __syncwarp();

        #pragma unroll
        for (int s=0;s<4;s++){
            uint32_t af[4];
            {
                const int m = m0 + (sub&1)*8 + rr;
                ldm_x4(af, sP + SWZ((uint32_t)(m*128 + s*32 + (sub>>1)*16)));
            }
            #pragma unroll
            for (int g=0;g<8;g++){
                uint32_t vf[4];
                const int dbase = g*16;
                const int kvrow = s*16 + (sub&1)*8 + rr;
                const int dloc  = (dbase + (sub>>1)*8) & 63;
                ldm_x4t(vf, vB + (dbase>>6)*8192 + SWZ((uint32_t)(kvrow*128 + dloc*2)));
                mma_fp16(oacc[g*2+0], af, vf[0], vf[1]);
                mma_fp16(oacc[g*2+1], af, vf[2], vf[3]);
            }
        }
        __syncthreads();
        if (kv+2 < SEQ/64) issueKV(kv+2);
        CP_COMMIT();
    }

    __half* Ob = O + ((size_t)(b*SEQ + qt*128))*D_MODEL + h*HDIM;
    #pragma unroll
    for (int hh=0; hh<2; ++hh){
        const float inv = 1.f/l_run[hh];
        const int row = m0 + (lane>>2) + hh*8;
        #pragma unroll
        for (int nt=0;nt<16;nt++){
            const int col = nt*8 + (lane&3)*2;
            *(__half2*)(Ob + (size_t)row*D_MODEL + col) =
                __floats2half2_rn(oacc[nt][hh*2]*inv, oacc[nt][hh*2+1]*inv);
        }
    }
}

// ---------------- LayerNorm -> fp16 (dual) ----------------
__global__ void __launch_bounds__(256) ln_h(
    const float* __restrict__ x,
    const float* __restrict__ g0, const float* __restrict__ b0, __half* __restrict__ out0,
    const float* __restrict__ g1, const float* __restrict__ b1, __half* __restrict__ out1)
{
    __shared__ float red[64];
    const int row = blockIdx.x;
    const int tid = threadIdx.x;
    const float4 v = ((const float4*)(x + (size_t)row*D_MODEL))[tid];
    float s  = v.x+v.y+v.z+v.w;
    float sq = v.x*v.x+v.y*v.y+v.z*v.z+v.w*v.w;
    #pragma unroll
    for (int o=16;o;o>>=1){ s += __shfl_xor_sync(0xffffffffu,s,o); sq += __shfl_xor_sync(0xffffffffu,sq,o); }
    if ((tid&31)==0){ red[tid>>5]=s; red[(tid>>5)+8]=sq; }
    __syncthreads();
    if (tid<32){
        float ss=(tid<8)?red[tid]:0.f, qq=(tid<8)?red[tid+8]:0.f;
        #pragma unroll
        for (int o=4;o;o>>=1){ ss += __shfl_xor_sync(0xffffffffu,ss,o); qq += __shfl_xor_sync(0xffffffffu,qq,o); }
        if (tid==0){ red[32]=ss; red[33]=qq; }
    }
    __syncthreads();
    const float mean = red[32]*(1.f/D_MODEL);
    const float var  = red[33]*(1.f/D_MODEL) - mean*mean;
    const float inv  = rsqrtf(var + 1e-5f);
    {
        const float4 g = ((const float4*)g0)[tid];
        const float4 b = ((const float4*)b0)[tid];
        __half2 h0 = __floats2half2_rn((v.x-mean)*inv*g.x + b.x, (v.y-mean)*inv*g.y + b.y);
        __half2 h1 = __floats2half2_rn((v.z-mean)*inv*g.z + b.z, (v.w-mean)*inv*g.w + b.w);
        __half* p = out0 + (size_t)row*D_MODEL + tid*4;
        *(__half2*)p = h0; *(__half2*)(p+2) = h1;
    }
    if (out1){
        const float4 g = ((const float4*)g1)[tid];
        const float4 b = ((const float4*)b1)[tid];
        __half2 h0 = __floats2half2_rn((v.x-mean)*inv*g.x + b.x, (v.y-mean)*inv*g.y + b.y);
        __half2 h1 = __floats2half2_rn((v.z-mean)*inv*g.z + b.z, (v.w-mean)*inv*g.w + b.w);
        __half* p = out1 + (size_t)row*D_MODEL + tid*4;
        *(__half2*)p = h0; *(__half2*)(p+2) = h1;
    }
}

// ---------------- final LayerNorm -> fp32 ----------------
__global__ void __launch_bounds__(256) ln_f(
    const float* __restrict__ x,
    const float* __restrict__ g0, const float* __restrict__ b0, float* __restrict__ out0)
{
    __shared__ float red[64];
    const int row = blockIdx.x;
    const int tid = threadIdx.x;
    const float4 v = ((const float4*)(x + (size_t)row*D_MODEL))[tid];
    float s  = v.x+v.y+v.z+v.w;
    float sq = v.x*v.x+v.y*v.y+v.z*v.z+v.w*v.w;
    #pragma unroll
    for (int o=16;o;o>>=1){ s += __shfl_xor_sync(0xffffffffu,s,o); sq += __shfl_xor_sync(0xffffffffu,sq,o); }
    if ((tid&31)==0){ red[tid>>5]=s; red[(tid>>5)+8]=sq; }
    __syncthreads();
    if (tid<32){
        float ss=(tid<8)?red[tid]:0.f, qq=(tid<8)?red[tid+8]:0.f;
        #pragma unroll
        for (int o=4;o;o>>=1){ ss += __shfl_xor_sync(0xffffffffu,ss,o); qq += __shfl_xor_sync(0xffffffffu,qq,o); }
        if (tid==0){ red[32]=ss; red[33]=qq; }
    }
    __syncthreads();
    const float mean = red[32]*(1.f/D_MODEL);
    const float var  = red[33]*(1.f/D_MODEL) - mean*mean;
    const float inv  = rsqrtf(var + 1e-5f);
    const float4 g = ((const float4*)g0)[tid];
    const float4 b = ((const float4*)b0)[tid];
    float4 o0;
    o0.x = (v.x-mean)*inv*g.x + b.x;
    o0.y = (v.y-mean)*inv*g.y + b.y;
    o0.z = (v.z-mean)*inv*g.z + b.z;
    o0.w = (v.w-mean)*inv*g.w + b.w;
    ((float4*)(out0 + (size_t)row*D_MODEL))[tid] = o0;
}

// ---------------- delta / Bt (xn fp16 in) ----------------
__global__ void __launch_bounds__(256) delta_bt_kernel(
    const __half* __restrict__ xn,
    const float* __restrict__ Wd, const float* __restrict__ bd,
    const float* __restrict__ Wi, const float* __restrict__ bi,
    float* __restrict__ delta, float* __restrict__ bt)
{
    __shared__ float xs[D_MODEL];
    __shared__ float red[256];
    const int row = blockIdx.x, tid = threadIdx.x;
    #pragma unroll
    for (int i=0;i<4;i++) xs[tid + i*256] = __half2float(xn[(size_t)row*D_MODEL + tid + i*256]);
    __syncthreads();
    const int c = tid & 15;
    const int which = (tid>>4)&1;
    const int grp = tid>>5;
    const float* W = which ? Wi : Wd;
    float acc = 0.f;
    const int k0 = grp*128;
    #pragma unroll 8
    for (int k=0;k<128;k++) acc += xs[k0+k]*W[(size_t)(k0+k)*16 + c];
    red[tid]=acc; __syncthreads();
    if (tid<32){
        float sacc=0.f;
        #pragma unroll
        for (int g=0;g<8;g++) sacc += red[g*32+tid];
        if (tid<16) delta[(size_t)row*16+tid] = 1.f/(1.f+__expf(-(sacc+bd[tid])));
        else        bt   [(size_t)row*16+tid-16] = sacc + bi[tid-16];
    }
}

// ---------------- sequential mamba scan ----------------
__global__ void __launch_bounds__(32) scan_kernel(
    const float* __restrict__ delta, const float* __restrict__ bt,
    const float* __restrict__ A, float* __restrict__ h_all)
{
    __shared__ float ds[128*16], bs[128*16];
    const int b = blockIdx.x, lane = threadIdx.x;
    const int j = lane & 15;
    float Acol[16];
    #pragma unroll
    for (int i=0;i<16;i++) Acol[i] = A[i*16 + j];
    float h = 0.f;
    const float* dp = delta + (size_t)b*SEQ*16;
    const float* bp = bt    + (size_t)b*SEQ*16;
    float* hp = h_all + (size_t)b*SEQ*16;
    for (int chunk=0; chunk<SEQ; chunk+=128){
        const float4* s0 = (const float4*)(dp + (size_t)chunk*16);
        const float4* s1 = (const float4*)(bp + (size_t)chunk*16);
        for (int i=lane;i<512;i+=32){ ((float4*)ds)[i]=s0[i]; ((float4*)bs)[i]=s1[i]; }
        __syncwarp();
        #pragma unroll 4
        for (int t=0;t<128;t++){
            const float d = ds[t*16+j];
            const float bv = bs[t*16+j];
            const float v = h*d;
            float a0 = bv, a1 = 0.f;
            #pragma unroll
            for (int i=0;i<16;i+=2){
                a0 += __shfl_sync(0xffffffffu, v, i,   16)*Acol[i];
                a1 += __shfl_sync(0xffffffffu, v, i+1, 16)*Acol[i+1];
            }
            h = tanh_fast(a0+a1);
            if (lane<16) hp[(size_t)(chunk+t)*16 + j] = h;
        }
        __syncwarp();
    }
}

// ---------------- mamba_out -> cat[:,0:1024] fp16 (gate fp16 in) ----------------
__global__ void __launch_bounds__(256) mamba_out_kernel(
    const float* __restrict__ h_all, const float* __restrict__ Cm,
    const __half* __restrict__ gate, const float* __restrict__ x,
    __half* __restrict__ out)  // pitch 2048
{
    __shared__ float hs[16];
    const int row = blockIdx.x, tid = threadIdx.x;
    if (tid<16) hs[tid] = h_all[(size_t)row*16+tid];
    __syncthreads();
    const size_t base = (size_t)row*D_MODEL;
    const size_t obase = (size_t)row*2048;
    #pragma unroll
    for (int kk=0; kk<4; kk++){
        const int c = tid + kk*256;
        float acc = 0.f;
        #pragma unroll
        for (int i=0;i<16;i++) acc += hs[i]*Cm[(size_t)i*D_MODEL + c];
        out[obase+c] = __float2half_rn(acc*__half2float(gate[base+c]) + x[base+c]);
    }
}

// ---------------- launch ----------------
extern "C" void kernel_launch(void* const* d_in, const int* in_sizes, int n_in,
                              void* d_out, int out_size)
{
    const float* x      = (const float*)d_in[0];
    const float* ln_g   = (const float*)d_in[1];
    const float* ln_b   = (const float*)d_in[2];
    const float* Wdelta = (const float*)d_in[3];
    const float* bdelta = (const float*)d_in[4];
    const float* Win    = (const float*)d_in[5];
    const float* b_in   = (const float*)d_in[6];
    const float* Wgate  = (const float*)d_in[7];
    const float* bgate  = (const float*)d_in[8];
    const float* Amat   = (const float*)d_in[9];
    const float* Cmat   = (const float*)d_in[10];
    const float* ln1_g  = (const float*)d_in[11];
    const float* ln1_b  = (const float*)d_in[12];
    const float* Wq     = (const float*)d_in[13];
    const float* bq     = (const float*)d_in[14];
    const float* Wk     = (const float*)d_in[15];
    const float* bk     = (const float*)d_in[16];
    const float* Wv     = (const float*)d_in[17];
    const float* bv     = (const float*)d_in[18];
    const float* Wo     = (const float*)d_in[19];
    const float* bo     = (const float*)d_in[20];
    const float* ln2_g  = (const float*)d_in[21];
    const float* ln2_b  = (const float*)d_in[22];
    const float* W1     = (const float*)d_in[23];
    const float* b1     = (const float*)d_in[24];
    const float* W2     = (const float*)d_in[25];
    const float* b2     = (const float*)d_in[26];
    const float* Wf     = (const float*)d_in[27];
    const float* bf     = (const float*)d_in[28];
    const float* lnf_g  = (const float*)d_in[29];
    const float* lnf_b  = (const float*)d_in[30];

    __half *xnh,*xn1h,*qkvh,*ctxh,*xn2h,*ffn1h,*cath,*gateh;
    __half *Wgh,*Wqkvh,*Woh,*W1h,*W2h,*Wfh;
    float *x2,*y,*delta,*bt,*h,*bqkv;
    cudaGetSymbolAddress((void**)&xnh,  g_xnh);
    cudaGetSymbolAddress((void**)&xn1h, g_xn1h);
    cudaGetSymbolAddress((void**)&qkvh, g_qkvh);
    cudaGetSymbolAddress((void**)&ctxh, g_ctxh);
    cudaGetSymbolAddress((void**)&xn2h, g_xn2h);
    cudaGetSymbolAddress((void**)&ffn1h,g_ffn1h);
    cudaGetSymbolAddress((void**)&cath, g_cath);
    cudaGetSymbolAddress((void**)&gateh,g_gateh);
    cudaGetSymbolAddress((void**)&x2,   g_x2);
    cudaGetSymbolAddress((void**)&y,    g_y);
    cudaGetSymbolAddress((void**)&delta,g_delta);
    cudaGetSymbolAddress((void**)&bt,   g_bt);
    cudaGetSymbolAddress((void**)&h,    g_h);
    cudaGetSymbolAddress((void**)&bqkv, g_bqkv);
    cudaGetSymbolAddress((void**)&Wgh,  g_Wgh);
    cudaGetSymbolAddress((void**)&Wqkvh,g_Wqkvh);
    cudaGetSymbolAddress((void**)&Woh,  g_Woh);
    cudaGetSymbolAddress((void**)&W1h,  g_W1h);
    cudaGetSymbolAddress((void**)&W2h,  g_W2h);
    cudaGetSymbolAddress((void**)&Wfh,  g_Wfh);

    cudaFuncSetAttribute(gemm_mma<0,0>, cudaFuncAttributeMaxDynamicSharedMemorySize, GEMM_SMEM);
    cudaFuncSetAttribute(gemm_mma<0,1>, cudaFuncAttributeMaxDynamicSharedMemorySize, GEMM_SMEM);
    cudaFuncSetAttribute(gemm_mma<1,1>, cudaFuncAttributeMaxDynamicSharedMemorySize, GEMM_SMEM);
    cudaFuncSetAttribute(gemm_mma<2,1>, cudaFuncAttributeMaxDynamicSharedMemorySize, GEMM_SMEM);
    cudaFuncSetAttribute(attn_mma, cudaFuncAttributeMaxDynamicSharedMemorySize, ATT_SMEM);

    // streams/events (lazy one-time init; host objects, no device allocation)
    static cudaStream_t s1 = nullptr, s2 = nullptr;
    static cudaEvent_t eFork, eLn, eWqkv, eWo, eW1, eW2, eWf, eGate, eMamba;
    if (!s1){
        cudaStreamCreateWithFlags(&s1, cudaStreamNonBlocking);
        cudaStreamCreateWithFlags(&s2, cudaStreamNonBlocking);
        cudaEventCreateWithFlags(&eFork,  cudaEventDisableTiming);
        cudaEventCreateWithFlags(&eLn,    cudaEventDisableTiming);
        cudaEventCreateWithFlags(&eWqkv,  cudaEventDisableTiming);
        cudaEventCreateWithFlags(&eWo,    cudaEventDisableTiming);
        cudaEventCreateWithFlags(&eW1,    cudaEventDisableTiming);
        cudaEventCreateWithFlags(&eW2,    cudaEventDisableTiming);
        cudaEventCreateWithFlags(&eWf,    cudaEventDisableTiming);
        cudaEventCreateWithFlags(&eGate,  cudaEventDisableTiming);
        cudaEventCreateWithFlags(&eMamba, cudaEventDisableTiming);
    }

    const dim3 gD(D_MODEL/128, ROWS/128);
    const dim3 gQKV(3*D_MODEL/128, ROWS/128);
    const dim3 gF(DFF/128,     ROWS/128);
    const int M4 = D_MODEL*D_MODEL/4;

    // ---- fork ----
    cudaEventRecord(eFork, 0);
    cudaStreamWaitEvent(s1, eFork, 0);
    cudaStreamWaitEvent(s2, eFork, 0);

    // ---- s2: weight conversions (+ gate GEMM later) ----
    wcvt<<<M4/256,256,0,s2>>>(Wq, Wqkvh, D_MODEL, 3*D_MODEL, 0,         M4);
    wcvt<<<M4/256,256,0,s2>>>(Wk, Wqkvh, D_MODEL, 3*D_MODEL, D_MODEL,   M4);
    wcvt<<<M4/256,256,0,s2>>>(Wv, Wqkvh, D_MODEL, 3*D_MODEL, 2*D_MODEL, M4);
    biaspack<<<4,256,0,s2>>>(bq, bk, bv, bqkv);
    cudaEventRecord(eWqkv, s2);
    wcvt<<<M4/256,256,0,s2>>>(Wgate, Wgh, D_MODEL, D_MODEL, 0, M4);

    // ---- s0: dual LN ----
    ln_h<<<ROWS,256>>>(x, ln_g, ln_b, xnh, ln1_g, ln1_b, xn1h);
    cudaEventRecord(eLn, 0);

    // ---- s2: gate GEMM (needs xnh + Wgh), then remaining weight cvts ----
    cudaStreamWaitEvent(s2, eLn, 0);
    gemm_mma<1,1><<<gD,256,GEMM_SMEM,s2>>>(xnh, Wgh, bgate, nullptr, nullptr, gateh,
                                           D_MODEL, D_MODEL, D_MODEL, D_MODEL, 0);
    cudaEventRecord(eGate, s2);
    wcvt<<<M4/256,256,0,s2>>>(Wo, Woh, D_MODEL, D_MODEL, 0, M4);
    cudaEventRecord(eWo, s2);
    wcvt<<<4*M4/256,256,0,s2>>>(W1, W1h, DFF, DFF, 0, 4*M4);
    cudaEventRecord(eW1, s2);
    wcvt<<<4*M4/256,256,0,s2>>>(W2, W2h, D_MODEL, D_MODEL, 0, 4*M4);
    cudaEventRecord(eW2, s2);
    wcvt<<<2*M4/256,256,0,s2>>>(Wf, Wfh, D_MODEL, D_MODEL, 0, 2*M4);
    cudaEventRecord(eWf, s2);

    // ---- s1: mamba branch (overlaps transformer chain) ----
    cudaStreamWaitEvent(s1, eLn, 0);
    delta_bt_kernel<<<ROWS,256,0,s1>>>(xnh, Wdelta, bdelta, Win, b_in, delta, bt);
    scan_kernel<<<BATCH,32,0,s1>>>(delta, bt, Amat, h);
    cudaStreamWaitEvent(s1, eGate, 0);
    mamba_out_kernel<<<ROWS,256,0,s1>>>(h, Cmat, gateh, x, cath);
    cudaEventRecord(eMamba, s1);

    // ---- s0: transformer chain ----
    cudaStreamWaitEvent(0, eWqkv, 0);
    gemm_mma<0,1><<<gQKV,256,GEMM_SMEM>>>(xn1h, Wqkvh, bqkv, nullptr, nullptr, qkvh,
                                          D_MODEL, D_MODEL, 3*D_MODEL, 3*D_MODEL, 0);
    attn_mma<<<dim3(SEQ/128, BATCH*NHEADS), 256, ATT_SMEM>>>(qkvh, ctxh);
    cudaStreamWaitEvent(0, eWo, 0);
    gemm_mma<0,0><<<gD,256,GEMM_SMEM>>>(ctxh, Woh, bo, x, x2, nullptr,
                                        D_MODEL, D_MODEL, D_MODEL, D_MODEL, D_MODEL);
    ln_h<<<ROWS,256>>>(x2, ln2_g, ln2_b, xn2h, nullptr, nullptr, nullptr);
    cudaStreamWaitEvent(0, eW1, 0);
    gemm_mma<2,1><<<gF,256,GEMM_SMEM>>>(xn2h, W1h, b1, nullptr, nullptr, ffn1h,
                                        D_MODEL, D_MODEL, DFF, DFF, 0);
    cudaStreamWaitEvent(0, eW2, 0);
    gemm_mma<0,1><<<gD,256,GEMM_SMEM>>>(ffn1h, W2h, b2, x2, nullptr, cath + D_MODEL,
                                        DFF, DFF, D_MODEL, 2*D_MODEL, D_MODEL);

    // ---- join: fusion GEMM needs both branches ----
    cudaStreamWaitEvent(0, eMamba, 0);
    cudaStreamWaitEvent(0, eWf, 0);
    gemm_mma<0,0><<<gD,256,GEMM_SMEM>>>(cath, Wfh, bf, nullptr, y, nullptr,
                                        2*D_MODEL, 2*D_MODEL, D_MODEL, D_MODEL, 0);
    ln_f<<<ROWS,256>>>(y, lnf_g, lnf_b, (float*)d_out);
}

// round 12
// speedup vs baseline: 14.4067x; 1.0463x over previous
#include <cuda_runtime.h>
#include <cuda_fp16.h>
#include <cstdint>
#include <math.h>

#define D_MODEL 1024
#define SEQ     2048
#define BATCH   4
#define ROWS    (BATCH*SEQ)   // 8192
#define HROWS   (ROWS/2)      // 4096 per pipeline half
#define DS      16
#define DFF     4096
#define NHEADS  8
#define HDIM    128

// ---------------- scratch ----------------
__device__ __half g_xnh  [ROWS*D_MODEL];
__device__ __half g_xn1h [ROWS*D_MODEL];
__device__ __half g_qkvh [ROWS*3*D_MODEL];     // q|k|v packed, pitch 3072
__device__ __half g_ctxh [ROWS*D_MODEL];
__device__ __half g_xn2h [ROWS*D_MODEL];
__device__ __half g_ffn1h[ROWS*DFF];
__device__ __half g_mambah[ROWS*D_MODEL];
__device__ __half g_touth [ROWS*D_MODEL];
__device__ __half g_gateh[ROWS*D_MODEL];
__device__ float  g_x2   [ROWS*D_MODEL];
__device__ float  g_y    [ROWS*D_MODEL];
__device__ float  g_delta[ROWS*DS];
__device__ float  g_bt   [ROWS*DS];
__device__ float  g_h    [ROWS*DS];
__device__ float  g_bqkv [3*D_MODEL];
// fp16 weights, ORIGINAL [K][N] row-major orientation
__device__ __half g_Wgh  [D_MODEL*D_MODEL];
__device__ __half g_Wqkvh[D_MODEL*3*D_MODEL];  // pitch 3072
__device__ __half g_Woh  [D_MODEL*D_MODEL];
__device__ __half g_W1h  [D_MODEL*DFF];
__device__ __half g_W2h  [DFF*D_MODEL];
__device__ __half g_Wfh  [2*D_MODEL*D_MODEL];

__device__ __forceinline__ float tanh_fast(float x){
    float y; asm("tanh.approx.f32 %0, %1;" : "=f"(y) : "f"(x)); return y;
}
__device__ __forceinline__ uint32_t smem_to_u32(const void* p){
    uint32_t a;
    asm("{ .reg .u64 t; cvta.to.shared.u64 t, %1; cvt.u32.u64 %0, t; }" : "=r"(a) : "l"(p));
    return a;
}
#define SWZ(o) ((o) ^ (((o) >> 3) & 0x70))

__device__ __forceinline__ void ldm_x4(uint32_t* r, uint32_t addr){
    asm volatile("ldmatrix.sync.aligned.m8n8.x4.shared.b16 {%0,%1,%2,%3}, [%4];"
        : "=r"(r[0]), "=r"(r[1]), "=r"(r[2]), "=r"(r[3]) : "r"(addr));
}
__device__ __forceinline__ void ldm_x4t(uint32_t* r, uint32_t addr){
    asm volatile("ldmatrix.sync.aligned.m8n8.x4.trans.shared.b16 {%0,%1,%2,%3}, [%4];"
        : "=r"(r[0]), "=r"(r[1]), "=r"(r[2]), "=r"(r[3]) : "r"(addr));
}
__device__ __forceinline__ void mma_fp16(float* d, const uint32_t* a, uint32_t b0, uint32_t b1){
    asm volatile("mma.sync.aligned.m16n8k16.row.col.f32.f16.f16.f32 "
        "{%0,%1,%2,%3}, {%4,%5,%6,%7}, {%8,%9}, {%0,%1,%2,%3};"
        : "+f"(d[0]), "+f"(d[1]), "+f"(d[2]), "+f"(d[3])
        : "r"(a[0]), "r"(a[1]), "r"(a[2]), "r"(a[3]), "r"(b0), "r"(b1));
}
__device__ __forceinline__ void cp16(uint32_t dst, const void* src){
    asm volatile("cp.async.cg.shared.global [%0], [%1], 16;" :: "r"(dst), "l"(src));
}
#define CP_COMMIT() asm volatile("cp.async.commit_group;" ::: "memory")
#define CP_WAIT1()  asm volatile("cp.async.wait_group 1;" ::: "memory")

// ---------------- weight convert ----------------
__global__ void __launch_bounds__(256) wcvt(const float* __restrict__ src, __half* __restrict__ dst,
                                            int N, int ldn, int coff, int total4){
    const int i = blockIdx.x*256 + threadIdx.x;
    if (i >= total4) return;
    const int e = i*4;
    const int row = e / N, col = e % N;
    const float4 v = *(const float4*)(src + e);
    __half* p = dst + (size_t)row*ldn + coff + col;
    *(__half2*)(p)   = __floats2half2_rn(v.x, v.y);
    *(__half2*)(p+2) = __floats2half2_rn(v.z, v.w);
}

__global__ void __launch_bounds__(256) biaspack(const float* bq, const float* bk, const float* bv,
                                                float* out){
    const int i = blockIdx.x*256 + threadIdx.x;
    if (i < D_MODEL){ out[i]=bq[i]; out[i+D_MODEL]=bk[i]; out[i+2*D_MODEL]=bv[i]; }
}

// ---------------- fp16 mma GEMM, cp.async 3-stage, tile 128x128 x k64, B row-major [K][N] ----------------
#define GEMM_SMEM (3*32768)
template<int ACT, int OUTH>
__global__ void __launch_bounds__(256,2) gemm_mma(
    const __half* __restrict__ A, const __half* __restrict__ B,
    const float* __restrict__ bias, const float* __restrict__ res,
    float* __restrict__ Cf, __half* __restrict__ Ch,
    int K, int lda, int ldb, int ldc, int ldr)
{
    extern __shared__ char smem[];
    const uint32_t sbase = smem_to_u32(smem);
    const int tid = threadIdx.x;
    const int lane = tid & 31, wid = tid >> 5;
    const int warp_m = wid >> 2, warp_n = wid & 3;
    const int row0 = blockIdx.y*128, col0 = blockIdx.x*128;
    const int sub = lane>>3, rr = lane&7;

    const __half* Ag = A + (size_t)row0*lda;
    const __half* Bg = B + col0;

    float acc[4][4][4];
    #pragma unroll
    for (int i=0;i<4;i++)
        #pragma unroll
        for (int j=0;j<4;j++){ acc[i][j][0]=0.f; acc[i][j][1]=0.f; acc[i][j][2]=0.f; acc[i][j][3]=0.f; }

    const int nk = K>>6;
    auto issue = [&](int kt){
        const uint32_t sA = sbase + (kt%3)*32768;
        const uint32_t sB = sA + 16384;
        const int koff = kt*64;
        #pragma unroll
        for (int i=0;i<4;i++){
            const int f = tid + i*256;
            const int ar = f>>3, aseg = f&7;
            cp16(sA + SWZ((uint32_t)(ar*128 + aseg*16)), Ag + (size_t)ar*lda + koff + aseg*8);
            const int br = f>>4, cs = f&15;
            cp16(sB + (cs>>3)*8192 + SWZ((uint32_t)(br*128 + (cs&7)*16)),
                 Bg + (size_t)(koff+br)*ldb + cs*8);
        }
    };
    issue(0); CP_COMMIT();
    if (nk>1) issue(1); CP_COMMIT();

    for (int kt=0; kt<nk; ++kt){
        CP_WAIT1();
        __syncthreads();
        if (kt+2 < nk) issue(kt+2);
        CP_COMMIT();
        const uint32_t aB = sbase + (kt%3)*32768;
        const uint32_t bB = aB + 16384;
        #pragma unroll
        for (int s=0;s<4;s++){
            uint32_t af[4][4], bf[2][4];
            #pragma unroll
            for (int mt=0;mt<4;mt++){
                const int m = warp_m*64 + mt*16 + (sub&1)*8 + rr;
                ldm_x4(af[mt], aB + SWZ((uint32_t)(m*128 + s*32 + (sub>>1)*16)));
            }
            #pragma unroll
            for (int p=0;p<2;p++){
                const int kr = s*16 + (sub&1)*8 + rr;
                const int nbase = warp_n*32 + p*16;
                const int dloc = (nbase&63) + (sub>>1)*8;
                ldm_x4t(bf[p], bB + (nbase>>6)*8192 + SWZ((uint32_t)(kr*128 + dloc*2)));
            }
            #pragma unroll
            for (int mt=0;mt<4;mt++)
                #pragma unroll
                for (int p=0;p<2;p++){
                    mma_fp16(acc[mt][p*2+0], af[mt], bf[p][0], bf[p][1]);
                    mma_fp16(acc[mt][p*2+1], af[mt], bf[p][2], bf[p][3]);
                }
        }
    }
    __syncthreads();

    // epilogue via smem staging (pitch 132 floats)
    float* Es = (float*)smem;
    const int qrow = lane>>2, qcol = (lane&3)*2;
    #pragma unroll
    for (int mt=0;mt<4;mt++)
        #pragma unroll
        for (int nt=0;nt<4;nt++)
            #pragma unroll
            for (int half=0; half<2; half++){
                const int r = warp_m*64 + mt*16 + qrow + half*8;
                const int c = warp_n*32 + nt*8 + qcol;
                *(float2*)&Es[r*132 + c] = make_float2(acc[mt][nt][half*2], acc[mt][nt][half*2+1]);
            }
    __syncthreads();
    #pragma unroll
    for (int i=0;i<16;i++){
        const int f = tid + i*256, r = f>>5, c4 = (f&31)<<2;
        float4 v = *(float4*)&Es[r*132 + c4];
        const int col = col0 + c4;
        if (bias){
            const float4 bb = *(const float4*)(bias + col);
            v.x+=bb.x; v.y+=bb.y; v.z+=bb.z; v.w+=bb.w;
        }
        if (ACT==1){
            v.x=1.f/(1.f+__expf(-v.x)); v.y=1.f/(1.f+__expf(-v.y));
            v.z=1.f/(1.f+__expf(-v.z)); v.w=1.f/(1.f+__expf(-v.w));
        } else if (ACT==2){
            v.x=fmaxf(v.x,0.f); v.y=fmaxf(v.y,0.f); v.z=fmaxf(v.z,0.f); v.w=fmaxf(v.w,0.f);
        }
        if (res){
            const float4 rv = *(const float4*)(res + (size_t)(row0+r)*ldr + col);
            v.x+=rv.x; v.y+=rv.y; v.z+=rv.z; v.w+=rv.w;
        }
        if (OUTH){
            __half* p = Ch + (size_t)(row0+r)*ldc + col;
            *(__half2*)(p)   = __floats2half2_rn(v.x, v.y);
            *(__half2*)(p+2) = __floats2half2_rn(v.z, v.w);
        } else {
            *(float4*)(Cf + (size_t)(row0+r)*ldc + col) = v;
        }
    }
}

// ---------------- fp16 mma flash attention, double-buffered KV via cp.async ----------------
#define ATT_SMEM (32768 + 32768 + 32768 + 16384)
__global__ void __launch_bounds__(256,2) attn_mma(
    const __half* __restrict__ QKV, __half* __restrict__ O)
{
    extern __shared__ char smem[];
    const uint32_t sQ = smem_to_u32(smem);
    const uint32_t sK = sQ + 32768;
    const uint32_t sV = sK + 32768;
    const uint32_t sP = sV + 32768;

    const int tid = threadIdx.x, lane = tid&31, wid = tid>>5;
    const int sub = lane>>3, rr = lane&7;
    const int qt = blockIdx.x;
    const int b  = blockIdx.y>>3, h = blockIdx.y&7;
    const int m0 = wid*16;
    const float scale = 0.08838834764831845f;

    const __half* Qb = QKV + ((size_t)(b*SEQ + qt*128))*3072 + h*HDIM;
    const __half* Kb = QKV + (size_t)b*SEQ*3072 + D_MODEL   + h*HDIM;
    const __half* Vb = QKV + (size_t)b*SEQ*3072 + 2*D_MODEL + h*HDIM;

    auto issueKV = [&](int kv){
        const uint32_t kbuf = sK + (kv&1)*16384;
        const uint32_t vbuf = sV + (kv&1)*16384;
        #pragma unroll
        for (int i=0;i<4;i++){
            const int f = tid + i*256, r = f>>4, cs = f&15;
            const uint32_t off = (uint32_t)((cs>>3)*8192 + SWZ((uint32_t)(r*128 + (cs&7)*16)));
            cp16(kbuf + off, Kb + (size_t)(kv*64+r)*3072 + cs*8);
            cp16(vbuf + off, Vb + (size_t)(kv*64+r)*3072 + cs*8);
        }
    };

    #pragma unroll
    for (int i=0;i<8;i++){
        const int f = tid + i*256, r = f>>4, cs = f&15;
        const uint4 v = *(const uint4*)(Qb + (size_t)r*3072 + cs*8);
        *(uint4*)(smem + (cs>>3)*16384 + SWZ((uint32_t)(r*128 + (cs&7)*16))) = v;
    }
    issueKV(0); CP_COMMIT();
    issueKV(1); CP_COMMIT();

    float oacc[16][4];
    #pragma unroll
    for (int i=0;i<16;i++){ oacc[i][0]=0.f; oacc[i][1]=0.f; oacc[i][2]=0.f; oacc[i][3]=0.f; }
    float m_run[2] = {-1e30f,-1e30f}, l_run[2] = {0.f,0.f};

    for (int kv=0; kv<SEQ/64; ++kv){
        CP_WAIT1();
        __syncthreads();
        const uint32_t kB = sK + (kv&1)*16384;
        const uint32_t vB = sV + (kv&1)*16384;

        float sacc[8][4];
        #pragma unroll
        for (int i=0;i<8;i++){ sacc[i][0]=0.f; sacc[i][1]=0.f; sacc[i][2]=0.f; sacc[i][3]=0.f; }
        #pragma unroll
        for (int s=0;s<8;s++){
            const int p = s>>2, sk = s&3;
            uint32_t af[4], bf[4][4];
            {
                const int m = m0 + (sub&1)*8 + rr;
                ldm_x4(af, sQ + p*16384 + SWZ((uint32_t)(m*128 + sk*32 + (sub>>1)*16)));
            }
            #pragma unroll
            for (int g=0;g<4;g++){
                const int n = g*16 + (sub&1)*8 + rr;
                ldm_x4(bf[g], kB + p*8192 + SWZ((uint32_t)(n*128 + sk*32 + (sub>>1)*16)));
            }
            #pragma unroll
            for (int g=0;g<4;g++){
                mma_fp16(sacc[g*2+0], af, bf[g][0], bf[g][2]);
                mma_fp16(sacc[g*2+1], af, bf[g][1], bf[g][3]);
            }
        }

        #pragma unroll
        for (int hh=0; hh<2; ++hh){
            float mx = -1e30f;
            #pragma unroll
            for (int nt=0;nt<8;nt++)
                mx = fmaxf(mx, fmaxf(sacc[nt][hh*2], sacc[nt][hh*2+1]));
            mx *= scale;
            mx = fmaxf(mx, __shfl_xor_sync(0xffffffffu, mx, 1));
            mx = fmaxf(mx, __shfl_xor_sync(0xffffffffu, mx, 2));
            const float mnew = fmaxf(m_run[hh], mx);
            const float alpha = __expf(m_run[hh] - mnew);
            float lsum = 0.f;
            const int prow = m0 + (lane>>2) + hh*8;
            #pragma unroll
            for (int nt=0;nt<8;nt++){
                const float p0 = __expf(scale*sacc[nt][hh*2+0] - mnew);
                const float p1 = __expf(scale*sacc[nt][hh*2+1] - mnew);
                lsum += p0 + p1;
                *(__half2*)(smem + 98304 + SWZ((uint32_t)(prow*128 + nt*16 + (lane&3)*4)))
                    = __floats2half2_rn(p0, p1);
            }
            lsum += __shfl_xor_sync(0xffffffffu, lsum, 1);
            lsum += __shfl_xor_sync(0xffffffffu, lsum, 2);
            #pragma unroll
            for (int nt=0;nt<16;nt++){ oacc[nt][hh*2] *= alpha; oacc[nt][hh*2+1] *= alpha; }
            l_run[hh] = l_run[hh]*alpha + lsum;
            m_run[hh] = mnew;
        }
        __syncwarp();

        #pragma unroll
        for (int s=0;s<4;s++){
            uint32_t af[4];
            {
                const int m = m0 + (sub&1)*8 + rr;
                ldm_x4(af, sP + SWZ((uint32_t)(m*128 + s*32 + (sub>>1)*16)));
            }
            #pragma unroll
            for (int g=0;g<8;g++){
                uint32_t vf[4];
                const int dbase = g*16;
                const int kvrow = s*16 + (sub&1)*8 + rr;
                const int dloc  = (dbase + (sub>>1)*8) & 63;
                ldm_x4t(vf, vB + (dbase>>6)*8192 + SWZ((uint32_t)(kvrow*128 + dloc*2)));
                mma_fp16(oacc[g*2+0], af, vf[0], vf[1]);
                mma_fp16(oacc[g*2+1], af, vf[2], vf[3]);
            }
        }
        __syncthreads();
        if (kv+2 < SEQ/64) issueKV(kv+2);
        CP_COMMIT();
    }

    __half* Ob = O + ((size_t)(b*SEQ + qt*128))*D_MODEL + h*HDIM;
    #pragma unroll
    for (int hh=0; hh<2; ++hh){
        const float inv = 1.f/l_run[hh];
        const int row = m0 + (lane>>2) + hh*8;
        #pragma unroll
        for (int nt=0;nt<16;nt++){
            const int col = nt*8 + (lane&3)*2;
            *(__half2*)(Ob + (size_t)row*D_MODEL + col) =
                __floats2half2_rn(oacc[nt][hh*2]*inv, oacc[nt][hh*2+1]*inv);
        }
    }
}

// ---------------- LayerNorm -> fp16 (dual) ----------------
__global__ void __launch_bounds__(256) ln_h(
    const float* __restrict__ x,
    const float* __restrict__ g0, const float* __restrict__ b0, __half* __restrict__ out0,
    const float* __restrict__ g1, const float* __restrict__ b1, __half* __restrict__ out1)
{
    __shared__ float red[64];
    const int row = blockIdx.x;
    const int tid = threadIdx.x;
    const float4 v = ((const float4*)(x + (size_t)row*D_MODEL))[tid];
    float s  = v.x+v.y+v.z+v.w;
    float sq = v.x*v.x+v.y*v.y+v.z*v.z+v.w*v.w;
    #pragma unroll
    for (int o=16;o;o>>=1){ s += __shfl_xor_sync(0xffffffffu,s,o); sq += __shfl_xor_sync(0xffffffffu,sq,o); }
    if ((tid&31)==0){ red[tid>>5]=s; red[(tid>>5)+8]=sq; }
    __syncthreads();
    if (tid<32){
        float ss=(tid<8)?red[tid]:0.f, qq=(tid<8)?red[tid+8]:0.f;
        #pragma unroll
        for (int o=4;o;o>>=1){ ss += __shfl_xor_sync(0xffffffffu,ss,o); qq += __shfl_xor_sync(0xffffffffu,qq,o); }
        if (tid==0){ red[32]=ss; red[33]=qq; }
    }
    __syncthreads();
    const float mean = red[32]*(1.f/D_MODEL);
    const float var  = red[33]*(1.f/D_MODEL) - mean*mean;
    const float inv  = rsqrtf(var + 1e-5f);
    {
        const float4 g = ((const float4*)g0)[tid];
        const float4 b = ((const float4*)b0)[tid];
        __half2 h0 = __floats2half2_rn((v.x-mean)*inv*g.x + b.x, (v.y-mean)*inv*g.y + b.y);
        __half2 h1 = __floats2half2_rn((v.z-mean)*inv*g.z + b.z, (v.w-mean)*inv*g.w + b.w);
        __half* p = out0 + (size_t)row*D_MODEL + tid*4;
        *(__half2*)p = h0; *(__half2*)(p+2) = h1;
    }
    if (out1){
        const float4 g = ((const float4*)g1)[tid];
        const float4 b = ((const float4*)b1)[tid];
        __half2 h0 = __floats2half2_rn((v.x-mean)*inv*g.x + b.x, (v.y-mean)*inv*g.y + b.y);
        __half2 h1 = __floats2half2_rn((v.z-mean)*inv*g.z + b.z, (v.w-mean)*inv*g.w + b.w);
        __half* p = out1 + (size_t)row*D_MODEL + tid*4;
        *(__half2*)p = h0; *(__half2*)(p+2) = h1;
    }
}

// ---------------- final LayerNorm -> fp32 ----------------
__global__ void __launch_bounds__(256) ln_f(
    const float* __restrict__ x,
    const float* __restrict__ g0, const float* __restrict__ b0, float* __restrict__ out0)
{
    __shared__ float red[64];
    const int row = blockIdx.x;
    const int tid = threadIdx.x;
    const float4 v = ((const float4*)(x + (size_t)row*D_MODEL))[tid];
    float s  = v.x+v.y+v.z+v.w;
    float sq = v.x*v.x+v.y*v.y+v.z*v.z+v.w*v.w;
    #pragma unroll
    for (int o=16;o;o>>=1){ s += __shfl_xor_sync(0xffffffffu,s,o); sq += __shfl_xor_sync(0xffffffffu,sq,o); }
    if ((tid&31)==0){ red[tid>>5]=s; red[(tid>>5)+8]=sq; }
    __syncthreads();
    if (tid<32){
        float ss=(tid<8)?red[tid]:0.f, qq=(tid<8)?red[tid+8]:0.f;
        #pragma unroll
        for (int o=4;o;o>>=1){ ss += __shfl_xor_sync(0xffffffffu,ss,o); qq += __shfl_xor_sync(0xffffffffu,qq,o); }
        if (tid==0){ red[32]=ss; red[33]=qq; }
    }
    __syncthreads();
    const float mean = red[32]*(1.f/D_MODEL);
    const float var  = red[33]*(1.f/D_MODEL) - mean*mean;
    const float inv  = rsqrtf(var + 1e-5f);
    const float4 g = ((const float4*)g0)[tid];
    const float4 b = ((const float4*)b0)[tid];
    float4 o0;
    o0.x = (v.x-mean)*inv*g.x + b.x;
    o0.y = (v.y-mean)*inv*g.y + b.y;
    o0.z = (v.z-mean)*inv*g.z + b.z;
    o0.w = (v.w-mean)*inv*g.w + b.w;
    ((float4*)(out0 + (size_t)row*D_MODEL))[tid] = o0;
}

// ---------------- delta / Bt (xn fp16 in) ----------------
__global__ void __launch_bounds__(256) delta_bt_kernel(
    const __half* __restrict__ xn,
    const float* __restrict__ Wd, const float* __restrict__ bd,
    const float* __restrict__ Wi, const float* __restrict__ bi,
    float* __restrict__ delta, float* __restrict__ bt)
{
    __shared__ float xs[D_MODEL];
    __shared__ float red[256];
    const int row = blockIdx.x, tid = threadIdx.x;
    #pragma unroll
    for (int i=0;i<4;i++) xs[tid + i*256] = __half2float(xn[(size_t)row*D_MODEL + tid + i*256]);
    __syncthreads();
    const int c = tid & 15;
    const int which = (tid>>4)&1;
    const int grp = tid>>5;
    const float* W = which ? Wi : Wd;
    float acc = 0.f;
    const int k0 = grp*128;
    #pragma unroll 8
    for (int k=0;k<128;k++) acc += xs[k0+k]*W[(size_t)(k0+k)*16 + c];
    red[tid]=acc; __syncthreads();
    if (tid<32){
        float sacc=0.f;
        #pragma unroll
        for (int g=0;g<8;g++) sacc += red[g*32+tid];
        if (tid<16) delta[(size_t)row*16+tid] = 1.f/(1.f+__expf(-(sacc+bd[tid])));
        else        bt   [(size_t)row*16+tid-16] = sacc + bi[tid-16];
    }
}

// ---------------- sequential mamba scan ----------------
__global__ void __launch_bounds__(32) scan_kernel(
    const float* __restrict__ delta, const float* __restrict__ bt,
    const float* __restrict__ A, float* __restrict__ h_all)
{
    __shared__ float ds[128*16], bs[128*16];
    const int b = blockIdx.x, lane = threadIdx.x;
    const int j = lane & 15;
    float Acol[16];
    #pragma unroll
    for (int i=0;i<16;i++) Acol[i] = A[i*16 + j];
    float h = 0.f;
    const float* dp = delta + (size_t)b*SEQ*16;
    const float* bp = bt    + (size_t)b*SEQ*16;
    float* hp = h_all + (size_t)b*SEQ*16;
    for (int chunk=0; chunk<SEQ; chunk+=128){
        const float4* s0 = (const float4*)(dp + (size_t)chunk*16);
        const float4* s1 = (const float4*)(bp + (size_t)chunk*16);
        for (int i=lane;i<512;i+=32){ ((float4*)ds)[i]=s0[i]; ((float4*)bs)[i]=s1[i]; }
        __syncwarp();
        #pragma unroll 4
        for (int t=0;t<128;t++){
            const float d = ds[t*16+j];
            const float bv = bs[t*16+j];
            const float v = h*d;
            float a0 = bv, a1 = 0.f;
            #pragma unroll
            for (int i=0;i<16;i+=2){
                a0 += __shfl_sync(0xffffffffu, v, i,   16)*Acol[i];
                a1 += __shfl_sync(0xffffffffu, v, i+1, 16)*Acol[i+1];
            }
            h = tanh_fast(a0+a1);
            if (lane<16) hp[(size_t)(chunk+t)*16 + j] = h;
        }
        __syncwarp();
    }
}

// ---------------- mamba_out -> mambah fp16 (pitch 1024) ----------------
__global__ void __launch_bounds__(256) mamba_out_kernel(
    const float* __restrict__ h_all, const float* __restrict__ Cm,
    const __half* __restrict__ gate, const float* __restrict__ x,
    __half* __restrict__ out)
{
    __shared__ float hs[16];
    const int row = blockIdx.x, tid = threadIdx.x;
    if (tid<16) hs[tid] = h_all[(size_t)row*16+tid];
    __syncthreads();
    const size_t base = (size_t)row*D_MODEL;
    #pragma unroll
    for (int kk=0; kk<4; kk++){
        const int c = tid + kk*256;
        float acc = 0.f;
        #pragma unroll
        for (int i=0;i<16;i++) acc += hs[i]*Cm[(size_t)i*D_MODEL + c];
        out[base+c] = __float2half_rn(acc*__half2float(gate[base+c]) + x[base+c]);
    }
}

// ---------------- launch ----------------
extern "C" void kernel_launch(void* const* d_in, const int* in_sizes, int n_in,
                              void* d_out, int out_size)
{
    const float* x      = (const float*)d_in[0];
    const float* ln_g   = (const float*)d_in[1];
    const float* ln_b   = (const float*)d_in[2];
    const float* Wdelta = (const float*)d_in[3];
    const float* bdelta = (const float*)d_in[4];
    const float* Win    = (const float*)d_in[5];
    const float* b_in   = (const float*)d_in[6];
    const float* Wgate  = (const float*)d_in[7];
    const float* bgate  = (const float*)d_in[8];
    const float* Amat   = (const float*)d_in[9];
    const float* Cmat   = (const float*)d_in[10];
    const float* ln1_g  = (const float*)d_in[11];
    const float* ln1_b  = (const float*)d_in[12];
    const float* Wq     = (const float*)d_in[13];
    const float* bq     = (const float*)d_in[14];
    const float* Wk     = (const float*)d_in[15];
    const float* bk     = (const float*)d_in[16];
    const float* Wv     = (const float*)d_in[17];
    const float* bv     = (const float*)d_in[18];
    const float* Wo     = (const float*)d_in[19];
    const float* bo     = (const float*)d_in[20];
    const float* ln2_g  = (const float*)d_in[21];
    const float* ln2_b  = (const float*)d_in[22];
    const float* W1     = (const float*)d_in[23];
    const float* b1     = (const float*)d_in[24];
    const float* W2     = (const float*)d_in[25];
    const float* b2     = (const float*)d_in[26];
    const float* Wf     = (const float*)d_in[27];
    const float* bf     = (const float*)d_in[28];
    const float* lnf_g  = (const float*)d_in[29];
    const float* lnf_b  = (const float*)d_in[30];

    __half *xnh,*xn1h,*qkvh,*ctxh,*xn2h,*ffn1h,*mambah,*touth,*gateh;
    __half *Wgh,*Wqkvh,*Woh,*W1h,*W2h,*Wfh;
    float *x2,*y,*delta,*bt,*h,*bqkv;
    cudaGetSymbolAddress((void**)&xnh,  g_xnh);
    cudaGetSymbolAddress((void**)&xn1h, g_xn1h);
    cudaGetSymbolAddress((void**)&qkvh, g_qkvh);
    cudaGetSymbolAddress((void**)&ctxh, g_ctxh);
    cudaGetSymbolAddress((void**)&xn2h, g_xn2h);
    cudaGetSymbolAddress((void**)&ffn1h,g_ffn1h);
    cudaGetSymbolAddress((void**)&mambah,g_mambah);
    cudaGetSymbolAddress((void**)&touth,g_touth);
    cudaGetSymbolAddress((void**)&gateh,g_gateh);
    cudaGetSymbolAddress((void**)&x2,   g_x2);
    cudaGetSymbolAddress((void**)&y,    g_y);
    cudaGetSymbolAddress((void**)&delta,g_delta);
    cudaGetSymbolAddress((void**)&bt,   g_bt);
    cudaGetSymbolAddress((void**)&h,    g_h);
    cudaGetSymbolAddress((void**)&bqkv, g_bqkv);
    cudaGetSymbolAddress((void**)&Wgh,  g_Wgh);
    cudaGetSymbolAddress((void**)&Wqkvh,g_Wqkvh);
    cudaGetSymbolAddress((void**)&Woh,  g_Woh);
    cudaGetSymbolAddress((void**)&W1h,  g_W1h);
    cudaGetSymbolAddress((void**)&W2h,  g_W2h);
    cudaGetSymbolAddress((void**)&Wfh,  g_Wfh);

    cudaFuncSetAttribute(gemm_mma<0,0>, cudaFuncAttributeMaxDynamicSharedMemorySize, GEMM_SMEM);
    cudaFuncSetAttribute(gemm_mma<0,1>, cudaFuncAttributeMaxDynamicSharedMemorySize, GEMM_SMEM);
    cudaFuncSetAttribute(gemm_mma<1,1>, cudaFuncAttributeMaxDynamicSharedMemorySize, GEMM_SMEM);
    cudaFuncSetAttribute(gemm_mma<2,1>, cudaFuncAttributeMaxDynamicSharedMemorySize, GEMM_SMEM);
    cudaFuncSetAttribute(attn_mma, cudaFuncAttributeMaxDynamicSharedMemorySize, ATT_SMEM);

    static cudaStream_t s1 = nullptr, s2 = nullptr, s3 = nullptr;
    static cudaEvent_t eFork, eLn, eWqkv, eWo, eW1, eW2, eWf, eGate, eMamba, eH1;
    if (!s1){
        cudaStreamCreateWithFlags(&s1, cudaStreamNonBlocking);
        cudaStreamCreateWithFlags(&s2, cudaStreamNonBlocking);
        cudaStreamCreateWithFlags(&s3, cudaStreamNonBlocking);
        cudaEventCreateWithFlags(&eFork,  cudaEventDisableTiming);
        cudaEventCreateWithFlags(&eLn,    cudaEventDisableTiming);
        cudaEventCreateWithFlags(&eWqkv,  cudaEventDisableTiming);
        cudaEventCreateWithFlags(&eWo,    cudaEventDisableTiming);
        cudaEventCreateWithFlags(&eW1,    cudaEventDisableTiming);
        cudaEventCreateWithFlags(&eW2,    cudaEventDisableTiming);
        cudaEventCreateWithFlags(&eWf,    cudaEventDisableTiming);
        cudaEventCreateWithFlags(&eGate,  cudaEventDisableTiming);
        cudaEventCreateWithFlags(&eMamba, cudaEventDisableTiming);
        cudaEventCreateWithFlags(&eH1,    cudaEventDisableTiming);
    }

    const dim3 gDh(D_MODEL/128, HROWS/128);       // (8, 32)
    const dim3 gDfull(D_MODEL/128, ROWS/128);     // (8, 64)
    const dim3 gQKVh(3*D_MODEL/128, HROWS/128);   // (24, 32)
    const dim3 gFh(DFF/128, HROWS/128);           // (32, 32)
    const int M4 = D_MODEL*D_MODEL/4;

    // ---- fork ----
    cudaEventRecord(eFork, 0);
    cudaStreamWaitEvent(s1, eFork, 0);
    cudaStreamWaitEvent(s2, eFork, 0);
    cudaStreamWaitEvent(s3, eFork, 0);

    // ---- s2: weight conversions + gate GEMM ----
    wcvt<<<M4/256,256,0,s2>>>(Wq, Wqkvh, D_MODEL, 3*D_MODEL, 0,         M4);
    wcvt<<<M4/256,256,0,s2>>>(Wk, Wqkvh, D_MODEL, 3*D_MODEL, D_MODEL,   M4);
    wcvt<<<M4/256,256,0,s2>>>(Wv, Wqkvh, D_MODEL, 3*D_MODEL, 2*D_MODEL, M4);
    biaspack<<<4,256,0,s2>>>(bq, bk, bv, bqkv);
    cudaEventRecord(eWqkv, s2);
    wcvt<<<M4/256,256,0,s2>>>(Wgate, Wgh, D_MODEL, D_MODEL, 0, M4);

    // ---- s0: dual LN (full rows) ----
    ln_h<<<ROWS,256>>>(x, ln_g, ln_b, xnh, ln1_g, ln1_b, xn1h);
    cudaEventRecord(eLn, 0);

    // ---- s2 cont: gate GEMM + remaining weight cvts ----
    cudaStreamWaitEvent(s2, eLn, 0);
    gemm_mma<1,1><<<gDfull,256,GEMM_SMEM,s2>>>(xnh, Wgh, bgate, nullptr, nullptr, gateh,
                                               D_MODEL, D_MODEL, D_MODEL, D_MODEL, 0);
    cudaEventRecord(eGate, s2);
    wcvt<<<M4/256,256,0,s2>>>(Wo, Woh, D_MODEL, D_MODEL, 0, M4);
    cudaEventRecord(eWo, s2);
    wcvt<<<4*M4/256,256,0,s2>>>(W1, W1h, DFF, DFF, 0, 4*M4);
    cudaEventRecord(eW1, s2);
    wcvt<<<4*M4/256,256,0,s2>>>(W2, W2h, D_MODEL, D_MODEL, 0, 4*M4);
    cudaEventRecord(eW2, s2);
    wcvt<<<2*M4/256,256,0,s2>>>(Wf, Wfh, D_MODEL, D_MODEL, 0, 2*M4);
    cudaEventRecord(eWf, s2);

    // ---- s1: mamba branch + fusion(mamba half) fully off critical path ----
    cudaStreamWaitEvent(s1, eLn, 0);
    delta_bt_kernel<<<ROWS,256,0,s1>>>(xnh, Wdelta, bdelta, Win, b_in, delta, bt);
    scan_kernel<<<BATCH,32,0,s1>>>(delta, bt, Amat, h);
    cudaStreamWaitEvent(s1, eGate, 0);
    mamba_out_kernel<<<ROWS,256,0,s1>>>(h, Cmat, gateh, x, mambah);
    cudaStreamWaitEvent(s1, eWf, 0);
    // y = mamba @ Wf[:1024] + bf   (full rows)
    gemm_mma<0,0><<<gDfull,256,GEMM_SMEM,s1>>>(mambah, Wfh, bf, nullptr, y, nullptr,
                                               D_MODEL, D_MODEL, D_MODEL, D_MODEL, 0);
    cudaEventRecord(eMamba, s1);

    // ---- per-half transformer chains (H0 on stream 0, H1 on s3) ----
    for (int half=0; half<2; ++half){
        cudaStream_t st = half ? s3 : (cudaStream_t)0;
        const size_t r1024 = (size_t)half*HROWS*1024;
        const size_t r3072 = (size_t)half*HROWS*3072;
        const size_t r4096 = (size_t)half*HROWS*4096;
        if (half){ cudaStreamWaitEvent(st, eLn, 0); }
        cudaStreamWaitEvent(st, eWqkv, 0);
        gemm_mma<0,1><<<gQKVh,256,GEMM_SMEM,st>>>(xn1h + r1024, Wqkvh, bqkv, nullptr, nullptr,
                                                  qkvh + r3072, D_MODEL, D_MODEL, 3*D_MODEL, 3*D_MODEL, 0);
        attn_mma<<<dim3(SEQ/128, 2*NHEADS), 256, ATT_SMEM, st>>>(qkvh + r3072, ctxh + r1024);
        cudaStreamWaitEvent(st, eWo, 0);
        gemm_mma<0,0><<<gDh,256,GEMM_SMEM,st>>>(ctxh + r1024, Woh, bo, x + r1024, x2 + r1024, nullptr,
                                                D_MODEL, D_MODEL, D_MODEL, D_MODEL, D_MODEL);
        ln_h<<<HROWS,256,0,st>>>(x2 + r1024, ln2_g, ln2_b, xn2h + r1024, nullptr, nullptr, nullptr);
        cudaStreamWaitEvent(st, eW1, 0);
        gemm_mma<2,1><<<gFh,256,GEMM_SMEM,st>>>(xn2h + r1024, W1h, b1, nullptr, nullptr, ffn1h + r4096,
                                                D_MODEL, D_MODEL, DFF, DFF, 0);
        cudaStreamWaitEvent(st, eW2, 0);
        gemm_mma<0,1><<<gDh,256,GEMM_SMEM,st>>>(ffn1h + r4096, W2h, b2, x2 + r1024, nullptr, touth + r1024,
                                                DFF, DFF, D_MODEL, D_MODEL, D_MODEL);
        cudaStreamWaitEvent(st, eMamba, 0);
        // y[half] += tout[half] @ Wf[1024:]
        gemm_mma<0,0><<<gDh,256,GEMM_SMEM,st>>>(touth + r1024, Wfh + (size_t)D_MODEL*D_MODEL, nullptr,
                                                y + r1024, y + r1024, nullptr,
                                                D_MODEL, D_MODEL, D_MODEL, D_MODEL, D_MODEL);
        ln_f<<<HROWS,256,0,st>>>(y + r1024, lnf_g, lnf_b, (float*)d_out + r1024);
    }
    cudaEventRecord(eH1, s3);
    cudaStreamWaitEvent(0, eH1, 0);
}

// round 13
// speedup vs baseline: 14.7282x; 1.0223x over previous
#include <cuda_runtime.h>
#include <cuda_fp16.h>
#include <cstdint>
#include <math.h>

#define D_MODEL 1024
#define SEQ     2048
#define BATCH   4
#define ROWS    (BATCH*SEQ)   // 8192
#define HROWS   (ROWS/2)      // 4096 per pipeline half
#define DS      16
#define DFF     4096
#define NHEADS  8
#define HDIM    128

// ---------------- scratch ----------------
__device__ __half g_xnh  [ROWS*D_MODEL];
__device__ __half g_xn1h [ROWS*D_MODEL];
__device__ __half g_qkvh [ROWS*3*D_MODEL];     // q|k|v packed, pitch 3072
__device__ __half g_ctxh [ROWS*D_MODEL];
__device__ __half g_xn2h [ROWS*D_MODEL];
__device__ __half g_ffn1h[ROWS*DFF];
__device__ __half g_mambah[ROWS*D_MODEL];
__device__ __half g_touth [ROWS*D_MODEL];
__device__ __half g_gateh[ROWS*D_MODEL];
__device__ float  g_x2   [ROWS*D_MODEL];
__device__ float  g_y    [ROWS*D_MODEL];
__device__ float  g_delta[ROWS*DS];
__device__ float  g_bt   [ROWS*DS];
__device__ float  g_h    [ROWS*DS];
__device__ float  g_bqkv [3*D_MODEL];
// fp16 weights, ORIGINAL [K][N] row-major orientation
__device__ __half g_Wgh  [D_MODEL*D_MODEL];
__device__ __half g_Wqkvh[D_MODEL*3*D_MODEL];  // pitch 3072
__device__ __half g_Woh  [D_MODEL*D_MODEL];
__device__ __half g_W1h  [D_MODEL*DFF];
__device__ __half g_W2h  [DFF*D_MODEL];
__device__ __half g_Wfh  [2*D_MODEL*D_MODEL];

__device__ __forceinline__ float tanh_fast(float x){
    float y; asm("tanh.approx.f32 %0, %1;" : "=f"(y) : "f"(x)); return y;
}
__device__ __forceinline__ uint32_t smem_to_u32(const void* p){
    uint32_t a;
    asm("{ .reg .u64 t; cvta.to.shared.u64 t, %1; cvt.u32.u64 %0, t; }" : "=r"(a) : "l"(p));
    return a;
}
#define SWZ(o) ((o) ^ (((o) >> 3) & 0x70))

__device__ __forceinline__ void ldm_x4(uint32_t* r, uint32_t addr){
    asm volatile("ldmatrix.sync.aligned.m8n8.x4.shared.b16 {%0,%1,%2,%3}, [%4];"
        : "=r"(r[0]), "=r"(r[1]), "=r"(r[2]), "=r"(r[3]) : "r"(addr));
}
__device__ __forceinline__ void ldm_x4t(uint32_t* r, uint32_t addr){
    asm volatile("ldmatrix.sync.aligned.m8n8.x4.trans.shared.b16 {%0,%1,%2,%3}, [%4];"
        : "=r"(r[0]), "=r"(r[1]), "=r"(r[2]), "=r"(r[3]) : "r"(addr));
}
__device__ __forceinline__ void mma_fp16(float* d, const uint32_t* a, uint32_t b0, uint32_t b1){
    asm volatile("mma.sync.aligned.m16n8k16.row.col.f32.f16.f16.f32 "
        "{%0,%1,%2,%3}, {%4,%5,%6,%7}, {%8,%9}, {%0,%1,%2,%3};"
        : "+f"(d[0]), "+f"(d[1]), "+f"(d[2]), "+f"(d[3])
        : "r"(a[0]), "r"(a[1]), "r"(a[2]), "r"(a[3]), "r"(b0), "r"(b1));
}
__device__ __forceinline__ void cp16(uint32_t dst, const void* src){
    asm volatile("cp.async.cg.shared.global [%0], [%1], 16;" :: "r"(dst), "l"(src));
}
#define CP_COMMIT() asm volatile("cp.async.commit_group;" ::: "memory")
#define CP_WAIT1()  asm volatile("cp.async.wait_group 1;" ::: "memory")

// ---------------- weight convert ----------------
__global__ void __launch_bounds__(256) wcvt(const float* __restrict__ src, __half* __restrict__ dst,
                                            int N, int ldn, int coff, int total4){
    const int i = blockIdx.x*256 + threadIdx.x;
    if (i >= total4) return;
    const int e = i*4;
    const int row = e / N, col = e % N;
    const float4 v = *(const float4*)(src + e);
    __half* p = dst + (size_t)row*ldn + coff + col;
    *(__half2*)(p)   = __floats2half2_rn(v.x, v.y);
    *(__half2*)(p+2) = __floats2half2_rn(v.z, v.w);
}

__global__ void __launch_bounds__(256) biaspack(const float* bq, const float* bk, const float* bv,
                                                float* out){
    const int i = blockIdx.x*256 + threadIdx.x;
    if (i < D_MODEL){ out[i]=bq[i]; out[i+D_MODEL]=bk[i]; out[i+2*D_MODEL]=bv[i]; }
}

// ---------------- fp16 mma GEMM, cp.async 3-stage, tile 128x128 x k64, B row-major [K][N] ----------------
#define GEMM_SMEM (3*32768)
template<int ACT, int OUTH>
__global__ void __launch_bounds__(256,2) gemm_mma(
    const __half* __restrict__ A, const __half* __restrict__ B,
    const float* __restrict__ bias, const float* __restrict__ res,
    float* __restrict__ Cf, __half* __restrict__ Ch,
    int K, int lda, int ldb, int ldc, int ldr)
{
    extern __shared__ char smem[];
    const uint32_t sbase = smem_to_u32(smem);
    const int tid = threadIdx.x;
    const int lane = tid & 31, wid = tid >> 5;
    const int warp_m = wid >> 2, warp_n = wid & 3;
    const int row0 = blockIdx.y*128, col0 = blockIdx.x*128;
    const int sub = lane>>3, rr = lane&7;

    const __half* Ag = A + (size_t)row0*lda;
    const __half* Bg = B + col0;

    float acc[4][4][4];
    #pragma unroll
    for (int i=0;i<4;i++)
        #pragma unroll
        for (int j=0;j<4;j++){ acc[i][j][0]=0.f; acc[i][j][1]=0.f; acc[i][j][2]=0.f; acc[i][j][3]=0.f; }

    const int nk = K>>6;
    auto issue = [&](int kt){
        const uint32_t sA = sbase + (kt%3)*32768;
        const uint32_t sB = sA + 16384;
        const int koff = kt*64;
        #pragma unroll
        for (int i=0;i<4;i++){
            const int f = tid + i*256;
            const int ar = f>>3, aseg = f&7;
            cp16(sA + SWZ((uint32_t)(ar*128 + aseg*16)), Ag + (size_t)ar*lda + koff + aseg*8);
            const int br = f>>4, cs = f&15;
            cp16(sB + (cs>>3)*8192 + SWZ((uint32_t)(br*128 + (cs&7)*16)),
                 Bg + (size_t)(koff+br)*ldb + cs*8);
        }
    };
    issue(0); CP_COMMIT();
    if (nk>1) issue(1); CP_COMMIT();

    for (int kt=0; kt<nk; ++kt){
        CP_WAIT1();
        __syncthreads();
        if (kt+2 < nk) issue(kt+2);
        CP_COMMIT();
        const uint32_t aB = sbase + (kt%3)*32768;
        const uint32_t bB = aB + 16384;
        #pragma unroll
        for (int s=0;s<4;s++){
            uint32_t af[4][4], bf[2][4];
            #pragma unroll
            for (int mt=0;mt<4;mt++){
                const int m = warp_m*64 + mt*16 + (sub&1)*8 + rr;
                ldm_x4(af[mt], aB + SWZ((uint32_t)(m*128 + s*32 + (sub>>1)*16)));
            }
            #pragma unroll
            for (int p=0;p<2;p++){
                const int kr = s*16 + (sub&1)*8 + rr;
                const int nbase = warp_n*32 + p*16;
                const int dloc = (nbase&63) + (sub>>1)*8;
                ldm_x4t(bf[p], bB + (nbase>>6)*8192 + SWZ((uint32_t)(kr*128 + dloc*2)));
            }
            #pragma unroll
            for (int mt=0;mt<4;mt++)
                #pragma unroll
                for (int p=0;p<2;p++){
                    mma_fp16(acc[mt][p*2+0], af[mt], bf[p][0], bf[p][1]);
                    mma_fp16(acc[mt][p*2+1], af[mt], bf[p][2], bf[p][3]);
                }
        }
    }
    __syncthreads();

    // epilogue via smem staging (pitch 132 floats)
    float* Es = (float*)smem;
    const int qrow = lane>>2, qcol = (lane&3)*2;
    #pragma unroll
    for (int mt=0;mt<4;mt++)
        #pragma unroll
        for (int nt=0;nt<4;nt++)
            #pragma unroll
            for (int half=0; half<2; half++){
                const int r = warp_m*64 + mt*16 + qrow + half*8;
                const int c = warp_n*32 + nt*8 + qcol;
                *(float2*)&Es[r*132 + c] = make_float2(acc[mt][nt][half*2], acc[mt][nt][half*2+1]);
            }
    __syncthreads();
    #pragma unroll
    for (int i=0;i<16;i++){
        const int f = tid + i*256, r = f>>5, c4 = (f&31)<<2;
        float4 v = *(float4*)&Es[r*132 + c4];
        const int col = col0 + c4;
        if (bias){
            const float4 bb = *(const float4*)(bias + col);
            v.x+=bb.x; v.y+=bb.y; v.z+=bb.z; v.w+=bb.w;
        }
        if (ACT==1){
            v.x=1.f/(1.f+__expf(-v.x)); v.y=1.f/(1.f+__expf(-v.y));
            v.z=1.f/(1.f+__expf(-v.z)); v.w=1.f/(1.f+__expf(-v.w));
        } else if (ACT==2){
            v.x=fmaxf(v.x,0.f); v.y=fmaxf(v.y,0.f); v.z=fmaxf(v.z,0.f); v.w=fmaxf(v.w,0.f);
        }
        if (res){
            const float4 rv = *(const float4*)(res + (size_t)(row0+r)*ldr + col);
            v.x+=rv.x; v.y+=rv.y; v.z+=rv.z; v.w+=rv.w;
        }
        if (OUTH){
            __half* p = Ch + (size_t)(row0+r)*ldc + col;
            *(__half2*)(p)   = __floats2half2_rn(v.x, v.y);
            *(__half2*)(p+2) = __floats2half2_rn(v.z, v.w);
        } else {
            *(float4*)(Cf + (size_t)(row0+r)*ldc + col) = v;
        }
    }
}

// ---------------- fp16 mma flash attention, double-buffered KV, register-resident P ----------------
// smem: Q 32KB | K 2 bufs x 16KB | V 2 bufs x 16KB = 96KB
#define ATT_SMEM (32768 + 32768 + 32768)
__global__ void __launch_bounds__(256,2) attn_mma(
    const __half* __restrict__ QKV, __half* __restrict__ O)
{
    extern __shared__ char smem[];
    const uint32_t sQ = smem_to_u32(smem);
    const uint32_t sK = sQ + 32768;
    const uint32_t sV = sK + 32768;

    const int tid = threadIdx.x, lane = tid&31, wid = tid>>5;
    const int sub = lane>>3, rr = lane&7;
    const int qt = blockIdx.x;
    const int b  = blockIdx.y>>3, h = blockIdx.y&7;
    const int m0 = wid*16;
    const float scale = 0.08838834764831845f;

    const __half* Qb = QKV + ((size_t)(b*SEQ + qt*128))*3072 + h*HDIM;
    const __half* Kb = QKV + (size_t)b*SEQ*3072 + D_MODEL   + h*HDIM;
    const __half* Vb = QKV + (size_t)b*SEQ*3072 + 2*D_MODEL + h*HDIM;

    auto issueKV = [&](int kv){
        const uint32_t kbuf = sK + (kv&1)*16384;
        const uint32_t vbuf = sV + (kv&1)*16384;
        #pragma unroll
        for (int i=0;i<4;i++){
            const int f = tid + i*256, r = f>>4, cs = f&15;
            const uint32_t off = (uint32_t)((cs>>3)*8192 + SWZ((uint32_t)(r*128 + (cs&7)*16)));
            cp16(kbuf + off, Kb + (size_t)(kv*64+r)*3072 + cs*8);
            cp16(vbuf + off, Vb + (size_t)(kv*64+r)*3072 + cs*8);
        }
    };

    #pragma unroll
    for (int i=0;i<8;i++){
        const int f = tid + i*256, r = f>>4, cs = f&15;
        const uint4 v = *(const uint4*)(Qb + (size_t)r*3072 + cs*8);
        *(uint4*)(smem + (cs>>3)*16384 + SWZ((uint32_t)(r*128 + (cs&7)*16))) = v;
    }
    issueKV(0); CP_COMMIT();
    issueKV(1); CP_COMMIT();

    float oacc[16][4];
    #pragma unroll
    for (int i=0;i<16;i++){ oacc[i][0]=0.f; oacc[i][1]=0.f; oacc[i][2]=0.f; oacc[i][3]=0.f; }
    float m_run[2] = {-1e30f,-1e30f}, l_run[2] = {0.f,0.f};

    for (int kv=0; kv<SEQ/64; ++kv){
        CP_WAIT1();
        __syncthreads();
        const uint32_t kB = sK + (kv&1)*16384;
        const uint32_t vB = sV + (kv&1)*16384;

        // ---- S = Q @ K^T ----
        float sacc[8][4];
        #pragma unroll
        for (int i=0;i<8;i++){ sacc[i][0]=0.f; sacc[i][1]=0.f; sacc[i][2]=0.f; sacc[i][3]=0.f; }
        #pragma unroll
        for (int s=0;s<8;s++){
            const int p = s>>2, sk = s&3;
            uint32_t af[4], bf[4][4];
            {
                const int m = m0 + (sub&1)*8 + rr;
                ldm_x4(af, sQ + p*16384 + SWZ((uint32_t)(m*128 + sk*32 + (sub>>1)*16)));
            }
            #pragma unroll
            for (int g=0;g<4;g++){
                const int n = g*16 + (sub&1)*8 + rr;
                ldm_x4(bf[g], kB + p*8192 + SWZ((uint32_t)(n*128 + sk*32 + (sub>>1)*16)));
            }
            #pragma unroll
            for (int g=0;g<4;g++){
                mma_fp16(sacc[g*2+0], af, bf[g][0], bf[g][2]);
                mma_fp16(sacc[g*2+1], af, bf[g][1], bf[g][3]);
            }
        }

        // ---- FA2 softmax; P packed straight into A-fragment registers ----
        // A-frag (m16k16) for k16-step t: {S[2t].(d0,d1), S[2t].(d2,d3), S[2t+1].(d0,d1), S[2t+1].(d2,d3)}
        uint32_t pf[16];
        #pragma unroll
        for (int hh=0; hh<2; ++hh){
            float mx = -1e30f;
            #pragma unroll
            for (int nt=0;nt<8;nt++)
                mx = fmaxf(mx, fmaxf(sacc[nt][hh*2], sacc[nt][hh*2+1]));
            mx *= scale;
            mx = fmaxf(mx, __shfl_xor_sync(0xffffffffu, mx, 1));
            mx = fmaxf(mx, __shfl_xor_sync(0xffffffffu, mx, 2));
            const float mnew = fmaxf(m_run[hh], mx);
            const float alpha = __expf(m_run[hh] - mnew);
            float lsum = 0.f;
            #pragma unroll
            for (int nt=0;nt<8;nt++){
                const float p0 = __expf(scale*sacc[nt][hh*2+0] - mnew);
                const float p1 = __expf(scale*sacc[nt][hh*2+1] - mnew);
                lsum += p0 + p1;
                __half2 hp = __floats2half2_rn(p0, p1);
                pf[(nt>>1)*4 + (nt&1)*2 + hh] = *reinterpret_cast<uint32_t*>(&hp);
            }
            lsum += __shfl_xor_sync(0xffffffffu, lsum, 1);
            lsum += __shfl_xor_sync(0xffffffffu, lsum, 2);
            #pragma unroll
            for (int nt=0;nt<16;nt++){ oacc[nt][hh*2] *= alpha; oacc[nt][hh*2+1] *= alpha; }
            l_run[hh] = l_run[hh]*alpha + lsum;
            m_run[hh] = mnew;
        }

        // ---- O += P @ V (A from registers, B via ldmatrix.trans on V) ----
        #pragma unroll
        for (int t=0;t<4;t++){
            const uint32_t* af = &pf[t*4];
            #pragma unroll
            for (int g=0;g<8;g++){
                uint32_t vf[4];
                const int dbase = g*16;
                const int kvrow = t*16 + (sub&1)*8 + rr;
                const int dloc  = (dbase + (sub>>1)*8) & 63;
                ldm_x4t(vf, vB + (dbase>>6)*8192 + SWZ((uint32_t)(kvrow*128 + dloc*2)));
                mma_fp16(oacc[g*2+0], af, vf[0], vf[1]);
                mma_fp16(oacc[g*2+1], af, vf[2], vf[3]);
            }
        }
        __syncthreads();                      // all warps done with buf kv&1
        if (kv+2 < SEQ/64) issueKV(kv+2);
        CP_COMMIT();
    }

    __half* Ob = O + ((size_t)(b*SEQ + qt*128))*D_MODEL + h*HDIM;
    #pragma unroll
    for (int hh=0; hh<2; ++hh){
        const float inv = 1.f/l_run[hh];
        const int row = m0 + (lane>>2) + hh*8;
        #pragma unroll
        for (int nt=0;nt<16;nt++){
            const int col = nt*8 + (lane&3)*2;
            *(__half2*)(Ob + (size_t)row*D_MODEL + col) =
                __floats2half2_rn(oacc[nt][hh*2]*inv, oacc[nt][hh*2+1]*inv);
        }
    }
}

// ---------------- LayerNorm -> fp16 (dual) ----------------
__global__ void __launch_bounds__(256) ln_h(
    const float* __restrict__ x,
    const float* __restrict__ g0, const float* __restrict__ b0, __half* __restrict__ out0,
    const float* __restrict__ g1, const float* __restrict__ b1, __half* __restrict__ out1)
{
    __shared__ float red[64];
    const int row = blockIdx.x;
    const int tid = threadIdx.x;
    const float4 v = ((const float4*)(x + (size_t)row*D_MODEL))[tid];
    float s  = v.x+v.y+v.z+v.w;
    float sq = v.x*v.x+v.y*v.y+v.z*v.z+v.w*v.w;
    #pragma unroll
    for (int o=16;o;o>>=1){ s += __shfl_xor_sync(0xffffffffu,s,o); sq += __shfl_xor_sync(0xffffffffu,sq,o); }
    if ((tid&31)==0){ red[tid>>5]=s; red[(tid>>5)+8]=sq; }
    __syncthreads();
    if (tid<32){
        float ss=(tid<8)?red[tid]:0.f, qq=(tid<8)?red[tid+8]:0.f;
        #pragma unroll
        for (int o=4;o;o>>=1){ ss += __shfl_xor_sync(0xffffffffu,ss,o); qq += __shfl_xor_sync(0xffffffffu,qq,o); }
        if (tid==0){ red[32]=ss; red[33]=qq; }
    }
    __syncthreads();
    const float mean = red[32]*(1.f/D_MODEL);
    const float var  = red[33]*(1.f/D_MODEL) - mean*mean;
    const float inv  = rsqrtf(var + 1e-5f);
    {
        const float4 g = ((const float4*)g0)[tid];
        const float4 b = ((const float4*)b0)[tid];
        __half2 h0 = __floats2half2_rn((v.x-mean)*inv*g.x + b.x, (v.y-mean)*inv*g.y + b.y);
        __half2 h1 = __floats2half2_rn((v.z-mean)*inv*g.z + b.z, (v.w-mean)*inv*g.w + b.w);
        __half* p = out0 + (size_t)row*D_MODEL + tid*4;
        *(__half2*)p = h0; *(__half2*)(p+2) = h1;
    }
    if (out1){
        const float4 g = ((const float4*)g1)[tid];
        const float4 b = ((const float4*)b1)[tid];
        __half2 h0 = __floats2half2_rn((v.x-mean)*inv*g.x + b.x, (v.y-mean)*inv*g.y + b.y);
        __half2 h1 = __floats2half2_rn((v.z-mean)*inv*g.z + b.z, (v.w-mean)*inv*g.w + b.w);
        __half* p = out1 + (size_t)row*D_MODEL + tid*4;
        *(__half2*)p = h0; *(__half2*)(p+2) = h1;
    }
}

// ---------------- final LayerNorm -> fp32 ----------------
__global__ void __launch_bounds__(256) ln_f(
    const float* __restrict__ x,
    const float* __restrict__ g0, const float* __restrict__ b0, float* __restrict__ out0)
{
    __shared__ float red[64];
    const int row = blockIdx.x;
    const int tid = threadIdx.x;
    const float4 v = ((const float4*)(x + (size_t)row*D_MODEL))[tid];
    float s  = v.x+v.y+v.z+v.w;
    float sq = v.x*v.x+v.y*v.y+v.z*v.z+v.w*v.w;
    #pragma unroll
    for (int o=16;o;o>>=1){ s += __shfl_xor_sync(0xffffffffu,s,o); sq += __shfl_xor_sync(0xffffffffu,sq,o); }
    if ((tid&31)==0){ red[tid>>5]=s; red[(tid>>5)+8]=sq; }
    __syncthreads();
    if (tid<32){
        float ss=(tid<8)?red[tid]:0.f, qq=(tid<8)?red[tid+8]:0.f;
        #pragma unroll
        for (int o=4;o;o>>=1){ ss += __shfl_xor_sync(0xffffffffu,ss,o); qq += __shfl_xor_sync(0xffffffffu,qq,o); }
        if (tid==0){ red[32]=ss; red[33]=qq; }
    }
    __syncthreads();
    const float mean = red[32]*(1.f/D_MODEL);
    const float var  = red[33]*(1.f/D_MODEL) - mean*mean;
    const float inv  = rsqrtf(var + 1e-5f);
    const float4 g = ((const float4*)g0)[tid];
    const float4 b = ((const float4*)b0)[tid];
    float4 o0;
    o0.x = (v.x-mean)*inv*g.x + b.x;
    o0.y = (v.y-mean)*inv*g.y + b.y;
    o0.z = (v.z-mean)*inv*g.z + b.z;
    o0.w = (v.w-mean)*inv*g.w + b.w;
    ((float4*)(out0 + (size_t)row*D_MODEL))[tid] = o0;
}

// ---------------- delta / Bt (xn fp16 in) ----------------
__global__ void __launch_bounds__(256) delta_bt_kernel(
    const __half* __restrict__ xn,
    const float* __restrict__ Wd, const float* __restrict__ bd,
    const float* __restrict__ Wi, const float* __restrict__ bi,
    float* __restrict__ delta, float* __restrict__ bt)
{
    __shared__ float xs[D_MODEL];
    __shared__ float red[256];
    const int row = blockIdx.x, tid = threadIdx.x;
    #pragma unroll
    for (int i=0;i<4;i++) xs[tid + i*256] = __half2float(xn[(size_t)row*D_MODEL + tid + i*256]);
    __syncthreads();
    const int c = tid & 15;
    const int which = (tid>>4)&1;
    const int grp = tid>>5;
    const float* W = which ? Wi : Wd;
    float acc = 0.f;
    const int k0 = grp*128;
    #pragma unroll 8
    for (int k=0;k<128;k++) acc += xs[k0+k]*W[(size_t)(k0+k)*16 + c];
    red[tid]=acc; __syncthreads();
    if (tid<32){
        float sacc=0.f;
        #pragma unroll
        for (int g=0;g<8;g++) sacc += red[g*32+tid];
        if (tid<16) delta[(size_t)row*16+tid] = 1.f/(1.f+__expf(-(sacc+bd[tid])));
        else        bt   [(size_t)row*16+tid-16] = sacc + bi[tid-16];
    }
}

// ---------------- sequential mamba scan ----------------
__global__ void __launch_bounds__(32) scan_kernel(
    const float* __restrict__ delta, const float* __restrict__ bt,
    const float* __restrict__ A, float* __restrict__ h_all)
{
    __shared__ float ds[128*16], bs[128*16];
    const int b = blockIdx.x, lane = threadIdx.x;
    const int j = lane & 15;
    float Acol[16];
    #pragma unroll
    for (int i=0;i<16;i++) Acol[i] = A[i*16 + j];
    float h = 0.f;
    const float* dp = delta + (size_t)b*SEQ*16;
    const float* bp = bt    + (size_t)b*SEQ*16;
    float* hp = h_all + (size_t)b*SEQ*16;
    for (int chunk=0; chunk<SEQ; chunk+=128){
        const float4* s0 = (const float4*)(dp + (size_t)chunk*16);
        const float4* s1 = (const float4*)(bp + (size_t)chunk*16);
        for (int i=lane;i<512;i+=32){ ((float4*)ds)[i]=s0[i]; ((float4*)bs)[i]=s1[i]; }
        __syncwarp();
        #pragma unroll 4
        for (int t=0;t<128;t++){
            const float d = ds[t*16+j];
            const float bv = bs[t*16+j];
            const float v = h*d;
            float a0 = bv, a1 = 0.f;
            #pragma unroll
            for (int i=0;i<16;i+=2){
                a0 += __shfl_sync(0xffffffffu, v, i,   16)*Acol[i];
                a1 += __shfl_sync(0xffffffffu, v, i+1, 16)*Acol[i+1];
            }
            h = tanh_fast(a0+a1);
            if (lane<16) hp[(size_t)(chunk+t)*16 + j] = h;
        }
        __syncwarp();
    }
}

// ---------------- mamba_out -> mambah fp16 (pitch 1024) ----------------
__global__ void __launch_bounds__(256) mamba_out_kernel(
    const float* __restrict__ h_all, const float* __restrict__ Cm,
    const __half* __restrict__ gate, const float* __restrict__ x,
    __half* __restrict__ out)
{
    __shared__ float hs[16];
    const int row = blockIdx.x, tid = threadIdx.x;
    if (tid<16) hs[tid] = h_all[(size_t)row*16+tid];
    __syncthreads();
    const size_t base = (size_t)row*D_MODEL;
    #pragma unroll
    for (int kk=0; kk<4; kk++){
        const int c = tid + kk*256;
        float acc = 0.f;
        #pragma unroll
        for (int i=0;i<16;i++) acc += hs[i]*Cm[(size_t)i*D_MODEL + c];
        out[base+c] = __float2half_rn(acc*__half2float(gate[base+c]) + x[base+c]);
    }
}

// ---------------- launch ----------------
extern "C" void kernel_launch(void* const* d_in, const int* in_sizes, int n_in,
                              void* d_out, int out_size)
{
    const float* x      = (const float*)d_in[0];
    const float* ln_g   = (const float*)d_in[1];
    const float* ln_b   = (const float*)d_in[2];
    const float* Wdelta = (const float*)d_in[3];
    const float* bdelta = (const float*)d_in[4];
    const float* Win    = (const float*)d_in[5];
    const float* b_in   = (const float*)d_in[6];
    const float* Wgate  = (const float*)d_in[7];
    const float* bgate  = (const float*)d_in[8];
    const float* Amat   = (const float*)d_in[9];
    const float* Cmat   = (const float*)d_in[10];
    const float* ln1_g  = (const float*)d_in[11];
    const float* ln1_b  = (const float*)d_in[12];
    const float* Wq     = (const float*)d_in[13];
    const float* bq     = (const float*)d_in[14];
    const float* Wk     = (const float*)d_in[15];
    const float* bk     = (const float*)d_in[16];
    const float* Wv     = (const float*)d_in[17];
    const float* bv     = (const float*)d_in[18];
    const float* Wo     = (const float*)d_in[19];
    const float* bo     = (const float*)d_in[20];
    const float* ln2_g  = (const float*)d_in[21];
    const float* ln2_b  = (const float*)d_in[22];
    const float* W1     = (const float*)d_in[23];
    const float* b1     = (const float*)d_in[24];
    const float* W2     = (const float*)d_in[25];
    const float* b2     = (const float*)d_in[26];
    const float* Wf     = (const float*)d_in[27];
    const float* bf     = (const float*)d_in[28];
    const float* lnf_g  = (const float*)d_in[29];
    const float* lnf_b  = (const float*)d_in[30];

    __half *xnh,*xn1h,*qkvh,*ctxh,*xn2h,*ffn1h,*mambah,*touth,*gateh;
    __half *Wgh,*Wqkvh,*Woh,*W1h,*W2h,*Wfh;
    float *x2,*y,*delta,*bt,*h,*bqkv;
    cudaGetSymbolAddress((void**)&xnh,  g_xnh);
    cudaGetSymbolAddress((void**)&xn1h, g_xn1h);
    cudaGetSymbolAddress((void**)&qkvh, g_qkvh);
    cudaGetSymbolAddress((void**)&ctxh, g_ctxh);
    cudaGetSymbolAddress((void**)&xn2h, g_xn2h);
    cudaGetSymbolAddress((void**)&ffn1h,g_ffn1h);
    cudaGetSymbolAddress((void**)&mambah,g_mambah);
    cudaGetSymbolAddress((void**)&touth,g_touth);
    cudaGetSymbolAddress((void**)&gateh,g_gateh);
    cudaGetSymbolAddress((void**)&x2,   g_x2);
    cudaGetSymbolAddress((void**)&y,    g_y);
    cudaGetSymbolAddress((void**)&delta,g_delta);
    cudaGetSymbolAddress((void**)&bt,   g_bt);
    cudaGetSymbolAddress((void**)&h,    g_h);
    cudaGetSymbolAddress((void**)&bqkv, g_bqkv);
    cudaGetSymbolAddress((void**)&Wgh,  g_Wgh);
    cudaGetSymbolAddress((void**)&Wqkvh,g_Wqkvh);
    cudaGetSymbolAddress((void**)&Woh,  g_Woh);
    cudaGetSymbolAddress((void**)&W1h,  g_W1h);
    cudaGetSymbolAddress((void**)&W2h,  g_W2h);
    cudaGetSymbolAddress((void**)&Wfh,  g_Wfh);

    cudaFuncSetAttribute(gemm_mma<0,0>, cudaFuncAttributeMaxDynamicSharedMemorySize, GEMM_SMEM);
    cudaFuncSetAttribute(gemm_mma<0,1>, cudaFuncAttributeMaxDynamicSharedMemorySize, GEMM_SMEM);
    cudaFuncSetAttribute(gemm_mma<1,1>, cudaFuncAttributeMaxDynamicSharedMemorySize, GEMM_SMEM);
    cudaFuncSetAttribute(gemm_mma<2,1>, cudaFuncAttributeMaxDynamicSharedMemorySize, GEMM_SMEM);
    cudaFuncSetAttribute(attn_mma, cudaFuncAttributeMaxDynamicSharedMemorySize, ATT_SMEM);

    static cudaStream_t s1 = nullptr, s2 = nullptr, s3 = nullptr;
    static cudaEvent_t eFork, eLn0, eLn1, eWqkv, eWo, eW1, eW2, eWf, eGate, eMamba, eH1;
    if (!s1){
        cudaStreamCreateWithFlags(&s1, cudaStreamNonBlocking);
        cudaStreamCreateWithFlags(&s2, cudaStreamNonBlocking);
        cudaStreamCreateWithFlags(&s3, cudaStreamNonBlocking);
        cudaEventCreateWithFlags(&eFork,  cudaEventDisableTiming);
        cudaEventCreateWithFlags(&eLn0,   cudaEventDisableTiming);
        cudaEventCreateWithFlags(&eLn1,   cudaEventDisableTiming);
        cudaEventCreateWithFlags(&eWqkv,  cudaEventDisableTiming);
        cudaEventCreateWithFlags(&eWo,    cudaEventDisableTiming);
        cudaEventCreateWithFlags(&eW1,    cudaEventDisableTiming);
        cudaEventCreateWithFlags(&eW2,    cudaEventDisableTiming);
        cudaEventCreateWithFlags(&eWf,    cudaEventDisableTiming);
        cudaEventCreateWithFlags(&eGate,  cudaEventDisableTiming);
        cudaEventCreateWithFlags(&eMamba, cudaEventDisableTiming);
        cudaEventCreateWithFlags(&eH1,    cudaEventDisableTiming);
    }

    const dim3 gDh(D_MODEL/128, HROWS/128);       // (8, 32)
    const dim3 gDfull(D_MODEL/128, ROWS/128);     // (8, 64)
    const dim3 gQKVh(3*D_MODEL/128, HROWS/128);   // (24, 32)
    const dim3 gFh(DFF/128, HROWS/128);           // (32, 32)
    const int M4 = D_MODEL*D_MODEL/4;

    // ---- fork ----
    cudaEventRecord(eFork, 0);
    cudaStreamWaitEvent(s1, eFork, 0);
    cudaStreamWaitEvent(s2, eFork, 0);
    cudaStreamWaitEvent(s3, eFork, 0);

    // ---- s2: weight conversions ----
    wcvt<<<M4/256,256,0,s2>>>(Wq, Wqkvh, D_MODEL, 3*D_MODEL, 0,         M4);
    wcvt<<<M4/256,256,0,s2>>>(Wk, Wqkvh, D_MODEL, 3*D_MODEL, D_MODEL,   M4);
    wcvt<<<M4/256,256,0,s2>>>(Wv, Wqkvh, D_MODEL, 3*D_MODEL, 2*D_MODEL, M4);
    biaspack<<<4,256,0,s2>>>(bq, bk, bv, bqkv);
    cudaEventRecord(eWqkv, s2);
    wcvt<<<M4/256,256,0,s2>>>(Wgate, Wgh, D_MODEL, D_MODEL, 0, M4);

    // ---- per-half dual LN (H0 on stream0, H1 on s3) ----
    ln_h<<<HROWS,256>>>(x, ln_g, ln_b, xnh, ln1_g, ln1_b, xn1h);
    cudaEventRecord(eLn0, 0);
    ln_h<<<HROWS,256,0,s3>>>(x + (size_t)HROWS*D_MODEL, ln_g, ln_b, xnh + (size_t)HROWS*D_MODEL,
                             ln1_g, ln1_b, xn1h + (size_t)HROWS*D_MODEL);
    cudaEventRecord(eLn1, s3);

    // ---- s2 cont: gate GEMM (needs full xnh) + remaining weight cvts ----
    cudaStreamWaitEvent(s2, eLn0, 0);
    cudaStreamWaitEvent(s2, eLn1, 0);
    gemm_mma<1,1><<<gDfull,256,GEMM_SMEM,s2>>>(xnh, Wgh, bgate, nullptr, nullptr, gateh,
                                               D_MODEL, D_MODEL, D_MODEL, D_MODEL, 0);
    cudaEventRecord(eGate, s2);
    wcvt<<<M4/256,256,0,s2>>>(Wo, Woh, D_MODEL, D_MODEL, 0, M4);
    cudaEventRecord(eWo, s2);
    wcvt<<<4*M4/256,256,0,s2>>>(W1, W1h, DFF, DFF, 0, 4*M4);
    cudaEventRecord(eW1, s2);
    wcvt<<<4*M4/256,256,0,s2>>>(W2, W2h, D_MODEL, D_MODEL, 0, 4*M4);
    cudaEventRecord(eW2, s2);
    wcvt<<<2*M4/256,256,0,s2>>>(Wf, Wfh, D_MODEL, D_MODEL, 0, 2*M4);
    cudaEventRecord(eWf, s2);

    // ---- s1: mamba branch + fusion(mamba half) off the critical path ----
    cudaStreamWaitEvent(s1, eLn0, 0);
    cudaStreamWaitEvent(s1, eLn1, 0);
    delta_bt_kernel<<<ROWS,256,0,s1>>>(xnh, Wdelta, bdelta, Win, b_in, delta, bt);
    scan_kernel<<<BATCH,32,0,s1>>>(delta, bt, Amat, h);
    cudaStreamWaitEvent(s1, eGate, 0);
    mamba_out_kernel<<<ROWS,256,0,s1>>>(h, Cmat, gateh, x, mambah);
    cudaStreamWaitEvent(s1, eWf, 0);
    gemm_mma<0,0><<<gDfull,256,GEMM_SMEM,s1>>>(mambah, Wfh, bf, nullptr, y, nullptr,
                                               D_MODEL, D_MODEL, D_MODEL, D_MODEL, 0);
    cudaEventRecord(eMamba, s1);

    // ---- per-half transformer chains (H0 on stream 0, H1 on s3) ----
    for (int half=0; half<2; ++half){
        cudaStream_t st = half ? s3 : (cudaStream_t)0;
        const size_t r1024 = (size_t)half*HROWS*1024;
        const size_t r3072 = (size_t)half*HROWS*3072;
        const size_t r4096 = (size_t)half*HROWS*4096;
        cudaStreamWaitEvent(st, eWqkv, 0);
        gemm_mma<0,1><<<gQKVh,256,GEMM_SMEM,st>>>(xn1h + r1024, Wqkvh, bqkv, nullptr, nullptr,
                                                  qkvh + r3072, D_MODEL, D_MODEL, 3*D_MODEL, 3*D_MODEL, 0);
        attn_mma<<<dim3(SEQ/128, 2*NHEADS), 256, ATT_SMEM, st>>>(qkvh + r3072, ctxh + r1024);
        cudaStreamWaitEvent(st, eWo, 0);
        gemm_mma<0,0><<<gDh,256,GEMM_SMEM,st>>>(ctxh + r1024, Woh, bo, x + r1024, x2 + r1024, nullptr,
                                                D_MODEL, D_MODEL, D_MODEL, D_MODEL, D_MODEL);
        ln_h<<<HROWS,256,0,st>>>(x2 + r1024, ln2_g, ln2_b, xn2h + r1024, nullptr, nullptr, nullptr);
        cudaStreamWaitEvent(st, eW1, 0);
        gemm_mma<2,1><<<gFh,256,GEMM_SMEM,st>>>(xn2h + r1024, W1h, b1, nullptr, nullptr, ffn1h + r4096,
                                                D_MODEL, D_MODEL, DFF, DFF, 0);
        cudaStreamWaitEvent(st, eW2, 0);
        gemm_mma<0,1><<<gDh,256,GEMM_SMEM,st>>>(ffn1h + r4096, W2h, b2, x2 + r1024, nullptr, touth + r1024,
                                                DFF, DFF, D_MODEL, D_MODEL, D_MODEL);
        cudaStreamWaitEvent(st, eMamba, 0);
        gemm_mma<0,0><<<gDh,256,GEMM_SMEM,st>>>(touth + r1024, Wfh + (size_t)D_MODEL*D_MODEL, nullptr,
                                                y + r1024, y + r1024, nullptr,
                                                D_MODEL, D_MODEL, D_MODEL, D_MODEL, D_MODEL);
        ln_f<<<HROWS,256,0,st>>>(y + r1024, lnf_g, lnf_b, (float*)d_out + r1024);
    }
    cudaEventRecord(eH1, s3);
    cudaStreamWaitEvent(0, eH1, 0);
}

// round 15
// speedup vs baseline: 14.9030x; 1.0119x over previous
#include <cuda_runtime.h>
#include <cuda_fp16.h>
#include <cstdint>
#include <math.h>

#define D_MODEL 1024
#define SEQ     2048
#define BATCH   4
#define ROWS    (BATCH*SEQ)   // 8192
#define HROWS   (ROWS/2)      // 4096 per pipeline half
#define DS      16
#define DFF     4096
#define NHEADS  8
#define HDIM    128

// ---------------- scratch ----------------
__device__ __half g_xnh  [ROWS*D_MODEL];
__device__ __half g_xn1h [ROWS*D_MODEL];
__device__ __half g_qkvh [ROWS*3*D_MODEL];     // q|k|v packed, pitch 3072
__device__ __half g_ctxh [ROWS*D_MODEL];
__device__ __half g_xn2h [ROWS*D_MODEL];
__device__ __half g_ffn1h[ROWS*DFF];
__device__ __half g_mambah[ROWS*D_MODEL];
__device__ __half g_touth [ROWS*D_MODEL];
__device__ __half g_gateh[ROWS*D_MODEL];
__device__ float  g_x2   [ROWS*D_MODEL];
__device__ float  g_y    [ROWS*D_MODEL];
__device__ float  g_delta[ROWS*DS];
__device__ float  g_bt   [ROWS*DS];
__device__ float  g_h    [ROWS*DS];
__device__ float  g_bqkv [3*D_MODEL];
// fp16 weights, ORIGINAL [K][N] row-major orientation
__device__ __half g_Wgh  [D_MODEL*D_MODEL];
__device__ __half g_Wqkvh[D_MODEL*3*D_MODEL];  // pitch 3072
__device__ __half g_Woh  [D_MODEL*D_MODEL];
__device__ __half g_W1h  [D_MODEL*DFF];
__device__ __half g_W2h  [DFF*D_MODEL];
__device__ __half g_Wfh  [2*D_MODEL*D_MODEL];

__device__ __forceinline__ float tanh_fast(float x){
    float y; asm("tanh.approx.f32 %0, %1;" : "=f"(y) : "f"(x)); return y;
}
__device__ __forceinline__ uint32_t smem_to_u32(const void* p){
    uint32_t a;
    asm("{ .reg .u64 t; cvta.to.shared.u64 t, %1; cvt.u32.u64 %0, t; }" : "=r"(a) : "l"(p));
    return a;
}
#define SWZ(o) ((o) ^ (((o) >> 3) & 0x70))

__device__ __forceinline__ void ldm_x4(uint32_t* r, uint32_t addr){
    asm volatile("ldmatrix.sync.aligned.m8n8.x4.shared.b16 {%0,%1,%2,%3}, [%4];"
        : "=r"(r[0]), "=r"(r[1]), "=r"(r[2]), "=r"(r[3]) : "r"(addr));
}
__device__ __forceinline__ void ldm_x4t(uint32_t* r, uint32_t addr){
    asm volatile("ldmatrix.sync.aligned.m8n8.x4.trans.shared.b16 {%0,%1,%2,%3}, [%4];"
        : "=r"(r[0]), "=r"(r[1]), "=r"(r[2]), "=r"(r[3]) : "r"(addr));
}
__device__ __forceinline__ void mma_fp16(float* d, const uint32_t* a, uint32_t b0, uint32_t b1){
    asm volatile("mma.sync.aligned.m16n8k16.row.col.f32.f16.f16.f32 "
        "{%0,%1,%2,%3}, {%4,%5,%6,%7}, {%8,%9}, {%0,%1,%2,%3};"
        : "+f"(d[0]), "+f"(d[1]), "+f"(d[2]), "+f"(d[3])
        : "r"(a[0]), "r"(a[1]), "r"(a[2]), "r"(a[3]), "r"(b0), "r"(b1));
}
__device__ __forceinline__ void cp16(uint32_t dst, const void* src){
    asm volatile("cp.async.cg.shared.global [%0], [%1], 16;" :: "r"(dst), "l"(src));
}
#define CP_COMMIT() asm volatile("cp.async.commit_group;" ::: "memory")
#define CP_WAIT1()  asm volatile("cp.async.wait_group 1;" ::: "memory")

// ---------------- weight convert ----------------
__global__ void __launch_bounds__(256) wcvt(const float* __restrict__ src, __half* __restrict__ dst,
                                            int N, int ldn, int coff, int total4){
    const int i = blockIdx.x*256 + threadIdx.x;
    if (i >= total4) return;
    const int e = i*4;
    const int row = e / N, col = e % N;
    const float4 v = *(const float4*)(src + e);
    __half* p = dst + (size_t)row*ldn + coff + col;
    *(__half2*)(p)   = __floats2half2_rn(v.x, v.y);
    *(__half2*)(p+2) = __floats2half2_rn(v.z, v.w);
}

// fused: Wq|Wk|Wv -> Wqkvh (pitch 3072) + bias pack, single launch
// grid = 3*M4/256 + 1
__global__ void __launch_bounds__(256) wcvt_qkv(
    const float* __restrict__ Wq, const float* __restrict__ Wk, const float* __restrict__ Wv,
    const float* __restrict__ bq, const float* __restrict__ bk, const float* __restrict__ bv,
    __half* __restrict__ dst, float* __restrict__ bout, int M4)
{
    const int blk = blockIdx.x;
    if (blk >= 3*(M4/256)){
        const int i = threadIdx.x;
        #pragma unroll
        for (int j=0;j<4;j++){
            const int c = i + j*256;
            bout[c] = bq[c]; bout[c+D_MODEL] = bk[c]; bout[c+2*D_MODEL] = bv[c];
        }
        return;
    }
    const int which = blk / (M4/256);
    const int i = (blk % (M4/256))*256 + threadIdx.x;
    const float* src = which==0 ? Wq : (which==1 ? Wk : Wv);
    const int e = i*4;
    const int row = e >> 10, col = e & 1023;          // N = D_MODEL = 1024
    const float4 v = *(const float4*)(src + e);
    __half* p = dst + (size_t)row*(3*D_MODEL) + which*D_MODEL + col;
    *(__half2*)(p)   = __floats2half2_rn(v.x, v.y);
    *(__half2*)(p+2) = __floats2half2_rn(v.z, v.w);
}

// ---------------- fp16 mma GEMM, cp.async 3-stage, tile 128x128 x k64, B row-major [K][N] ----------------
#define GEMM_SMEM (3*32768)
template<int ACT, int OUTH>
__global__ void __launch_bounds__(256,2) gemm_mma(
    const __half* __restrict__ A, const __half* __restrict__ B,
    const float* __restrict__ bias, const float* __restrict__ res,
    float* __restrict__ Cf, __half* __restrict__ Ch,
    int K, int lda, int ldb, int ldc, int ldr)
{
    extern __shared__ char smem[];
    const uint32_t sbase = smem_to_u32(smem);
    const int tid = threadIdx.x;
    const int lane = tid & 31, wid = tid >> 5;
    const int warp_m = wid >> 2, warp_n = wid & 3;
    const int row0 = blockIdx.y*128, col0 = blockIdx.x*128;
    const int sub = lane>>3, rr = lane&7;

    const __half* Ag = A + (size_t)row0*lda;
    const __half* Bg = B + col0;

    float acc[4][4][4];
    #pragma unroll
    for (int i=0;i<4;i++)
        #pragma unroll
        for (int j=0;j<4;j++){ acc[i][j][0]=0.f; acc[i][j][1]=0.f; acc[i][j][2]=0.f; acc[i][j][3]=0.f; }

    const int nk = K>>6;
    auto issue = [&](int kt){
        const uint32_t sA = sbase + (kt%3)*32768;
        const uint32_t sB = sA + 16384;
        const int koff = kt*64;
        #pragma unroll
        for (int i=0;i<4;i++){
            const int f = tid + i*256;
            const int ar = f>>3, aseg = f&7;
            cp16(sA + SWZ((uint32_t)(ar*128 + aseg*16)), Ag + (size_t)ar*lda + koff + aseg*8);
            const int br = f>>4, cs = f&15;
            cp16(sB + (cs>>3)*8192 + SWZ((uint32_t)(br*128 + (cs&7)*16)),
                 Bg + (size_t)(koff+br)*ldb + cs*8);
        }
    };
    issue(0); CP_COMMIT();
    if (nk>1) issue(1); CP_COMMIT();

    for (int kt=0; kt<nk; ++kt){
        CP_WAIT1();
        __syncthreads();
        if (kt+2 < nk) issue(kt+2);
        CP_COMMIT();
        const uint32_t aB = sbase + (kt%3)*32768;
        const uint32_t bB = aB + 16384;
        #pragma unroll
        for (int s=0;s<4;s++){
            uint32_t af[4][4], bf[2][4];
            #pragma unroll
            for (int mt=0;mt<4;mt++){
                const int m = warp_m*64 + mt*16 + (sub&1)*8 + rr;
                ldm_x4(af[mt], aB + SWZ((uint32_t)(m*128 + s*32 + (sub>>1)*16)));
            }
            #pragma unroll
            for (int p=0;p<2;p++){
                const int kr = s*16 + (sub&1)*8 + rr;
                const int nbase = warp_n*32 + p*16;
                const int dloc = (nbase&63) + (sub>>1)*8;
                ldm_x4t(bf[p], bB + (nbase>>6)*8192 + SWZ((uint32_t)(kr*128 + dloc*2)));
            }
            #pragma unroll
            for (int mt=0;mt<4;mt++)
                #pragma unroll
                for (int p=0;p<2;p++){
                    mma_fp16(acc[mt][p*2+0], af[mt], bf[p][0], bf[p][1]);
                    mma_fp16(acc[mt][p*2+1], af[mt], bf[p][2], bf[p][3]);
                }
        }
    }
    __syncthreads();

    // epilogue via smem staging (pitch 132 floats)
    float* Es = (float*)smem;
    const int qrow = lane>>2, qcol = (lane&3)*2;
    #pragma unroll
    for (int mt=0;mt<4;mt++)
        #pragma unroll
        for (int nt=0;nt<4;nt++)
            #pragma unroll
            for (int half=0; half<2; half++){
                const int r = warp_m*64 + mt*16 + qrow + half*8;
                const int c = warp_n*32 + nt*8 + qcol;
                *(float2*)&Es[r*132 + c] = make_float2(acc[mt][nt][half*2], acc[mt][nt][half*2+1]);
            }
    __syncthreads();
    #pragma unroll
    for (int i=0;i<16;i++){
        const int f = tid + i*256, r = f>>5, c4 = (f&31)<<2;
        float4 v = *(float4*)&Es[r*132 + c4];
        const int col = col0 + c4;
        if (bias){
            const float4 bb = *(const float4*)(bias + col);
            v.x+=bb.x; v.y+=bb.y; v.z+=bb.z; v.w+=bb.w;
        }
        if (ACT==1){
            v.x=1.f/(1.f+__expf(-v.x)); v.y=1.f/(1.f+__expf(-v.y));
            v.z=1.f/(1.f+__expf(-v.z)); v.w=1.f/(1.f+__expf(-v.w));
        } else if (ACT==2){
            v.x=fmaxf(v.x,0.f); v.y=fmaxf(v.y,0.f); v.z=fmaxf(v.z,0.f); v.w=fmaxf(v.w,0.f);
        }
        if (res){
            const float4 rv = *(const float4*)(res + (size_t)(row0+r)*ldr + col);
            v.x+=rv.x; v.y+=rv.y; v.z+=rv.z; v.w+=rv.w;
        }
        if (OUTH){
            __half* p = Ch + (size_t)(row0+r)*ldc + col;
            *(__half2*)(p)   = __floats2half2_rn(v.x, v.y);
            *(__half2*)(p+2) = __floats2half2_rn(v.z, v.w);
        } else {
            *(float4*)(Cf + (size_t)(row0+r)*ldc + col) = v;
        }
    }
}

// ---------------- fp16 mma flash attention, double-buffered KV, register-resident P ----------------
// smem: Q 32KB | K 2 bufs x 16KB | V 2 bufs x 16KB = 96KB
#define ATT_SMEM (32768 + 32768 + 32768)
__global__ void __launch_bounds__(256,2) attn_mma(
    const __half* __restrict__ QKV, __half* __restrict__ O)
{
    extern __shared__ char smem[];
    const uint32_t sQ = smem_to_u32(smem);
    const uint32_t sK = sQ + 32768;
    const uint32_t sV = sK + 32768;

    const int tid = threadIdx.x, lane = tid&31, wid = tid>>5;
    const int sub = lane>>3, rr = lane&7;
    const int qt = blockIdx.x;
    const int b  = blockIdx.y>>3, h = blockIdx.y&7;
    const int m0 = wid*16;
    const float scale = 0.08838834764831845f;

    const __half* Qb = QKV + ((size_t)(b*SEQ + qt*128))*3072 + h*HDIM;
    const __half* Kb = QKV + (size_t)b*SEQ*3072 + D_MODEL   + h*HDIM;
    const __half* Vb = QKV + (size_t)b*SEQ*3072 + 2*D_MODEL + h*HDIM;

    auto issueKV = [&](int kv){
        const uint32_t kbuf = sK + (kv&1)*16384;
        const uint32_t vbuf = sV + (kv&1)*16384;
        #pragma unroll
        for (int i=0;i<4;i++){
            const int f = tid + i*256, r = f>>4, cs = f&15;
            const uint32_t off = (uint32_t)((cs>>3)*8192 + SWZ((uint32_t)(r*128 + (cs&7)*16)));
            cp16(kbuf + off, Kb + (size_t)(kv*64+r)*3072 + cs*8);
            cp16(vbuf + off, Vb + (size_t)(kv*64+r)*3072 + cs*8);
        }
    };

    #pragma unroll
    for (int i=0;i<8;i++){
        const int f = tid + i*256, r = f>>4, cs = f&15;
        const uint4 v = *(const uint4*)(Qb + (size_t)r*3072 + cs*8);
        *(uint4*)(smem + (cs>>3)*16384 + SWZ((uint32_t)(r*128 + (cs&7)*16))) = v;
    }
    issueKV(0); CP_COMMIT();
    issueKV(1); CP_COMMIT();

    float oacc[16][4];
    #pragma unroll
    for (int i=0;i<16;i++){ oacc[i][0]=0.f; oacc[i][1]=0.f; oacc[i][2]=0.f; oacc[i][3]=0.f; }
    float m_run[2] = {-1e30f,-1e30f}, l_run[2] = {0.f,0.f};

    for (int kv=0; kv<SEQ/64; ++kv){
        CP_WAIT1();
        __syncthreads();
        const uint32_t kB = sK + (kv&1)*16384;
        const uint32_t vB = sV + (kv&1)*16384;

        // ---- S = Q @ K^T ----
        float sacc[8][4];
        #pragma unroll
        for (int i=0;i<8;i++){ sacc[i][0]=0.f; sacc[i][1]=0.f; sacc[i][2]=0.f; sacc[i][3]=0.f; }
        #pragma unroll
        for (int s=0;s<8;s++){
            const int p = s>>2, sk = s&3;
            uint32_t af[4], bf[4][4];
            {
                const int m = m0 + (sub&1)*8 + rr;
                ldm_x4(af, sQ + p*16384 + SWZ((uint32_t)(m*128 + sk*32 + (sub>>1)*16)));
            }
            #pragma unroll
            for (int g=0;g<4;g++){
                const int n = g*16 + (sub&1)*8 + rr;
                ldm_x4(bf[g], kB + p*8192 + SWZ((uint32_t)(n*128 + sk*32 + (sub>>1)*16)));
            }
            #pragma unroll
            for (int g=0;g<4;g++){
                mma_fp16(sacc[g*2+0], af, bf[g][0], bf[g][2]);
                mma_fp16(sacc[g*2+1], af, bf[g][1], bf[g][3]);
            }
        }

        // ---- FA2 softmax; P packed straight into A-fragment registers ----
        uint32_t pf[16];
        #pragma unroll
        for (int hh=0; hh<2; ++hh){
            float mx = -1e30f;
            #pragma unroll
            for (int nt=0;nt<8;nt++)
                mx = fmaxf(mx, fmaxf(sacc[nt][hh*2], sacc[nt][hh*2+1]));
            mx *= scale;
            mx = fmaxf(mx, __shfl_xor_sync(0xffffffffu, mx, 1));
            mx = fmaxf(mx, __shfl_xor_sync(0xffffffffu, mx, 2));
            const float mnew = fmaxf(m_run[hh], mx);
            const float alpha = __expf(m_run[hh] - mnew);
            float lsum = 0.f;
            #pragma unroll
            for (int nt=0;nt<8;nt++){
                const float p0 = __expf(scale*sacc[nt][hh*2+0] - mnew);
                const float p1 = __expf(scale*sacc[nt][hh*2+1] - mnew);
                lsum += p0 + p1;
                __half2 hp = __floats2half2_rn(p0, p1);
                pf[(nt>>1)*4 + (nt&1)*2 + hh] = *reinterpret_cast<uint32_t*>(&hp);
            }
            lsum += __shfl_xor_sync(0xffffffffu, lsum, 1);
            lsum += __shfl_xor_sync(0xffffffffu, lsum, 2);
            #pragma unroll
            for (int nt=0;nt<16;nt++){ oacc[nt][hh*2] *= alpha; oacc[nt][hh*2+1] *= alpha; }
            l_run[hh] = l_run[hh]*alpha + lsum;
            m_run[hh] = mnew;
        }

        // ---- O += P @ V (A from registers, B via ldmatrix.trans on V) ----
        #pragma unroll
        for (int t=0;t<4;t++){
            const uint32_t* af = &pf[t*4];
            #pragma unroll
            for (int g=0;g<8;g++){
                uint32_t vf[4];
                const int dbase = g*16;
                const int kvrow = t*16 + (sub&1)*8 + rr;
                const int dloc  = (dbase + (sub>>1)*8) & 63;
                ldm_x4t(vf, vB + (dbase>>6)*8192 + SWZ((uint32_t)(kvrow*128 + dloc*2)));
                mma_fp16(oacc[g*2+0], af, vf[0], vf[1]);
                mma_fp16(oacc[g*2+1], af, vf[2], vf[3]);
            }
        }
        __syncthreads();                      // all warps done with buf kv&1
        if (kv+2 < SEQ/64) issueKV(kv+2);
        CP_COMMIT();
    }

    __half* Ob = O + ((size_t)(b*SEQ + qt*128))*D_MODEL + h*HDIM;
    #pragma unroll
    for (int hh=0; hh<2; ++hh){
        const float inv = 1.f/l_run[hh];
        const int row = m0 + (lane>>2) + hh*8;
        #pragma unroll
        for (int nt=0;nt<16;nt++){
            const int col = nt*8 + (lane&3)*2;
            *(__half2*)(Ob + (size_t)row*D_MODEL + col) =
                __floats2half2_rn(oacc[nt][hh*2]*inv, oacc[nt][hh*2+1]*inv);
        }
    }
}

// ---------------- LayerNorm -> fp16 (dual) ----------------
__global__ void __launch_bounds__(256) ln_h(
    const float* __restrict__ x,
    const float* __restrict__ g0, const float* __restrict__ b0, __half* __restrict__ out0,
    const float* __restrict__ g1, const float* __restrict__ b1, __half* __restrict__ out1)
{
    __shared__ float red[64];
    const int row = blockIdx.x;
    const int tid = threadIdx.x;
    const float4 v = ((const float4*)(x + (size_t)row*D_MODEL))[tid];
    float s  = v.x+v.y+v.z+v.w;
    float sq = v.x*v.x+v.y*v.y+v.z*v.z+v.w*v.w;
    #pragma unroll
    for (int o=16;o;o>>=1){ s += __shfl_xor_sync(0xffffffffu,s,o); sq += __shfl_xor_sync(0xffffffffu,sq,o); }
    if ((tid&31)==0){ red[tid>>5]=s; red[(tid>>5)+8]=sq; }
    __syncthreads();
    if (tid<32){
        float ss=(tid<8)?red[tid]:0.f, qq=(tid<8)?red[tid+8]:0.f;
        #pragma unroll
        for (int o=4;o;o>>=1){ ss += __shfl_xor_sync(0xffffffffu,ss,o); qq += __shfl_xor_sync(0xffffffffu,qq,o); }
        if (tid==0){ red[32]=ss; red[33]=qq; }
    }
    __syncthreads();
    const float mean = red[32]*(1.f/D_MODEL);
    const float var  = red[33]*(1.f/D_MODEL) - mean*mean;
    const float inv  = rsqrtf(var + 1e-5f);
    {
        const float4 g = ((const float4*)g0)[tid];
        const float4 b = ((const float4*)b0)[tid];
        __half2 h0 = __floats2half2_rn((v.x-mean)*inv*g.x + b.x, (v.y-mean)*inv*g.y + b.y);
        __half2 h1 = __floats2half2_rn((v.z-mean)*inv*g.z + b.z, (v.w-mean)*inv*g.w + b.w);
        __half* p = out0 + (size_t)row*D_MODEL + tid*4;
        *(__half2*)p = h0; *(__half2*)(p+2) = h1;
    }
    if (out1){
        const float4 g = ((const float4*)g1)[tid];
        const float4 b = ((const float4*)b1)[tid];
        __half2 h0 = __floats2half2_rn((v.x-mean)*inv*g.x + b.x, (v.y-mean)*inv*g.y + b.y);
        __half2 h1 = __floats2half2_rn((v.z-mean)*inv*g.z + b.z, (v.w-mean)*inv*g.w + b.w);
        __half* p = out1 + (size_t)row*D_MODEL + tid*4;
        *(__half2*)p = h0; *(__half2*)(p+2) = h1;
    }
}

// ---------------- final LayerNorm -> fp32 ----------------
__global__ void __launch_bounds__(256) ln_f(
    const float* __restrict__ x,
    const float* __restrict__ g0, const float* __restrict__ b0, float* __restrict__ out0)
{
    __shared__ float red[64];
    const int row = blockIdx.x;
    const int tid = threadIdx.x;
    const float4 v = ((const float4*)(x + (size_t)row*D_MODEL))[tid];
    float s  = v.x+v.y+v.z+v.w;
    float sq = v.x*v.x+v.y*v.y+v.z*v.z+v.w*v.w;
    #pragma unroll
    for (int o=16;o;o>>=1){ s += __shfl_xor_sync(0xffffffffu,s,o); sq += __shfl_xor_sync(0xffffffffu,sq,o); }
    if ((tid&31)==0){ red[tid>>5]=s; red[(tid>>5)+8]=sq; }
    __syncthreads();
    if (tid<32){
        float ss=(tid<8)?red[tid]:0.f, qq=(tid<8)?red[tid+8]:0.f;
        #pragma unroll
        for (int o=4;o;o>>=1){ ss += __shfl_xor_sync(0xffffffffu,ss,o); qq += __shfl_xor_sync(0xffffffffu,qq,o); }
        if (tid==0){ red[32]=ss; red[33]=qq; }
    }
    __syncthreads();
    const float mean = red[32]*(1.f/D_MODEL);
    const float var  = red[33]*(1.f/D_MODEL) - mean*mean;
    const float inv  = rsqrtf(var + 1e-5f);
    const float4 g = ((const float4*)g0)[tid];
    const float4 b = ((const float4*)b0)[tid];
    float4 o0;
    o0.x = (v.x-mean)*inv*g.x + b.x;
    o0.y = (v.y-mean)*inv*g.y + b.y;
    o0.z = (v.z-mean)*inv*g.z + b.z;
    o0.w = (v.w-mean)*inv*g.w + b.w;
    ((float4*)(out0 + (size_t)row*D_MODEL))[tid] = o0;
}

// ---------------- delta / Bt (xn fp16 in) ----------------
__global__ void __launch_bounds__(256) delta_bt_kernel(
    const __half* __restrict__ xn,
    const float* __restrict__ Wd, const float* __restrict__ bd,
    const float* __restrict__ Wi, const float* __restrict__ bi,
    float* __restrict__ delta, float* __restrict__ bt)
{
    __shared__ float xs[D_MODEL];
    __shared__ float red[256];
    const int row = blockIdx.x, tid = threadIdx.x;
    #pragma unroll
    for (int i=0;i<4;i++) xs[tid + i*256] = __half2float(xn[(size_t)row*D_MODEL + tid + i*256]);
    __syncthreads();
    const int c = tid & 15;
    const int which = (tid>>4)&1;
    const int grp = tid>>5;
    const float* W = which ? Wi : Wd;
    float acc = 0.f;
    const int k0 = grp*128;
    #pragma unroll 8
    for (int k=0;k<128;k++) acc += xs[k0+k]*W[(size_t)(k0+k)*16 + c];
    red[tid]=acc; __syncthreads();
    if (tid<32){
        float sacc=0.f;
        #pragma unroll
        for (int g=0;g<8;g++) sacc += red[g*32+tid];
        if (tid<16) delta[(size_t)row*16+tid] = 1.f/(1.f+__expf(-(sacc+bd[tid])));
        else        bt   [(size_t)row*16+tid-16] = sacc + bi[tid-16];
    }
}

// ---------------- sequential mamba scan ----------------
__global__ void __launch_bounds__(32) scan_kernel(
    const float* __restrict__ delta, const float* __restrict__ bt,
    const float* __restrict__ A, float* __restrict__ h_all)
{
    __shared__ float ds[128*16], bs[128*16];
    const int b = blockIdx.x, lane = threadIdx.x;
    const int j = lane & 15;
    float Acol[16];
    #pragma unroll
    for (int i=0;i<16;i++) Acol[i] = A[i*16 + j];
    float h = 0.f;
    const float* dp = delta + (size_t)b*SEQ*16;
    const float* bp = bt    + (size_t)b*SEQ*16;
    float* hp = h_all + (size_t)b*SEQ*16;
    for (int chunk=0; chunk<SEQ; chunk+=128){
        const float4* s0 = (const float4*)(dp + (size_t)chunk*16);
        const float4* s1 = (const float4*)(bp + (size_t)chunk*16);
        for (int i=lane;i<512;i+=32){ ((float4*)ds)[i]=s0[i]; ((float4*)bs)[i]=s1[i]; }
        __syncwarp();
        #pragma unroll 4
        for (int t=0;t<128;t++){
            const float d = ds[t*16+j];
            const float bv = bs[t*16+j];
            const float v = h*d;
            float a0 = bv, a1 = 0.f;
            #pragma unroll
            for (int i=0;i<16;i+=2){
                a0 += __shfl_sync(0xffffffffu, v, i,   16)*Acol[i];
                a1 += __shfl_sync(0xffffffffu, v, i+1, 16)*Acol[i+1];
            }
            h = tanh_fast(a0+a1);
            if (lane<16) hp[(size_t)(chunk+t)*16 + j] = h;
        }
        __syncwarp();
    }
}

// ---------------- mamba_out -> mambah fp16 (pitch 1024) ----------------
__global__ void __launch_bounds__(256) mamba_out_kernel(
    const float* __restrict__ h_all, const float* __restrict__ Cm,
    const __half* __restrict__ gate, const float* __restrict__ x,
    __half* __restrict__ out)
{
    __shared__ float hs[16];
    const int row = blockIdx.x, tid = threadIdx.x;
    if (tid<16) hs[tid] = h_all[(size_t)row*16+tid];
    __syncthreads();
    const size_t base = (size_t)row*D_MODEL;
    #pragma unroll
    for (int kk=0; kk<4; kk++){
        const int c = tid + kk*256;
        float acc = 0.f;
        #pragma unroll
        for (int i=0;i<16;i++) acc += hs[i]*Cm[(size_t)i*D_MODEL + c];
        out[base+c] = __float2half_rn(acc*__half2float(gate[base+c]) + x[base+c]);
    }
}

// ---------------- launch ----------------
extern "C" void kernel_launch(void* const* d_in, const int* in_sizes, int n_in,
                              void* d_out, int out_size)
{
    const float* x      = (const float*)d_in[0];
    const float* ln_g   = (const float*)d_in[1];
    const float* ln_b   = (const float*)d_in[2];
    const float* Wdelta = (const float*)d_in[3];
    const float* bdelta = (const float*)d_in[4];
    const float* Win    = (const float*)d_in[5];
    const float* b_in   = (const float*)d_in[6];
    const float* Wgate  = (const float*)d_in[7];
    const float* bgate  = (const float*)d_in[8];
    const float* Amat   = (const float*)d_in[9];
    const float* Cmat   = (const float*)d_in[10];
    const float* ln1_g  = (const float*)d_in[11];
    const float* ln1_b  = (const float*)d_in[12];
    const float* Wq     = (const float*)d_in[13];
    const float* bq     = (const float*)d_in[14];
    const float* Wk     = (const float*)d_in[15];
    const float* bk     = (const float*)d_in[16];
    const float* Wv     = (const float*)d_in[17];
    const float* bv     = (const float*)d_in[18];
    const float* Wo     = (const float*)d_in[19];
    const float* bo     = (const float*)d_in[20];
    const float* ln2_g  = (const float*)d_in[21];
    const float* ln2_b  = (const float*)d_in[22];
    const float* W1     = (const float*)d_in[23];
    const float* b1     = (const float*)d_in[24];
    const float* W2     = (const float*)d_in[25];
    const float* b2     = (const float*)d_in[26];
    const float* Wf     = (const float*)d_in[27];
    const float* bf     = (const float*)d_in[28];
    const float* lnf_g  = (const float*)d_in[29];
    const float* lnf_b  = (const float*)d_in[30];

    __half *xnh,*xn1h,*qkvh,*ctxh,*xn2h,*ffn1h,*mambah,*touth,*gateh;
    __half *Wgh,*Wqkvh,*Woh,*W1h,*W2h,*Wfh;
    float *x2,*y,*delta,*bt,*h,*bqkv;
    cudaGetSymbolAddress((void**)&xnh,  g_xnh);
    cudaGetSymbolAddress((void**)&xn1h, g_xn1h);
    cudaGetSymbolAddress((void**)&qkvh, g_qkvh);
    cudaGetSymbolAddress((void**)&ctxh, g_ctxh);
    cudaGetSymbolAddress((void**)&xn2h, g_xn2h);
    cudaGetSymbolAddress((void**)&ffn1h,g_ffn1h);
    cudaGetSymbolAddress((void**)&mambah,g_mambah);
    cudaGetSymbolAddress((void**)&touth,g_touth);
    cudaGetSymbolAddress((void**)&gateh,g_gateh);
    cudaGetSymbolAddress((void**)&x2,   g_x2);
    cudaGetSymbolAddress((void**)&y,    g_y);
    cudaGetSymbolAddress((void**)&delta,g_delta);
    cudaGetSymbolAddress((void**)&bt,   g_bt);
    cudaGetSymbolAddress((void**)&h,    g_h);
    cudaGetSymbolAddress((void**)&bqkv, g_bqkv);
    cudaGetSymbolAddress((void**)&Wgh,  g_Wgh);
    cudaGetSymbolAddress((void**)&Wqkvh,g_Wqkvh);
    cudaGetSymbolAddress((void**)&Woh,  g_Woh);
    cudaGetSymbolAddress((void**)&W1h,  g_W1h);
    cudaGetSymbolAddress((void**)&W2h,  g_W2h);
    cudaGetSymbolAddress((void**)&Wfh,  g_Wfh);

    cudaFuncSetAttribute(gemm_mma<0,0>, cudaFuncAttributeMaxDynamicSharedMemorySize, GEMM_SMEM);
    cudaFuncSetAttribute(gemm_mma<0,1>, cudaFuncAttributeMaxDynamicSharedMemorySize, GEMM_SMEM);
    cudaFuncSetAttribute(gemm_mma<1,1>, cudaFuncAttributeMaxDynamicSharedMemorySize, GEMM_SMEM);
    cudaFuncSetAttribute(gemm_mma<2,1>, cudaFuncAttributeMaxDynamicSharedMemorySize, GEMM_SMEM);
    cudaFuncSetAttribute(attn_mma, cudaFuncAttributeMaxDynamicSharedMemorySize, ATT_SMEM);

    static cudaStream_t s1 = nullptr, s2 = nullptr, s3 = nullptr;
    static cudaEvent_t eFork, eLn0, eLn1, eWqkv, eWo, eW1, eW2, eWf, eGate, eMamba, eH1;
    if (!s1){
        cudaStreamCreateWithFlags(&s1, cudaStreamNonBlocking);
        cudaStreamCreateWithFlags(&s2, cudaStreamNonBlocking);
        cudaStreamCreateWithFlags(&s3, cudaStreamNonBlocking);
        cudaEventCreateWithFlags(&eFork,  cudaEventDisableTiming);
        cudaEventCreateWithFlags(&eLn0,   cudaEventDisableTiming);
        cudaEventCreateWithFlags(&eLn1,   cudaEventDisableTiming);
        cudaEventCreateWithFlags(&eWqkv,  cudaEventDisableTiming);
        cudaEventCreateWithFlags(&eWo,    cudaEventDisableTiming);
        cudaEventCreateWithFlags(&eW1,    cudaEventDisableTiming);
        cudaEventCreateWithFlags(&eW2,    cudaEventDisableTiming);
        cudaEventCreateWithFlags(&eWf,    cudaEventDisableTiming);
        cudaEventCreateWithFlags(&eGate,  cudaEventDisableTiming);
        cudaEventCreateWithFlags(&eMamba, cudaEventDisableTiming);
        cudaEventCreateWithFlags(&eH1,    cudaEventDisableTiming);
    }

    const dim3 gDh(D_MODEL/128, HROWS/128);       // (8, 32)
    const dim3 gDfull(D_MODEL/128, ROWS/128);     // (8, 64)
    const dim3 gQKVh(3*D_MODEL/128, HROWS/128);   // (24, 32)
    const dim3 gFh(DFF/128, HROWS/128);           // (32, 32)
    const int M4 = D_MODEL*D_MODEL/4;

    // ---- fork ----
    cudaEventRecord(eFork, 0);
    cudaStreamWaitEvent(s1, eFork, 0);
    cudaStreamWaitEvent(s2, eFork, 0);
    cudaStreamWaitEvent(s3, eFork, 0);

    // ---- s2: fused qkv weight+bias convert (single launch -> early eWqkv) ----
    wcvt_qkv<<<3*(M4/256)+1,256,0,s2>>>(Wq, Wk, Wv, bq, bk, bv, Wqkvh, bqkv, M4);
    cudaEventRecord(eWqkv, s2);
    wcvt<<<M4/256,256,0,s2>>>(Wgate, Wgh, D_MODEL, D_MODEL, 0, M4);

    // ---- per-half dual LN (H0 on stream0, H1 on s3) ----
    ln_h<<<HROWS,256>>>(x, ln_g, ln_b, xnh, ln1_g, ln1_b, xn1h);
    cudaEventRecord(eLn0, 0);
    ln_h<<<HROWS,256,0,s3>>>(x + (size_t)HROWS*D_MODEL, ln_g, ln_b, xnh + (size_t)HROWS*D_MODEL,
                             ln1_g, ln1_b, xn1h + (size_t)HROWS*D_MODEL);
    cudaEventRecord(eLn1, s3);

    // ---- s2 cont: gate GEMM (needs full xnh) + remaining weight cvts ----
    cudaStreamWaitEvent(s2, eLn0, 0);
    cudaStreamWaitEvent(s2, eLn1, 0);
    gemm_mma<1,1><<<gDfull,256,GEMM_SMEM,s2>>>(xnh, Wgh, bgate, nullptr, nullptr, gateh,
                                               D_MODEL, D_MODEL, D_MODEL, D_MODEL, 0);
    cudaEventRecord(eGate, s2);
    wcvt<<<M4/256,256,0,s2>>>(Wo, Woh, D_MODEL, D_MODEL, 0, M4);
    cudaEventRecord(eWo, s2);
    wcvt<<<4*M4/256,256,0,s2>>>(W1, W1h, DFF, DFF, 0, 4*M4);
    cudaEventRecord(eW1, s2);
    wcvt<<<4*M4/256,256,0,s2>>>(W2, W2h, D_MODEL, D_MODEL, 0, 4*M4);
    cudaEventRecord(eW2, s2);
    wcvt<<<2*M4/256,256,0,s2>>>(Wf, Wfh, D_MODEL, D_MODEL, 0, 2*M4);
    cudaEventRecord(eWf, s2);

    // ---- s1: mamba branch + fusion(mamba half) off the critical path ----
    cudaStreamWaitEvent(s1, eLn0, 0);
    cudaStreamWaitEvent(s1, eLn1, 0);
    delta_bt_kernel<<<ROWS,256,0,s1>>>(xnh, Wdelta, bdelta, Win, b_in, delta, bt);
    scan_kernel<<<BATCH,32,0,s1>>>(delta, bt, Amat, h);
    cudaStreamWaitEvent(s1, eGate, 0);
    mamba_out_kernel<<<ROWS,256,0,s1>>>(h, Cmat, gateh, x, mambah);
    cudaStreamWaitEvent(s1, eWf, 0);
    gemm_mma<0,0><<<gDfull,256,GEMM_SMEM,s1>>>(mambah, Wfh, bf, nullptr, y, nullptr,
                                               D_MODEL, D_MODEL, D_MODEL, D_MODEL, 0);
    cudaEventRecord(eMamba, s1);

    // ---- per-half transformer chains (H0 on stream 0, H1 on s3) ----
    for (int half=0; half<2; ++half){
        cudaStream_t st = half ? s3 : (cudaStream_t)0;
        const size_t r1024 = (size_t)half*HROWS*1024;
        const size_t r3072 = (size_t)half*HROWS*3072;
        const size_t r4096 = (size_t)half*HROWS*4096;
        cudaStreamWaitEvent(st, eWqkv, 0);
        gemm_mma<0,1><<<gQKVh,256,GEMM_SMEM,st>>>(xn1h + r1024, Wqkvh, bqkv, nullptr, nullptr,
                                                  qkvh + r3072, D_MODEL, D_MODEL, 3*D_MODEL, 3*D_MODEL, 0);
        attn_mma<<<dim3(SEQ/128, 2*NHEADS), 256, ATT_SMEM, st>>>(qkvh + r3072, ctxh + r1024);
        cudaStreamWaitEvent(st, eWo, 0);
        gemm_mma<0,0><<<gDh,256,GEMM_SMEM,st>>>(ctxh + r1024, Woh, bo, x + r1024, x2 + r1024, nullptr,
                                                D_MODEL, D_MODEL, D_MODEL, D_MODEL, D_MODEL);
        ln_h<<<HROWS,256,0,st>>>(x2 + r1024, ln2_g, ln2_b, xn2h + r1024, nullptr, nullptr, nullptr);
        cudaStreamWaitEvent(st, eW1, 0);
        gemm_mma<2,1><<<gFh,256,GEMM_SMEM,st>>>(xn2h + r1024, W1h, b1, nullptr, nullptr, ffn1h + r4096,
                                                D_MODEL, D_MODEL, DFF, DFF, 0);
        cudaStreamWaitEvent(st, eW2, 0);
        gemm_mma<0,1><<<gDh,256,GEMM_SMEM,st>>>(ffn1h + r4096, W2h, b2, x2 + r1024, nullptr, touth + r1024,
                                                DFF, DFF, D_MODEL, D_MODEL, D_MODEL);
        cudaStreamWaitEvent(st, eMamba, 0);
        gemm_mma<0,0><<<gDh,256,GEMM_SMEM,st>>>(touth + r1024, Wfh + (size_t)D_MODEL*D_MODEL, nullptr,
                                                y + r1024, y + r1024, nullptr,
                                                D_MODEL, D_MODEL, D_MODEL, D_MODEL, D_MODEL);
        ln_f<<<HROWS,256,0,st>>>(y + r1024, lnf_g, lnf_b, (float*)d_out + r1024);
    }
    cudaEventRecord(eH1, s3);
    cudaStreamWaitEvent(0, eH1, 0);
}